// round 2
// baseline (speedup 1.0000x reference)
#include <cuda_runtime.h>
#include <cuda_bf16.h>
#include <cstdint>

#define N_NODES 100000
#define N_EDGES 1600000
#define KTOT 384   // 128 (root/x) + 128 (rel 0) + 128 (rel 1)

// Scratch (device globals: no allocation allowed in kernel_launch)
__device__ float g_G[(size_t)N_NODES * KTOT];   // [N, 384]: cols 0:128 = x/H, 128:256 = A0, 256:384 = A1
__device__ float g_cnt[2 * N_NODES];            // per-relation in-degree counts
__device__ float g_W1[KTOT * 128];              // [W1_root; W1_rel[0]; W1_rel[1]]
__device__ float g_W2[KTOT * 64];

// ---------------------------------------------------------------------------
// copy x into cols 0:128 of G
__global__ void copy_x_kernel(const float* __restrict__ x, float* __restrict__ G) {
    int i = blockIdx.x * blockDim.x + threadIdx.x;      // over N*32 float4
    if (i >= N_NODES * 32) return;
    int n = i >> 5, c = i & 31;
    ((float4*)(G + (size_t)n * KTOT))[c] = ((const float4*)(x + (size_t)n * 128))[c];
}

// zero cols 128:384 of G
__global__ void zero_mid_kernel(float* __restrict__ G) {
    int i = blockIdx.x * blockDim.x + threadIdx.x;      // over N*64 float4
    if (i >= N_NODES * 64) return;
    int n = i >> 6, c = i & 63;
    ((float4*)(G + (size_t)n * KTOT + 128))[c] = make_float4(0.f, 0.f, 0.f, 0.f);
}

// ---------------------------------------------------------------------------
// One warp per edge: gather 128 floats from G[src, 0:128], vector-atomic-add
// into G[dst, 128 + r*128 : ...]. Lane 0 bumps the relation count.
__global__ void scatter_kernel(const int* __restrict__ ei,
                               const int* __restrict__ et,
                               float* __restrict__ G,
                               float* __restrict__ cnt) {
    int t = blockIdx.x * blockDim.x + threadIdx.x;
    int e = t >> 5;
    int lane = threadIdx.x & 31;
    if (e >= N_EDGES) return;
    int s = ei[e];
    int d = ei[N_EDGES + e];
    int r = et[e];
    float4 v = ((const float4*)(G + (size_t)s * KTOT))[lane];
    float* p = G + (size_t)d * KTOT + 128 + r * 128 + lane * 4;
    asm volatile("red.global.add.v4.f32 [%0], {%1, %2, %3, %4};"
                 :: "l"(p), "f"(v.x), "f"(v.y), "f"(v.z), "f"(v.w) : "memory");
    if (lane == 0)
        atomicAdd(cnt + (size_t)r * N_NODES + d, 1.0f);
}

// Divide accumulated messages by max(cnt, 1)
__global__ void norm_mid_kernel(float* __restrict__ G, const float* __restrict__ cnt) {
    int i = blockIdx.x * blockDim.x + threadIdx.x;      // over N*64 float4
    if (i >= N_NODES * 64) return;
    int n = i >> 6, j = i & 63;
    int r = j >> 5;                                      // 32 float4 per relation segment
    float c = cnt[(size_t)r * N_NODES + n];
    float s = 1.0f / fmaxf(c, 1.0f);
    float4* p = ((float4*)(G + (size_t)n * KTOT + 128)) + j;
    float4 v = *p;
    v.x *= s; v.y *= s; v.z *= s; v.w *= s;
    *p = v;
}

// ---------------------------------------------------------------------------
// Tiled FP32 GEMM: C[M, BN] = op(A[M,384] @ B[384,BN] + bias), op = relu?
// BM=128, BK=32, TM=8; 256 threads; single column block (BN == full N_out).
template<int BN, int TN, bool RELU>
__global__ void gemm384_kernel(const float* __restrict__ A,
                               const float* __restrict__ B,
                               const float* __restrict__ bias,
                               float* C, int M, int ldc) {
    constexpr int BM = 128, BK = 32, TM = 8;
    constexpr int NTX = BN / TN;                         // 16
    __shared__ float As[BK][BM];
    __shared__ float Bs[BK][BN];

    const int tid = threadIdx.x;
    const int tx = tid % NTX;
    const int ty = tid / NTX;
    const int m0 = blockIdx.x * BM;

    float acc[TM][TN];
#pragma unroll
    for (int i = 0; i < TM; i++)
#pragma unroll
        for (int j = 0; j < TN; j++) acc[i][j] = 0.f;

    const float* Ab = A + (size_t)m0 * KTOT;

    for (int k0 = 0; k0 < KTOT; k0 += BK) {
        // Load A tile (BM x BK), transpose into As[k][m]
#pragma unroll
        for (int i = 0; i < 4; i++) {
            int v = tid + i * 256;                      // 1024 float4 total
            int row = v >> 3;                            // 8 float4 per row
            int kv = v & 7;
            float4 a;
            if (m0 + row < M)
                a = *(const float4*)(Ab + (size_t)row * KTOT + k0 + kv * 4);
            else
                a = make_float4(0.f, 0.f, 0.f, 0.f);
            As[kv * 4 + 0][row] = a.x;
            As[kv * 4 + 1][row] = a.y;
            As[kv * 4 + 2][row] = a.z;
            As[kv * 4 + 3][row] = a.w;
        }
        // Load B tile (BK x BN) as-is
        constexpr int BV = (BK * BN / 4) / 256;          // 4 (BN=128) or 2 (BN=64)
#pragma unroll
        for (int i = 0; i < BV; i++) {
            int v = tid + i * 256;
            int kk = v / (BN / 4);
            int nn = v % (BN / 4);
            *(float4*)&Bs[kk][nn * 4] = *(const float4*)(B + (size_t)(k0 + kk) * BN + nn * 4);
        }
        __syncthreads();

#pragma unroll
        for (int k = 0; k < BK; k++) {
            float ar[TM], br[TN];
#pragma unroll
            for (int i = 0; i < TM; i++) ar[i] = As[k][ty * TM + i];
#pragma unroll
            for (int j = 0; j < TN; j++) br[j] = Bs[k][tx * TN + j];
#pragma unroll
            for (int i = 0; i < TM; i++)
#pragma unroll
                for (int j = 0; j < TN; j++) acc[i][j] += ar[i] * br[j];
        }
        __syncthreads();
    }

    // Epilogue: bias (+relu), vectorized float4 stores
    float bv[TN];
#pragma unroll
    for (int j = 0; j < TN; j++) bv[j] = bias[tx * TN + j];

#pragma unroll
    for (int i = 0; i < TM; i++) {
        int row = m0 + ty * TM + i;
        if (row >= M) continue;
        float* crow = C + (size_t)row * ldc + tx * TN;
#pragma unroll
        for (int j4 = 0; j4 < TN / 4; j4++) {
            float4 o;
            float v0 = acc[i][j4 * 4 + 0] + bv[j4 * 4 + 0];
            float v1 = acc[i][j4 * 4 + 1] + bv[j4 * 4 + 1];
            float v2 = acc[i][j4 * 4 + 2] + bv[j4 * 4 + 2];
            float v3 = acc[i][j4 * 4 + 3] + bv[j4 * 4 + 3];
            if (RELU) {
                v0 = fmaxf(v0, 0.f); v1 = fmaxf(v1, 0.f);
                v2 = fmaxf(v2, 0.f); v3 = fmaxf(v3, 0.f);
            }
            o.x = v0; o.y = v1; o.z = v2; o.w = v3;
            *(float4*)(crow + j4 * 4) = o;
        }
    }
}

// ---------------------------------------------------------------------------
// Row-wise L2 normalize (64 cols), one warp per row, in-place on d_out
__global__ void l2norm_kernel(float* __restrict__ out) {
    int t = blockIdx.x * blockDim.x + threadIdx.x;
    int row = t >> 5;
    int lane = threadIdx.x & 31;
    if (row >= N_NODES) return;
    float2 v = ((float2*)(out + (size_t)row * 64))[lane];
    float ss = v.x * v.x + v.y * v.y;
#pragma unroll
    for (int o = 16; o; o >>= 1) ss += __shfl_xor_sync(0xFFFFFFFFu, ss, o);
    float nrm = sqrtf(ss);
    float s = 1.0f / fmaxf(nrm, 1e-12f);
    v.x *= s; v.y *= s;
    ((float2*)(out + (size_t)row * 64))[lane] = v;
}

// ---------------------------------------------------------------------------
extern "C" void kernel_launch(void* const* d_in, const int* in_sizes, int n_in,
                              void* d_out, int out_size) {
    const float* x       = (const float*)d_in[0];
    const int*   ei      = (const int*)d_in[1];   // int32: JAX x64 disabled
    const int*   et      = (const int*)d_in[2];   // int32
    const float* W1_rel  = (const float*)d_in[3];
    const float* W1_root = (const float*)d_in[4];
    const float* b1      = (const float*)d_in[5];
    const float* W2_rel  = (const float*)d_in[6];
    const float* W2_root = (const float*)d_in[7];
    const float* b2      = (const float*)d_in[8];
    float* out = (float*)d_out;

    float *G, *cnt, *W1, *W2;
    cudaGetSymbolAddress((void**)&G,   g_G);
    cudaGetSymbolAddress((void**)&cnt, g_cnt);
    cudaGetSymbolAddress((void**)&W1,  g_W1);
    cudaGetSymbolAddress((void**)&W2,  g_W2);

    // Concatenated weights: [W_root; W_rel] is contiguous along K
    cudaMemcpyAsync(W1,             W1_root, (size_t)128 * 128 * 4,     cudaMemcpyDeviceToDevice);
    cudaMemcpyAsync(W1 + 128 * 128, W1_rel,  (size_t)2 * 128 * 128 * 4, cudaMemcpyDeviceToDevice);
    cudaMemcpyAsync(W2,             W2_root, (size_t)128 * 64 * 4,      cudaMemcpyDeviceToDevice);
    cudaMemcpyAsync(W2 + 128 * 64,  W2_rel,  (size_t)2 * 128 * 64 * 4,  cudaMemcpyDeviceToDevice);

    const int TB = 256;
    const int g_copy = (N_NODES * 32 + TB - 1) / TB;
    const int g_mid  = (N_NODES * 64 + TB - 1) / TB;
    const int g_scat = ((N_EDGES * 32) + TB - 1) / TB;
    const int g_gemm = (N_NODES + 127) / 128;
    const int g_l2   = (N_NODES * 32 + TB - 1) / TB;

    // ---- Layer 1 ----
    cudaMemsetAsync(cnt, 0, (size_t)2 * N_NODES * 4);
    copy_x_kernel<<<g_copy, TB>>>(x, G);
    zero_mid_kernel<<<g_mid, TB>>>(G);
    scatter_kernel<<<g_scat, TB>>>(ei, et, G, cnt);
    norm_mid_kernel<<<g_mid, TB>>>(G, cnt);
    gemm384_kernel<128, 8, true><<<g_gemm, TB>>>(G, W1, b1, G, N_NODES, KTOT);  // H -> G[:,0:128]

    // ---- Layer 2 ----
    cudaMemsetAsync(cnt, 0, (size_t)2 * N_NODES * 4);
    zero_mid_kernel<<<g_mid, TB>>>(G);
    scatter_kernel<<<g_scat, TB>>>(ei, et, G, cnt);
    norm_mid_kernel<<<g_mid, TB>>>(G, cnt);
    gemm384_kernel<64, 4, false><<<g_gemm, TB>>>(G, W2, b2, out, N_NODES, 64);

    // ---- L2 normalize rows of output ----
    l2norm_kernel<<<g_l2, TB>>>(out);
}

// round 4
// speedup vs baseline: 1.3681x; 1.3681x over previous
#include <cuda_runtime.h>
#include <cuda_bf16.h>
#include <cstdint>

#define N_NODES 100000
#define N_EDGES 1600000
#define KTOT 384   // 128 (root/x|H) + 128 (rel 0) + 128 (rel 1)

// ---------------------------------------------------------------------------
// Device-global scratch (no allocation allowed in kernel_launch)
__device__ float g_G[(size_t)N_NODES * KTOT];       // [N,384]
__device__ float g_cnt[2 * N_NODES];                // per-relation in-degree
__device__ __nv_bfloat16 g_W1T_hi[128 * KTOT];      // W1^T [n][k], bf16 hi
__device__ __nv_bfloat16 g_W1T_lo[128 * KTOT];      // bf16 lo residual
__device__ __nv_bfloat16 g_W2T_hi[64 * KTOT];
__device__ __nv_bfloat16 g_W2T_lo[64 * KTOT];

// ---------------------------------------------------------------------------
// Build transposed, bf16-split weight matrices: WT[n][k] = W[k][n]
__global__ void prep_w_kernel(const float* __restrict__ W1_rel,
                              const float* __restrict__ W1_root,
                              const float* __restrict__ W2_rel,
                              const float* __restrict__ W2_root) {
    int i = blockIdx.x * blockDim.x + threadIdx.x;
    const int SZ1 = 128 * KTOT;
    const int SZ2 = 64 * KTOT;
    if (i >= SZ1 + SZ2) return;
    float v;
    __nv_bfloat16 *dh, *dl;
    if (i < SZ1) {
        int n = i / KTOT, k = i % KTOT;
        if (k < 128) v = W1_root[k * 128 + n];
        else {
            int r = (k - 128) >> 7, kk = (k - 128) & 127;
            v = W1_rel[(size_t)r * 128 * 128 + kk * 128 + n];
        }
        dh = g_W1T_hi + i; dl = g_W1T_lo + i;
    } else {
        int j = i - SZ1;
        int n = j / KTOT, k = j % KTOT;
        if (k < 128) v = W2_root[k * 64 + n];
        else {
            int r = (k - 128) >> 7, kk = (k - 128) & 127;
            v = W2_rel[(size_t)r * 128 * 64 + kk * 64 + n];
        }
        dh = g_W2T_hi + j; dl = g_W2T_lo + j;
    }
    __nv_bfloat16 h = __float2bfloat16(v);
    *dh = h;
    *dl = __float2bfloat16(v - __bfloat162float(h));
}

// ---------------------------------------------------------------------------
// Layer-1 init: copy x into cols 0:128 of G, zero cols 128:384
__global__ void init_G_kernel(const float* __restrict__ x, float* __restrict__ G) {
    int i = blockIdx.x * blockDim.x + threadIdx.x;      // over N*96 float4
    if (i >= N_NODES * 96) return;
    int n = i / 96, c = i % 96;
    float4* dst = (float4*)(G + (size_t)n * KTOT) + c;
    if (c < 32)
        *dst = ((const float4*)(x + (size_t)n * 128))[c];
    else
        *dst = make_float4(0.f, 0.f, 0.f, 0.f);
}

// ---------------------------------------------------------------------------
// One warp per edge: gather 128 floats from G[src,0:128], vector-atomic-add
// into G[dst, 128 + r*128]. Lane 0 bumps the relation count.
__global__ void scatter_kernel(const int* __restrict__ ei,
                               const int* __restrict__ et,
                               float* __restrict__ G,
                               float* __restrict__ cnt) {
    int t = blockIdx.x * blockDim.x + threadIdx.x;
    int e = t >> 5;
    int lane = threadIdx.x & 31;
    if (e >= N_EDGES) return;
    int s = ei[e];
    int d = ei[N_EDGES + e];
    int r = et[e];
    float4 v = ((const float4*)(G + (size_t)s * KTOT))[lane];
    float* p = G + (size_t)d * KTOT + 128 + r * 128 + lane * 4;
    asm volatile("red.global.add.v4.f32 [%0], {%1, %2, %3, %4};"
                 :: "l"(p), "f"(v.x), "f"(v.y), "f"(v.z), "f"(v.w) : "memory");
    if (lane == 0)
        atomicAdd(cnt + (size_t)r * N_NODES + d, 1.0f);
}

// ---------------------------------------------------------------------------
__device__ __forceinline__ void mma_bf16(float* c, const unsigned* a, const unsigned* b) {
    asm volatile(
        "mma.sync.aligned.m16n8k16.row.col.f32.bf16.bf16.f32 "
        "{%0,%1,%2,%3}, {%4,%5,%6,%7}, {%8,%9}, {%0,%1,%2,%3};"
        : "+f"(c[0]), "+f"(c[1]), "+f"(c[2]), "+f"(c[3])
        : "r"(a[0]), "r"(a[1]), "r"(a[2]), "r"(a[3]), "r"(b[0]), "r"(b[1]));
}

__device__ __forceinline__ unsigned pack2(__nv_bfloat16 a, __nv_bfloat16 b) {
    union { __nv_bfloat162 v; unsigned u; } c;
    c.v = __halves2bfloat162(a, b);
    return c.u;
}

// Split-scale: v*s -> (hi, lo) packed pairs
__device__ __forceinline__ void split4(const float4 v, float s,
                                       unsigned& hi0, unsigned& hi1,
                                       unsigned& lo0, unsigned& lo1) {
    float f0 = v.x * s, f1 = v.y * s, f2 = v.z * s, f3 = v.w * s;
    __nv_bfloat16 h0 = __float2bfloat16(f0), h1 = __float2bfloat16(f1);
    __nv_bfloat16 h2 = __float2bfloat16(f2), h3 = __float2bfloat16(f3);
    __nv_bfloat16 l0 = __float2bfloat16(f0 - __bfloat162float(h0));
    __nv_bfloat16 l1 = __float2bfloat16(f1 - __bfloat162float(h1));
    __nv_bfloat16 l2 = __float2bfloat16(f2 - __bfloat162float(h2));
    __nv_bfloat16 l3 = __float2bfloat16(f3 - __bfloat162float(h3));
    hi0 = pack2(h0, h1); hi1 = pack2(h2, h3);
    lo0 = pack2(l0, l1); lo1 = pack2(l2, l3);
}

// ---------------------------------------------------------------------------
// Tensor-core GEMM with bf16 3-term split (hi*hi + hi*lo + lo*hi).
// C[M,BN] = op( scale(A[M,384]) @ W[384,BN] + bias )
// A-row scale: cols 0:128 -> 1, cols 128+r*128 -> 1/max(cnt[r],1)  (fused mean)
// RELU: relu epilogue + zero G mid cols (layer-1).  L2NORM: row l2-normalize.
template<int BN, int WARPS_M, int WARPS_N, int MT, int NT, bool RELU, bool L2NORM>
__global__ void __launch_bounds__(256)
gemm_bf16_kernel(const float* __restrict__ A,
                 const __nv_bfloat16* __restrict__ WT_hi,
                 const __nv_bfloat16* __restrict__ WT_lo,
                 const float* __restrict__ bias,
                 const float* __restrict__ cnt,
                 float* __restrict__ C, int M, int ldc,
                 float* __restrict__ Gz) {
    constexpr int BM = 128, BK = 32, BKP = 40;          // pitch 40 bf16 = 80B (16B-aligned, conflict-free)
    __shared__ __align__(16) __nv_bfloat16 As_hi[BM * BKP];
    __shared__ __align__(16) __nv_bfloat16 As_lo[BM * BKP];
    __shared__ __align__(16) __nv_bfloat16 Bs_hi[BN * BKP];
    __shared__ __align__(16) __nv_bfloat16 Bs_lo[BN * BKP];
    __shared__ float sinv[2 * BM];
    __shared__ float rowss[BM];

    const int tid = threadIdx.x;
    const int lane = tid & 31;
    const int warp = tid >> 5;
    const int warpM = warp / WARPS_N;
    const int warpN = warp % WARPS_N;
    const int m0 = blockIdx.x * BM;
    const int g = lane >> 2;            // group id (0..7)
    const int kq = (lane & 3) * 2;      // k-pair base within 8

    // Per-row relation scales
    {
        int r = tid >> 7, row = tid & 127;
        int m = m0 + row;
        float c = (m < M) ? cnt[(size_t)r * N_NODES + m] : 1.0f;
        sinv[tid] = 1.0f / fmaxf(c, 1.0f);
    }
    __syncthreads();

    float acc[MT][NT][4];
#pragma unroll
    for (int i = 0; i < MT; i++)
#pragma unroll
        for (int j = 0; j < NT; j++)
#pragma unroll
            for (int q = 0; q < 4; q++) acc[i][j][q] = 0.f;

    unsigned* AsHiU = (unsigned*)As_hi;
    unsigned* AsLoU = (unsigned*)As_lo;
    unsigned* BsHiU = (unsigned*)Bs_hi;
    unsigned* BsLoU = (unsigned*)Bs_lo;

    for (int k0 = 0; k0 < KTOT; k0 += BK) {
        // ---- A tile: 128 rows x 32 cols fp32 -> bf16 hi/lo with scale ----
        {
            int row = tid >> 1, hf = tid & 1;           // 2 threads/row, 16 cols each
            int m = m0 + row;
            float s = (k0 < 128) ? 1.0f : sinv[((k0 >= 256) ? BM : 0) + row];
            unsigned hibuf[8], lobuf[8];
            if (m < M) {
                const float4* src = (const float4*)(A + (size_t)m * KTOT + k0 + hf * 16);
#pragma unroll
                for (int j = 0; j < 4; j++) {
                    float4 v = src[j];
                    split4(v, s, hibuf[j * 2], hibuf[j * 2 + 1], lobuf[j * 2], lobuf[j * 2 + 1]);
                }
            } else {
#pragma unroll
                for (int j = 0; j < 8; j++) { hibuf[j] = 0; lobuf[j] = 0; }
            }
            int base = row * (BKP / 2) + hf * 8;        // uint index
            ((uint4*)(AsHiU + base))[0] = *(uint4*)(hibuf);
            ((uint4*)(AsHiU + base))[1] = *(uint4*)(hibuf + 4);
            ((uint4*)(AsLoU + base))[0] = *(uint4*)(lobuf);
            ((uint4*)(AsLoU + base))[1] = *(uint4*)(lobuf + 4);
        }
        // ---- B tile: BN rows x 32 cols bf16 (already split) ----
        if (BN == 128) {
            int n = tid >> 1, hf = tid & 1;
            const uint4* sh = (const uint4*)(WT_hi + (size_t)n * KTOT + k0 + hf * 16);
            const uint4* sl = (const uint4*)(WT_lo + (size_t)n * KTOT + k0 + hf * 16);
            int base = n * (BKP / 2) + hf * 8;
            ((uint4*)(BsHiU + base))[0] = sh[0];
            ((uint4*)(BsHiU + base))[1] = sh[1];
            ((uint4*)(BsLoU + base))[0] = sl[0];
            ((uint4*)(BsLoU + base))[1] = sl[1];
        } else {                                        // BN == 64
            int n = tid >> 2, q = tid & 3;
            const uint4* sh = (const uint4*)(WT_hi + (size_t)n * KTOT + k0 + q * 8);
            const uint4* sl = (const uint4*)(WT_lo + (size_t)n * KTOT + k0 + q * 8);
            int base = n * (BKP / 2) + q * 4;
            *(uint4*)(BsHiU + base) = sh[0];
            *(uint4*)(BsLoU + base) = sl[0];
        }
        __syncthreads();

        // ---- compute: 2 k16-steps ----
#pragma unroll
        for (int ks = 0; ks < BK; ks += 16) {
            int kb = ks + kq;
            unsigned ah[MT][4], al[MT][4], bh[NT][2], bl[NT][2];
#pragma unroll
            for (int mt = 0; mt < MT; mt++) {
                int r0 = warpM * (MT * 16) + mt * 16 + g;
                ah[mt][0] = AsHiU[r0 * 20 + (kb >> 1)];
                ah[mt][1] = AsHiU[(r0 + 8) * 20 + (kb >> 1)];
                ah[mt][2] = AsHiU[r0 * 20 + ((kb + 8) >> 1)];
                ah[mt][3] = AsHiU[(r0 + 8) * 20 + ((kb + 8) >> 1)];
                al[mt][0] = AsLoU[r0 * 20 + (kb >> 1)];
                al[mt][1] = AsLoU[(r0 + 8) * 20 + (kb >> 1)];
                al[mt][2] = AsLoU[r0 * 20 + ((kb + 8) >> 1)];
                al[mt][3] = AsLoU[(r0 + 8) * 20 + ((kb + 8) >> 1)];
            }
#pragma unroll
            for (int nt = 0; nt < NT; nt++) {
                int n0 = warpN * (NT * 8) + nt * 8 + g;
                bh[nt][0] = BsHiU[n0 * 20 + (kb >> 1)];
                bh[nt][1] = BsHiU[n0 * 20 + ((kb + 8) >> 1)];
                bl[nt][0] = BsLoU[n0 * 20 + (kb >> 1)];
                bl[nt][1] = BsLoU[n0 * 20 + ((kb + 8) >> 1)];
            }
#pragma unroll
            for (int mt = 0; mt < MT; mt++)
#pragma unroll
                for (int nt = 0; nt < NT; nt++) {
                    mma_bf16(acc[mt][nt], ah[mt], bh[nt]);
                    mma_bf16(acc[mt][nt], ah[mt], bl[nt]);
                    mma_bf16(acc[mt][nt], al[mt], bh[nt]);
                }
        }
        __syncthreads();
    }

    // ---- epilogue: bias (+relu) ----
#pragma unroll
    for (int nt = 0; nt < NT; nt++) {
        int n = warpN * (NT * 8) + nt * 8 + kq;
        float b0 = bias[n], b1 = bias[n + 1];
#pragma unroll
        for (int mt = 0; mt < MT; mt++) {
            float* c = acc[mt][nt];
            c[0] += b0; c[1] += b1; c[2] += b0; c[3] += b1;
            if (RELU) {
                c[0] = fmaxf(c[0], 0.f); c[1] = fmaxf(c[1], 0.f);
                c[2] = fmaxf(c[2], 0.f); c[3] = fmaxf(c[3], 0.f);
            }
        }
    }

    if (L2NORM) {
        if (tid < BM) rowss[tid] = 0.f;
        __syncthreads();
#pragma unroll
        for (int mt = 0; mt < MT; mt++) {
            float ss0 = 0.f, ss1 = 0.f;
#pragma unroll
            for (int nt = 0; nt < NT; nt++) {
                ss0 += acc[mt][nt][0] * acc[mt][nt][0] + acc[mt][nt][1] * acc[mt][nt][1];
                ss1 += acc[mt][nt][2] * acc[mt][nt][2] + acc[mt][nt][3] * acc[mt][nt][3];
            }
            ss0 += __shfl_xor_sync(0xFFFFFFFFu, ss0, 1);
            ss0 += __shfl_xor_sync(0xFFFFFFFFu, ss0, 2);
            ss1 += __shfl_xor_sync(0xFFFFFFFFu, ss1, 1);
            ss1 += __shfl_xor_sync(0xFFFFFFFFu, ss1, 2);
            if ((lane & 3) == 0) {
                int lr = warpM * (MT * 16) + mt * 16 + g;
                atomicAdd(&rowss[lr], ss0);
                atomicAdd(&rowss[lr + 8], ss1);
            }
        }
        __syncthreads();
#pragma unroll
        for (int mt = 0; mt < MT; mt++) {
            int lr = warpM * (MT * 16) + mt * 16 + g;
            float s0 = 1.0f / fmaxf(sqrtf(rowss[lr]), 1e-12f);
            float s1 = 1.0f / fmaxf(sqrtf(rowss[lr + 8]), 1e-12f);
            int r0 = m0 + lr;
#pragma unroll
            for (int nt = 0; nt < NT; nt++) {
                int n = warpN * (NT * 8) + nt * 8 + kq;
                float* c = acc[mt][nt];
                if (r0 < M)
                    *(float2*)(C + (size_t)r0 * ldc + n) = make_float2(c[0] * s0, c[1] * s0);
                if (r0 + 8 < M)
                    *(float2*)(C + (size_t)(r0 + 8) * ldc + n) = make_float2(c[2] * s1, c[3] * s1);
            }
        }
    } else {
#pragma unroll
        for (int mt = 0; mt < MT; mt++) {
            int r0 = m0 + warpM * (MT * 16) + mt * 16 + g;
#pragma unroll
            for (int nt = 0; nt < NT; nt++) {
                int n = warpN * (NT * 8) + nt * 8 + kq;
                float* c = acc[mt][nt];
                if (r0 < M)
                    *(float2*)(C + (size_t)r0 * ldc + n) = make_float2(c[0], c[1]);
                if (r0 + 8 < M)
                    *(float2*)(C + (size_t)(r0 + 8) * ldc + n) = make_float2(c[2], c[3]);
            }
        }
    }

    // ---- layer-1 extra: zero the mid cols (prep for next scatter) ----
    if (RELU && Gz != nullptr) {
        // all reads of this block's rows are complete (post-syncthreads)
        for (int i = tid; i < BM * 64; i += 256) {      // 128 rows x 64 float4
            int row = i >> 6, c = i & 63;
            int m = m0 + row;
            if (m < M)
                ((float4*)(Gz + (size_t)m * KTOT + 128))[c] = make_float4(0.f, 0.f, 0.f, 0.f);
        }
    }
}

// ---------------------------------------------------------------------------
extern "C" void kernel_launch(void* const* d_in, const int* in_sizes, int n_in,
                              void* d_out, int out_size) {
    const float* x       = (const float*)d_in[0];
    const int*   ei      = (const int*)d_in[1];
    const int*   et      = (const int*)d_in[2];
    const float* W1_rel  = (const float*)d_in[3];
    const float* W1_root = (const float*)d_in[4];
    const float* b1      = (const float*)d_in[5];
    const float* W2_rel  = (const float*)d_in[6];
    const float* W2_root = (const float*)d_in[7];
    const float* b2      = (const float*)d_in[8];
    float* out = (float*)d_out;

    float *G, *cnt;
    __nv_bfloat16 *W1Th, *W1Tl, *W2Th, *W2Tl;
    cudaGetSymbolAddress((void**)&G,    g_G);
    cudaGetSymbolAddress((void**)&cnt,  g_cnt);
    cudaGetSymbolAddress((void**)&W1Th, g_W1T_hi);
    cudaGetSymbolAddress((void**)&W1Tl, g_W1T_lo);
    cudaGetSymbolAddress((void**)&W2Th, g_W2T_hi);
    cudaGetSymbolAddress((void**)&W2Tl, g_W2T_lo);

    const int TB = 256;
    const int g_prep = (192 * KTOT + TB - 1) / TB;
    const int g_init = (N_NODES * 96 + TB - 1) / TB;
    const int g_scat = ((N_EDGES * 32) + TB - 1) / TB;
    const int g_gemm = (N_NODES + 127) / 128;

    prep_w_kernel<<<g_prep, TB>>>(W1_rel, W1_root, W2_rel, W2_root);

    // ---- Layer 1 ----
    cudaMemsetAsync(cnt, 0, (size_t)2 * N_NODES * 4);
    init_G_kernel<<<g_init, TB>>>(x, G);
    scatter_kernel<<<g_scat, TB>>>(ei, et, G, cnt);
    // H = relu(scale(G) @ W1 + b1) -> G[:,0:128]; also zeros G[:,128:384]
    gemm_bf16_kernel<128, 2, 4, 4, 4, true, false><<<g_gemm, TB>>>(
        G, W1Th, W1Tl, b1, cnt, G, N_NODES, KTOT, G);

    // ---- Layer 2 ----
    cudaMemsetAsync(cnt, 0, (size_t)2 * N_NODES * 4);
    scatter_kernel<<<g_scat, TB>>>(ei, et, G, cnt);
    // out = l2norm(scale(G) @ W2 + b2)
    gemm_bf16_kernel<64, 4, 2, 2, 4, false, true><<<g_gemm, TB>>>(
        G, W2Th, W2Tl, b2, cnt, out, N_NODES, 64, nullptr);
}

// round 5
// speedup vs baseline: 1.5952x; 1.1660x over previous
#include <cuda_runtime.h>
#include <cuda_bf16.h>
#include <cstdint>

#define N_NODES 100000
#define N_EDGES 1600000
#define KTOT 384   // G cols: 0:128 x|H, 128:256 A_r0(L1)/ACC(L2), 256:384 A_r1(L1)

// ---------------------------------------------------------------------------
// Device-global scratch
__device__ float g_G[(size_t)N_NODES * KTOT];       // [N,384]
__device__ float g_P[(size_t)N_NODES * 192];        // layer-2 transformed: [root|rel0|rel1] x 64
__device__ float g_cnt[2 * N_NODES];                // per-relation in-degree (edge-only, reused)
__device__ __nv_bfloat16 g_W1T_hi[128 * KTOT];      // W1^T [n][k] bf16 hi
__device__ __nv_bfloat16 g_W1T_lo[128 * KTOT];
__device__ __nv_bfloat16 g_W2T_hi[192 * 128];       // [W2_root|W2_rel0|W2_rel1]^T [n][k]
__device__ __nv_bfloat16 g_W2T_lo[192 * 128];

// ---------------------------------------------------------------------------
__global__ void prep_w_kernel(const float* __restrict__ W1_rel,
                              const float* __restrict__ W1_root,
                              const float* __restrict__ W2_rel,
                              const float* __restrict__ W2_root) {
    int i = blockIdx.x * blockDim.x + threadIdx.x;
    const int SZ1 = 128 * KTOT;        // W1T
    const int SZ2 = 192 * 128;         // W2T
    if (i >= SZ1 + SZ2) return;
    float v;
    __nv_bfloat16 *dh, *dl;
    if (i < SZ1) {
        int n = i / KTOT, k = i % KTOT;
        if (k < 128) v = W1_root[k * 128 + n];
        else {
            int r = (k - 128) >> 7, kk = (k - 128) & 127;
            v = W1_rel[(size_t)r * 128 * 128 + kk * 128 + n];
        }
        dh = g_W1T_hi + i; dl = g_W1T_lo + i;
    } else {
        int j = i - SZ1;
        int n = j / 128, k = j % 128;
        if (n < 64)       v = W2_root[k * 64 + n];
        else if (n < 128) v = W2_rel[(size_t)0 * 128 * 64 + k * 64 + (n - 64)];
        else              v = W2_rel[(size_t)1 * 128 * 64 + k * 64 + (n - 128)];
        dh = g_W2T_hi + j; dl = g_W2T_lo + j;
    }
    __nv_bfloat16 h = __float2bfloat16(v);
    *dh = h;
    *dl = __float2bfloat16(v - __bfloat162float(h));
}

// ---------------------------------------------------------------------------
// Layer-1 init: copy x into cols 0:128 of G, zero cols 128:384
__global__ void init_G_kernel(const float* __restrict__ x, float* __restrict__ G) {
    int i = blockIdx.x * blockDim.x + threadIdx.x;      // over N*96 float4
    if (i >= N_NODES * 96) return;
    int n = i / 96, c = i % 96;
    float4* dst = (float4*)(G + (size_t)n * KTOT) + c;
    if (c < 32)
        *dst = ((const float4*)(x + (size_t)n * 128))[c];
    else
        *dst = make_float4(0.f, 0.f, 0.f, 0.f);
}

// ---------------------------------------------------------------------------
// Layer-1 scatter: one warp per edge, width-128 messages from G[src,0:128]
// into G[dst, 128 + r*128]. Lane 0 bumps the relation count.
__global__ void scatter_kernel(const int* __restrict__ ei,
                               const int* __restrict__ et,
                               float* __restrict__ G,
                               float* __restrict__ cnt) {
    int t = blockIdx.x * blockDim.x + threadIdx.x;
    int e = t >> 5;
    int lane = threadIdx.x & 31;
    if (e >= N_EDGES) return;
    int s = ei[e];
    int d = ei[N_EDGES + e];
    int r = et[e];
    float4 v = ((const float4*)(G + (size_t)s * KTOT))[lane];
    float* p = G + (size_t)d * KTOT + 128 + r * 128 + lane * 4;
    asm volatile("red.global.add.v4.f32 [%0], {%1, %2, %3, %4};"
                 :: "l"(p), "f"(v.x), "f"(v.y), "f"(v.z), "f"(v.w) : "memory");
    if (lane == 0)
        atomicAdd(cnt + (size_t)r * N_NODES + d, 1.0f);
}

// Layer-2 scatter: half-warp per edge, width-64 messages from P[src,64+r*64]
// into G[dst, 128 + r*64]. Counts reused from layer 1.
__global__ void scatter2_kernel(const int* __restrict__ ei,
                                const int* __restrict__ et,
                                const float* __restrict__ P,
                                float* __restrict__ G) {
    int t = blockIdx.x * blockDim.x + threadIdx.x;
    int e = t >> 4;
    int l = threadIdx.x & 15;
    if (e >= N_EDGES) return;
    int s = ei[e];
    int d = ei[N_EDGES + e];
    int r = et[e];
    float4 v = *(const float4*)(P + (size_t)s * 192 + 64 + r * 64 + l * 4);
    float* p = G + (size_t)d * KTOT + 128 + r * 64 + l * 4;
    asm volatile("red.global.add.v4.f32 [%0], {%1, %2, %3, %4};"
                 :: "l"(p), "f"(v.x), "f"(v.y), "f"(v.z), "f"(v.w) : "memory");
}

// ---------------------------------------------------------------------------
__device__ __forceinline__ void mma_bf16(float* c, const unsigned* a, unsigned b0, unsigned b1) {
    asm volatile(
        "mma.sync.aligned.m16n8k16.row.col.f32.bf16.bf16.f32 "
        "{%0,%1,%2,%3}, {%4,%5,%6,%7}, {%8,%9}, {%0,%1,%2,%3};"
        : "+f"(c[0]), "+f"(c[1]), "+f"(c[2]), "+f"(c[3])
        : "r"(a[0]), "r"(a[1]), "r"(a[2]), "r"(a[3]), "r"(b0), "r"(b1));
}

__device__ __forceinline__ void ldsm4(uint32_t addr, unsigned& r0, unsigned& r1,
                                      unsigned& r2, unsigned& r3) {
    asm volatile("ldmatrix.sync.aligned.m8n8.x4.shared.b16 {%0,%1,%2,%3}, [%4];"
                 : "=r"(r0), "=r"(r1), "=r"(r2), "=r"(r3) : "r"(addr));
}

__device__ __forceinline__ unsigned pack2(__nv_bfloat16 a, __nv_bfloat16 b) {
    union { __nv_bfloat162 v; unsigned u; } c;
    c.v = __halves2bfloat162(a, b);
    return c.u;
}

__device__ __forceinline__ void split4(const float4 v, float s,
                                       unsigned& hi0, unsigned& hi1,
                                       unsigned& lo0, unsigned& lo1) {
    float f0 = v.x * s, f1 = v.y * s, f2 = v.z * s, f3 = v.w * s;
    __nv_bfloat16 h0 = __float2bfloat16(f0), h1 = __float2bfloat16(f1);
    __nv_bfloat16 h2 = __float2bfloat16(f2), h3 = __float2bfloat16(f3);
    __nv_bfloat16 l0 = __float2bfloat16(f0 - __bfloat162float(h0));
    __nv_bfloat16 l1 = __float2bfloat16(f1 - __bfloat162float(h1));
    __nv_bfloat16 l2 = __float2bfloat16(f2 - __bfloat162float(h2));
    __nv_bfloat16 l3 = __float2bfloat16(f3 - __bfloat162float(h3));
    hi0 = pack2(h0, h1); hi1 = pack2(h2, h3);
    lo0 = pack2(l0, l1); lo1 = pack2(l2, l3);
}

// ---------------------------------------------------------------------------
// Tensor-core GEMM, bf16 3-term split, ldmatrix fragment loads.
// C[M,BN] = op( scale(A[M,KDIM]) @ WT^T + bias? )
// SCALE: A cols >=128 scaled by 1/max(cnt[r],1) (fused mean, layer 1)
// RELU: relu epilogue. ZEROMID: zero G[:,128:256] after (layer-2 ACC prep).
template<int BN, int KDIM, int WM, int WN, int MT, int NT, bool SCALE, bool RELU, bool ZEROMID>
__global__ void __launch_bounds__(256)
gemm_bf16_kernel(const float* __restrict__ A, int lda,
                 const __nv_bfloat16* __restrict__ WT_hi,
                 const __nv_bfloat16* __restrict__ WT_lo,
                 const float* __restrict__ bias,
                 const float* __restrict__ cnt,
                 float* __restrict__ C, int M, int ldc,
                 float* __restrict__ Gz) {
    constexpr int BM = 128, BK = 32, BKP = 40;          // pitch 40 bf16 = 80B
    __shared__ __align__(16) __nv_bfloat16 As_hi[BM * BKP];
    __shared__ __align__(16) __nv_bfloat16 As_lo[BM * BKP];
    __shared__ __align__(16) __nv_bfloat16 Bs_hi[BN * BKP];
    __shared__ __align__(16) __nv_bfloat16 Bs_lo[BN * BKP];
    __shared__ float sinv[2 * BM];

    const int tid = threadIdx.x;
    const int lane = tid & 31;
    const int warp = tid >> 5;
    const int warpM = warp / WN;
    const int warpN = warp % WN;
    const int m0 = blockIdx.x * BM;
    const int g = lane >> 2;
    const int kq = (lane & 3) * 2;

    if (SCALE) {
        int r = tid >> 7, row = tid & 127;
        int m = m0 + row;
        float c = (m < M) ? cnt[(size_t)r * N_NODES + m] : 1.0f;
        sinv[tid] = 1.0f / fmaxf(c, 1.0f);
        __syncthreads();
    }

    float acc[MT][NT][4];
#pragma unroll
    for (int i = 0; i < MT; i++)
#pragma unroll
        for (int j = 0; j < NT; j++)
#pragma unroll
            for (int q = 0; q < 4; q++) acc[i][j][q] = 0.f;

    // ldmatrix lane-address components
    const uint32_t sAhi = (uint32_t)__cvta_generic_to_shared(As_hi);
    const uint32_t sAlo = (uint32_t)__cvta_generic_to_shared(As_lo);
    const uint32_t sBhi = (uint32_t)__cvta_generic_to_shared(Bs_hi);
    const uint32_t sBlo = (uint32_t)__cvta_generic_to_shared(Bs_lo);
    const int rowA = (lane & 7) + (lane & 8);           // 0..15
    const int colA = (lane & 16) ? 8 : 0;
    const int gB = lane >> 3;                           // 0..3
    const int rowB = (lane & 7) + ((gB & 1) ? 8 : 0);
    const int colB = (gB >> 1) * 8;

    for (int k0 = 0; k0 < KDIM; k0 += BK) {
        // ---- A tile: 128 x 32 fp32 -> bf16 hi/lo (+scale) ----
        {
            int row = tid >> 1, hf = tid & 1;
            int m = m0 + row;
            float s = 1.0f;
            if (SCALE && k0 >= 128) s = sinv[((k0 >= 256) ? BM : 0) + row];
            unsigned hibuf[8], lobuf[8];
            if (m < M) {
                const float4* src = (const float4*)(A + (size_t)m * lda + k0 + hf * 16);
#pragma unroll
                for (int j = 0; j < 4; j++) {
                    float4 v = src[j];
                    split4(v, s, hibuf[j * 2], hibuf[j * 2 + 1], lobuf[j * 2], lobuf[j * 2 + 1]);
                }
            } else {
#pragma unroll
                for (int j = 0; j < 8; j++) { hibuf[j] = 0; lobuf[j] = 0; }
            }
            __nv_bfloat16* dh = As_hi + row * BKP + hf * 16;
            __nv_bfloat16* dl = As_lo + row * BKP + hf * 16;
            ((uint4*)dh)[0] = *(uint4*)(hibuf);
            ((uint4*)dh)[1] = *(uint4*)(hibuf + 4);
            ((uint4*)dl)[0] = *(uint4*)(lobuf);
            ((uint4*)dl)[1] = *(uint4*)(lobuf + 4);
        }
        // ---- B tile: BN x 32 bf16 (pre-split) ----
        for (int i = tid; i < BN * 4; i += 256) {
            int n = i >> 2, q = i & 3;
            *(uint4*)(Bs_hi + n * BKP + q * 8) = *(const uint4*)(WT_hi + (size_t)n * KDIM + k0 + q * 8);
            *(uint4*)(Bs_lo + n * BKP + q * 8) = *(const uint4*)(WT_lo + (size_t)n * KDIM + k0 + q * 8);
        }
        __syncthreads();

#pragma unroll
        for (int ks = 0; ks < BK; ks += 16) {
            unsigned ah[MT][4], al[MT][4];
#pragma unroll
            for (int mt = 0; mt < MT; mt++) {
                uint32_t off = (uint32_t)(2 * ((warpM * MT * 16 + mt * 16 + rowA) * BKP + ks + colA));
                ldsm4(sAhi + off, ah[mt][0], ah[mt][1], ah[mt][2], ah[mt][3]);
                ldsm4(sAlo + off, al[mt][0], al[mt][1], al[mt][2], al[mt][3]);
            }
            unsigned bh0[NT], bh1[NT], bl0[NT], bl1[NT];
#pragma unroll
            for (int np = 0; np < NT / 2; np++) {
                uint32_t off = (uint32_t)(2 * ((warpN * NT * 8 + np * 16 + rowB) * BKP + ks + colB));
                ldsm4(sBhi + off, bh0[np * 2], bh0[np * 2 + 1], bh1[np * 2], bh1[np * 2 + 1]);
                ldsm4(sBlo + off, bl0[np * 2], bl0[np * 2 + 1], bl1[np * 2], bl1[np * 2 + 1]);
            }
#pragma unroll
            for (int mt = 0; mt < MT; mt++)
#pragma unroll
                for (int nt = 0; nt < NT; nt++) {
                    mma_bf16(acc[mt][nt], ah[mt], bh0[nt], bh1[nt]);
                    mma_bf16(acc[mt][nt], ah[mt], bl0[nt], bl1[nt]);
                    mma_bf16(acc[mt][nt], al[mt], bh0[nt], bh1[nt]);
                }
        }
        __syncthreads();
    }

    // ---- epilogue ----
#pragma unroll
    for (int nt = 0; nt < NT; nt++) {
        int n = warpN * NT * 8 + nt * 8 + kq;
        float b0 = bias ? bias[n] : 0.f;
        float b1 = bias ? bias[n + 1] : 0.f;
#pragma unroll
        for (int mt = 0; mt < MT; mt++) {
            float* c = acc[mt][nt];
            c[0] += b0; c[1] += b1; c[2] += b0; c[3] += b1;
            if (RELU) {
                c[0] = fmaxf(c[0], 0.f); c[1] = fmaxf(c[1], 0.f);
                c[2] = fmaxf(c[2], 0.f); c[3] = fmaxf(c[3], 0.f);
            }
        }
    }
#pragma unroll
    for (int mt = 0; mt < MT; mt++) {
        int r0 = m0 + warpM * MT * 16 + mt * 16 + g;
#pragma unroll
        for (int nt = 0; nt < NT; nt++) {
            int n = warpN * NT * 8 + nt * 8 + kq;
            float* c = acc[mt][nt];
            if (r0 < M)
                *(float2*)(C + (size_t)r0 * ldc + n) = make_float2(c[0], c[1]);
            if (r0 + 8 < M)
                *(float2*)(C + (size_t)(r0 + 8) * ldc + n) = make_float2(c[2], c[3]);
        }
    }

    if (ZEROMID && Gz != nullptr) {
        for (int i = tid; i < BM * 32; i += 256) {      // 128 rows x 32 float4 (cols 128:256)
            int row = i >> 5, c = i & 31;
            int m = m0 + row;
            if (m < M)
                ((float4*)(Gz + (size_t)m * KTOT + 128))[c] = make_float4(0.f, 0.f, 0.f, 0.f);
        }
    }
}

// ---------------------------------------------------------------------------
// Final epilogue: out = l2norm(P[:,0:64] + ACC0/c0 + ACC1/c1 + b2)
__global__ void out_epilogue_kernel(const float* __restrict__ P,
                                    const float* __restrict__ G,
                                    const float* __restrict__ cnt,
                                    const float* __restrict__ b2,
                                    float* __restrict__ out) {
    int t = blockIdx.x * blockDim.x + threadIdx.x;
    int n = t >> 4;
    int l = t & 15;
    if (n >= N_NODES) return;
    float s0 = 1.0f / fmaxf(cnt[n], 1.0f);
    float s1 = 1.0f / fmaxf(cnt[N_NODES + n], 1.0f);
    float4 p  = *(const float4*)(P + (size_t)n * 192 + l * 4);
    float4 a0 = *(const float4*)(G + (size_t)n * KTOT + 128 + l * 4);
    float4 a1 = *(const float4*)(G + (size_t)n * KTOT + 192 + l * 4);
    float4 bb = *(const float4*)(b2 + l * 4);
    float4 v;
    v.x = p.x + a0.x * s0 + a1.x * s1 + bb.x;
    v.y = p.y + a0.y * s0 + a1.y * s1 + bb.y;
    v.z = p.z + a0.z * s0 + a1.z * s1 + bb.z;
    v.w = p.w + a0.w * s0 + a1.w * s1 + bb.w;
    float ss = v.x * v.x + v.y * v.y + v.z * v.z + v.w * v.w;
#pragma unroll
    for (int o = 8; o; o >>= 1) ss += __shfl_xor_sync(0xFFFFFFFFu, ss, o);
    float s = 1.0f / fmaxf(sqrtf(ss), 1e-12f);
    v.x *= s; v.y *= s; v.z *= s; v.w *= s;
    *(float4*)(out + (size_t)n * 64 + l * 4) = v;
}

// ---------------------------------------------------------------------------
extern "C" void kernel_launch(void* const* d_in, const int* in_sizes, int n_in,
                              void* d_out, int out_size) {
    const float* x       = (const float*)d_in[0];
    const int*   ei      = (const int*)d_in[1];
    const int*   et      = (const int*)d_in[2];
    const float* W1_rel  = (const float*)d_in[3];
    const float* W1_root = (const float*)d_in[4];
    const float* b1      = (const float*)d_in[5];
    const float* W2_rel  = (const float*)d_in[6];
    const float* W2_root = (const float*)d_in[7];
    const float* b2      = (const float*)d_in[8];
    float* out = (float*)d_out;

    float *G, *P, *cnt;
    __nv_bfloat16 *W1Th, *W1Tl, *W2Th, *W2Tl;
    cudaGetSymbolAddress((void**)&G,    g_G);
    cudaGetSymbolAddress((void**)&P,    g_P);
    cudaGetSymbolAddress((void**)&cnt,  g_cnt);
    cudaGetSymbolAddress((void**)&W1Th, g_W1T_hi);
    cudaGetSymbolAddress((void**)&W1Tl, g_W1T_lo);
    cudaGetSymbolAddress((void**)&W2Th, g_W2T_hi);
    cudaGetSymbolAddress((void**)&W2Tl, g_W2T_lo);

    const int TB = 256;
    const int g_prep = (128 * KTOT + 192 * 128 + TB - 1) / TB;
    const int g_init = (N_NODES * 96 + TB - 1) / TB;
    const int g_sc1  = ((N_EDGES * 32) + TB - 1) / TB;
    const int g_sc2  = ((N_EDGES * 16) + TB - 1) / TB;
    const int g_gemm = (N_NODES + 127) / 128;
    const int g_epi  = (N_NODES * 16 + TB - 1) / TB;

    prep_w_kernel<<<g_prep, TB>>>(W1_rel, W1_root, W2_rel, W2_root);

    // ---- Layer 1 ----
    cudaMemsetAsync(cnt, 0, (size_t)2 * N_NODES * 4);
    init_G_kernel<<<g_init, TB>>>(x, G);
    scatter_kernel<<<g_sc1, TB>>>(ei, et, G, cnt);
    // H = relu(scale(G) @ W1 + b1) -> G[:,0:128]; zero G[:,128:256] (layer-2 ACC)
    gemm_bf16_kernel<128, KTOT, 2, 4, 4, 4, true, true, true><<<g_gemm, TB>>>(
        G, KTOT, W1Th, W1Tl, b1, cnt, G, N_NODES, KTOT, G);

    // ---- Layer 2 ----
    // P = H @ [W2_root|W2_rel0|W2_rel1]  (3 N-slices of 64)
    dim3 grid2(g_gemm, 3);
    for (int y = 0; y < 3; y++) {
        gemm_bf16_kernel<64, 128, 4, 2, 2, 4, false, false, false><<<g_gemm, TB>>>(
            G, KTOT, W2Th + (size_t)y * 64 * 128, W2Tl + (size_t)y * 64 * 128,
            nullptr, nullptr, P + y * 64, N_NODES, 192, nullptr);
    }
    scatter2_kernel<<<g_sc2, TB>>>(ei, et, P, G);
    out_epilogue_kernel<<<g_epi, TB>>>(P, G, cnt, b2, out);
}

// round 6
// speedup vs baseline: 1.6495x; 1.0341x over previous
#include <cuda_runtime.h>
#include <cuda_bf16.h>
#include <cstdint>

#define N_NODES 100000
#define N_EDGES 1600000
#define KTOT 384   // G cols: 0:128 x, 128:256 A_r0(L1)/ACC(L2), 256:384 A_r1(L1)

// ---------------------------------------------------------------------------
// Device-global scratch
__device__ float g_G[(size_t)N_NODES * KTOT];       // [N,384]
__device__ float g_P[(size_t)N_NODES * 192];        // layer-2 transformed [root|rel0|rel1] x 64
__device__ float g_cnt[2 * N_NODES];                // per-relation in-degree (edge-only, reused)
__device__ __nv_bfloat16 g_H_hi[(size_t)N_NODES * 128];  // H pre-split bf16
__device__ __nv_bfloat16 g_H_lo[(size_t)N_NODES * 128];
__device__ __nv_bfloat16 g_W1T_hi[128 * KTOT];      // W1^T [n][k]
__device__ __nv_bfloat16 g_W1T_lo[128 * KTOT];
__device__ __nv_bfloat16 g_W2T_hi[192 * 128];       // [W2_root|W2_rel0|W2_rel1]^T [n][k]
__device__ __nv_bfloat16 g_W2T_lo[192 * 128];

// ---------------------------------------------------------------------------
__global__ void prep_w_kernel(const float* __restrict__ W1_rel,
                              const float* __restrict__ W1_root,
                              const float* __restrict__ W2_rel,
                              const float* __restrict__ W2_root) {
    int i = blockIdx.x * blockDim.x + threadIdx.x;
    const int SZ1 = 128 * KTOT;
    const int SZ2 = 192 * 128;
    if (i >= SZ1 + SZ2) return;
    float v;
    __nv_bfloat16 *dh, *dl;
    if (i < SZ1) {
        int n = i / KTOT, k = i % KTOT;
        if (k < 128) v = W1_root[k * 128 + n];
        else {
            int r = (k - 128) >> 7, kk = (k - 128) & 127;
            v = W1_rel[(size_t)r * 128 * 128 + kk * 128 + n];
        }
        dh = g_W1T_hi + i; dl = g_W1T_lo + i;
    } else {
        int j = i - SZ1;
        int n = j / 128, k = j % 128;
        if (n < 64)       v = W2_root[k * 64 + n];
        else if (n < 128) v = W2_rel[(size_t)0 * 128 * 64 + k * 64 + (n - 64)];
        else              v = W2_rel[(size_t)1 * 128 * 64 + k * 64 + (n - 128)];
        dh = g_W2T_hi + j; dl = g_W2T_lo + j;
    }
    __nv_bfloat16 h = __float2bfloat16(v);
    *dh = h;
    *dl = __float2bfloat16(v - __bfloat162float(h));
}

// ---------------------------------------------------------------------------
// Layer-1 init: copy x into cols 0:128 of G, zero cols 128:384
__global__ void init_G_kernel(const float* __restrict__ x, float* __restrict__ G) {
    int i = blockIdx.x * blockDim.x + threadIdx.x;      // over N*96 float4
    if (i >= N_NODES * 96) return;
    int n = i / 96, c = i % 96;
    float4* dst = (float4*)(G + (size_t)n * KTOT) + c;
    if (c < 32)
        *dst = ((const float4*)(x + (size_t)n * 128))[c];
    else
        *dst = make_float4(0.f, 0.f, 0.f, 0.f);
}

// ---------------------------------------------------------------------------
// Layer-1 scatter: one warp per edge, width-128 messages from G[src,0:128]
__global__ void scatter_kernel(const int* __restrict__ ei,
                               const int* __restrict__ et,
                               float* __restrict__ G,
                               float* __restrict__ cnt) {
    int t = blockIdx.x * blockDim.x + threadIdx.x;
    int e = t >> 5;
    int lane = threadIdx.x & 31;
    if (e >= N_EDGES) return;
    int s = ei[e];
    int d = ei[N_EDGES + e];
    int r = et[e];
    float4 v = ((const float4*)(G + (size_t)s * KTOT))[lane];
    float* p = G + (size_t)d * KTOT + 128 + r * 128 + lane * 4;
    asm volatile("red.global.add.v4.f32 [%0], {%1, %2, %3, %4};"
                 :: "l"(p), "f"(v.x), "f"(v.y), "f"(v.z), "f"(v.w) : "memory");
    if (lane == 0)
        atomicAdd(cnt + (size_t)r * N_NODES + d, 1.0f);
}

// Layer-2 scatter: half-warp per edge, width-64 messages from P[src,64+r*64]
__global__ void scatter2_kernel(const int* __restrict__ ei,
                                const int* __restrict__ et,
                                const float* __restrict__ P,
                                float* __restrict__ G) {
    int t = blockIdx.x * blockDim.x + threadIdx.x;
    int e = t >> 4;
    int l = threadIdx.x & 15;
    if (e >= N_EDGES) return;
    int s = ei[e];
    int d = ei[N_EDGES + e];
    int r = et[e];
    float4 v = *(const float4*)(P + (size_t)s * 192 + 64 + r * 64 + l * 4);
    float* p = G + (size_t)d * KTOT + 128 + r * 64 + l * 4;
    asm volatile("red.global.add.v4.f32 [%0], {%1, %2, %3, %4};"
                 :: "l"(p), "f"(v.x), "f"(v.y), "f"(v.z), "f"(v.w) : "memory");
}

// ---------------------------------------------------------------------------
__device__ __forceinline__ void mma_bf16(float* c, const unsigned* a, unsigned b0, unsigned b1) {
    asm volatile(
        "mma.sync.aligned.m16n8k16.row.col.f32.bf16.bf16.f32 "
        "{%0,%1,%2,%3}, {%4,%5,%6,%7}, {%8,%9}, {%0,%1,%2,%3};"
        : "+f"(c[0]), "+f"(c[1]), "+f"(c[2]), "+f"(c[3])
        : "r"(a[0]), "r"(a[1]), "r"(a[2]), "r"(a[3]), "r"(b0), "r"(b1));
}

__device__ __forceinline__ void ldsm4(uint32_t addr, unsigned& r0, unsigned& r1,
                                      unsigned& r2, unsigned& r3) {
    asm volatile("ldmatrix.sync.aligned.m8n8.x4.shared.b16 {%0,%1,%2,%3}, [%4];"
                 : "=r"(r0), "=r"(r1), "=r"(r2), "=r"(r3) : "r"(addr));
}

__device__ __forceinline__ void cp16(void* dst_smem, const void* src) {
    uint32_t d = (uint32_t)__cvta_generic_to_shared(dst_smem);
    asm volatile("cp.async.ca.shared.global [%0], [%1], 16;" :: "r"(d), "l"(src));
}

__device__ __forceinline__ unsigned pack2(__nv_bfloat16 a, __nv_bfloat16 b) {
    union { __nv_bfloat162 v; unsigned u; } c;
    c.v = __halves2bfloat162(a, b);
    return c.u;
}

__device__ __forceinline__ void split4(const float4 v, float s,
                                       unsigned& hi0, unsigned& hi1,
                                       unsigned& lo0, unsigned& lo1) {
    float f0 = v.x * s, f1 = v.y * s, f2 = v.z * s, f3 = v.w * s;
    __nv_bfloat16 h0 = __float2bfloat16(f0), h1 = __float2bfloat16(f1);
    __nv_bfloat16 h2 = __float2bfloat16(f2), h3 = __float2bfloat16(f3);
    __nv_bfloat16 l0 = __float2bfloat16(f0 - __bfloat162float(h0));
    __nv_bfloat16 l1 = __float2bfloat16(f1 - __bfloat162float(h1));
    __nv_bfloat16 l2 = __float2bfloat16(f2 - __bfloat162float(h2));
    __nv_bfloat16 l3 = __float2bfloat16(f3 - __bfloat162float(h3));
    hi0 = pack2(h0, h1); hi1 = pack2(h2, h3);
    lo0 = pack2(l0, l1); lo1 = pack2(l2, l3);
}

// ---------------------------------------------------------------------------
// Double-buffered tensor-core GEMM, bf16 3-term split.
// AFP32: A is fp32 (convert+scale inline). else A is pre-split bf16 (Ah/Al).
// HOUT: write result as pre-split bf16 H (relu'd); else fp32 C.
// gridDim.y slices the weight/output N dimension by BN.
template<int BN, int KDIM, int WM, int WN, int MT, int NT,
         bool AFP32, bool SCALE, bool RELU, bool HOUT, bool ZEROMID>
__global__ void __launch_bounds__(256, 2)
gemm_db_kernel(const float* __restrict__ A32,
               const __nv_bfloat16* __restrict__ Ah,
               const __nv_bfloat16* __restrict__ Al, int lda,
               const __nv_bfloat16* __restrict__ WT_hi,
               const __nv_bfloat16* __restrict__ WT_lo,
               const float* __restrict__ bias,
               const float* __restrict__ cnt,
               float* __restrict__ C, int M, int ldc,
               __nv_bfloat16* __restrict__ Hh,
               __nv_bfloat16* __restrict__ Hl,
               float* __restrict__ Gz) {
    constexpr int BM = 128, BK = 32, BKP = 40;          // pitch 40 bf16 = 80B
    constexpr int ASZ = BM * BKP;                       // elements
    constexpr int BSZ = BN * BKP;
    constexpr int T = KDIM / BK;

    extern __shared__ __align__(16) char smem_raw[];
    __nv_bfloat16* As_hi[2]; __nv_bfloat16* As_lo[2];
    __nv_bfloat16* Bs_hi[2]; __nv_bfloat16* Bs_lo[2];
    {
        __nv_bfloat16* p = (__nv_bfloat16*)smem_raw;
        As_hi[0] = p;            As_lo[0] = p + ASZ;
        As_hi[1] = p + 2 * ASZ;  As_lo[1] = p + 3 * ASZ;
        p += 4 * ASZ;
        Bs_hi[0] = p;            Bs_lo[0] = p + BSZ;
        Bs_hi[1] = p + 2 * BSZ;  Bs_lo[1] = p + 3 * BSZ;
    }
    float* sinv = (float*)(smem_raw + (4 * ASZ + 4 * BSZ) * 2);

    const int tid = threadIdx.x;
    const int lane = tid & 31;
    const int warp = tid >> 5;
    const int warpM = warp / WN;
    const int warpN = warp % WN;
    const int m0 = blockIdx.x * BM;
    const int g = lane >> 2;
    const int kq = (lane & 3) * 2;

    // weight/output slice
    const __nv_bfloat16* Wh = WT_hi + (size_t)blockIdx.y * BN * KDIM;
    const __nv_bfloat16* Wl = WT_lo + (size_t)blockIdx.y * BN * KDIM;

    if (SCALE) {
        int r = tid >> 7, row = tid & 127;
        int m = m0 + row;
        float c = (m < M) ? cnt[(size_t)r * N_NODES + m] : 1.0f;
        sinv[tid] = 1.0f / fmaxf(c, 1.0f);
        __syncthreads();
    }

    float acc[MT][NT][4];
#pragma unroll
    for (int i = 0; i < MT; i++)
#pragma unroll
        for (int j = 0; j < NT; j++)
#pragma unroll
            for (int q = 0; q < 4; q++) acc[i][j][q] = 0.f;

    // ---- loaders ----
    const int rowT = tid >> 1, hfT = tid & 1;           // A fp32: 2 threads/row
    const int mClamp = (m0 + rowT < M) ? (m0 + rowT) : (M - 1);

    auto loadB = [&](int k0, int stg) {
#pragma unroll
        for (int i = tid; i < BN * 4; i += 256) {
            int n = i >> 2, q = i & 3;
            cp16(Bs_hi[stg] + n * BKP + q * 8, Wh + (size_t)n * KDIM + k0 + q * 8);
            cp16(Bs_lo[stg] + n * BKP + q * 8, Wl + (size_t)n * KDIM + k0 + q * 8);
        }
    };
    auto loadA_cp = [&](int k0, int stg) {              // pre-split bf16 A
#pragma unroll
        for (int i = tid; i < BM * 4; i += 256) {
            int row = i >> 2, q = i & 3;
            int m = (m0 + row < M) ? (m0 + row) : (M - 1);
            cp16(As_hi[stg] + row * BKP + q * 8, Ah + (size_t)m * lda + k0 + q * 8);
            cp16(As_lo[stg] + row * BKP + q * 8, Al + (size_t)m * lda + k0 + q * 8);
        }
    };
    float4 pref[4];
    auto ldgA = [&](int k0) {
        const float4* src = (const float4*)(A32 + (size_t)mClamp * lda + k0 + hfT * 16);
#pragma unroll
        for (int j = 0; j < 4; j++) pref[j] = src[j];
    };
    auto convA = [&](int k0, int stg) {
        float s = 1.0f;
        if (SCALE && k0 >= 128) s = sinv[((k0 >= 256) ? BM : 0) + rowT];
        unsigned hibuf[8], lobuf[8];
#pragma unroll
        for (int j = 0; j < 4; j++)
            split4(pref[j], s, hibuf[j * 2], hibuf[j * 2 + 1], lobuf[j * 2], lobuf[j * 2 + 1]);
        __nv_bfloat16* dh = As_hi[stg] + rowT * BKP + hfT * 16;
        __nv_bfloat16* dl = As_lo[stg] + rowT * BKP + hfT * 16;
        ((uint4*)dh)[0] = *(uint4*)(hibuf);
        ((uint4*)dh)[1] = *(uint4*)(hibuf + 4);
        ((uint4*)dl)[0] = *(uint4*)(lobuf);
        ((uint4*)dl)[1] = *(uint4*)(lobuf + 4);
    };

    // ---- ldmatrix lane addressing ----
    const int rowA = (lane & 7) + (lane & 8);
    const int colA = (lane & 16) ? 8 : 0;
    const int gB = lane >> 3;
    const int rowB = (lane & 7) + ((gB & 1) ? 8 : 0);
    const int colB = (gB >> 1) * 8;

    uint32_t sAhi[2], sAlo[2], sBhi[2], sBlo[2];
#pragma unroll
    for (int s = 0; s < 2; s++) {
        sAhi[s] = (uint32_t)__cvta_generic_to_shared(As_hi[s]);
        sAlo[s] = (uint32_t)__cvta_generic_to_shared(As_lo[s]);
        sBhi[s] = (uint32_t)__cvta_generic_to_shared(Bs_hi[s]);
        sBlo[s] = (uint32_t)__cvta_generic_to_shared(Bs_lo[s]);
    }

    auto compute = [&](int stg) {
#pragma unroll
        for (int ks = 0; ks < BK; ks += 16) {
            unsigned ah[MT][4], al[MT][4];
#pragma unroll
            for (int mt = 0; mt < MT; mt++) {
                uint32_t off = (uint32_t)(2 * ((warpM * MT * 16 + mt * 16 + rowA) * BKP + ks + colA));
                ldsm4(sAhi[stg] + off, ah[mt][0], ah[mt][1], ah[mt][2], ah[mt][3]);
                ldsm4(sAlo[stg] + off, al[mt][0], al[mt][1], al[mt][2], al[mt][3]);
            }
            unsigned bh0[NT], bh1[NT], bl0[NT], bl1[NT];
#pragma unroll
            for (int np = 0; np < NT / 2; np++) {
                uint32_t off = (uint32_t)(2 * ((warpN * NT * 8 + np * 16 + rowB) * BKP + ks + colB));
                ldsm4(sBhi[stg] + off, bh0[np * 2], bh0[np * 2 + 1], bh1[np * 2], bh1[np * 2 + 1]);
                ldsm4(sBlo[stg] + off, bl0[np * 2], bl0[np * 2 + 1], bl1[np * 2], bl1[np * 2 + 1]);
            }
#pragma unroll
            for (int mt = 0; mt < MT; mt++)
#pragma unroll
                for (int nt = 0; nt < NT; nt++) {
                    mma_bf16(acc[mt][nt], ah[mt], bh0[nt], bh1[nt]);
                    mma_bf16(acc[mt][nt], ah[mt], bl0[nt], bl1[nt]);
                    mma_bf16(acc[mt][nt], al[mt], bh0[nt], bh1[nt]);
                }
        }
    };

    // ---- prologue: fill stage 0 ----
    loadB(0, 0);
    if (AFP32) { ldgA(0); convA(0, 0); }
    else loadA_cp(0, 0);
    asm volatile("cp.async.commit_group;\ncp.async.wait_group 0;" ::: "memory");
    __syncthreads();

    // ---- mainloop ----
    for (int t = 0; t < T; t++) {
        int cur = t & 1, nxt = cur ^ 1;
        bool hasNext = (t + 1 < T);
        int k1 = (t + 1) * BK;
        if (hasNext) {
            loadB(k1, nxt);
            if (AFP32) ldgA(k1);
            else loadA_cp(k1, nxt);
        }
        compute(cur);
        if (AFP32 && hasNext) convA(k1, nxt);
        asm volatile("cp.async.commit_group;\ncp.async.wait_group 0;" ::: "memory");
        __syncthreads();
    }

    // ---- epilogue ----
#pragma unroll
    for (int nt = 0; nt < NT; nt++) {
        int n = warpN * NT * 8 + nt * 8 + kq;
        float b0 = bias ? bias[n] : 0.f;
        float b1 = bias ? bias[n + 1] : 0.f;
#pragma unroll
        for (int mt = 0; mt < MT; mt++) {
            float* c = acc[mt][nt];
            c[0] += b0; c[1] += b1; c[2] += b0; c[3] += b1;
            if (RELU) {
                c[0] = fmaxf(c[0], 0.f); c[1] = fmaxf(c[1], 0.f);
                c[2] = fmaxf(c[2], 0.f); c[3] = fmaxf(c[3], 0.f);
            }
        }
    }

    if (HOUT) {
#pragma unroll
        for (int mt = 0; mt < MT; mt++) {
            int r0 = m0 + warpM * MT * 16 + mt * 16 + g;
#pragma unroll
            for (int nt = 0; nt < NT; nt++) {
                int n = warpN * NT * 8 + nt * 8 + kq;
                float* c = acc[mt][nt];
                if (r0 < M) {
                    __nv_bfloat16 h0 = __float2bfloat16(c[0]);
                    __nv_bfloat16 h1 = __float2bfloat16(c[1]);
                    *(unsigned*)(Hh + (size_t)r0 * 128 + n) = pack2(h0, h1);
                    *(unsigned*)(Hl + (size_t)r0 * 128 + n) =
                        pack2(__float2bfloat16(c[0] - __bfloat162float(h0)),
                              __float2bfloat16(c[1] - __bfloat162float(h1)));
                }
                if (r0 + 8 < M) {
                    __nv_bfloat16 h2 = __float2bfloat16(c[2]);
                    __nv_bfloat16 h3 = __float2bfloat16(c[3]);
                    *(unsigned*)(Hh + (size_t)(r0 + 8) * 128 + n) = pack2(h2, h3);
                    *(unsigned*)(Hl + (size_t)(r0 + 8) * 128 + n) =
                        pack2(__float2bfloat16(c[2] - __bfloat162float(h2)),
                              __float2bfloat16(c[3] - __bfloat162float(h3)));
                }
            }
        }
    } else {
        float* Cb = C + (size_t)blockIdx.y * BN;
#pragma unroll
        for (int mt = 0; mt < MT; mt++) {
            int r0 = m0 + warpM * MT * 16 + mt * 16 + g;
#pragma unroll
            for (int nt = 0; nt < NT; nt++) {
                int n = warpN * NT * 8 + nt * 8 + kq;
                float* c = acc[mt][nt];
                if (r0 < M)
                    *(float2*)(Cb + (size_t)r0 * ldc + n) = make_float2(c[0], c[1]);
                if (r0 + 8 < M)
                    *(float2*)(Cb + (size_t)(r0 + 8) * ldc + n) = make_float2(c[2], c[3]);
            }
        }
    }

    if (ZEROMID && Gz != nullptr) {
        for (int i = tid; i < BM * 32; i += 256) {      // cols 128:256
            int row = i >> 5, c = i & 31;
            int m = m0 + row;
            if (m < M)
                ((float4*)(Gz + (size_t)m * KTOT + 128))[c] = make_float4(0.f, 0.f, 0.f, 0.f);
        }
    }
}

// ---------------------------------------------------------------------------
// Final epilogue: out = l2norm(P[:,0:64] + ACC0/c0 + ACC1/c1 + b2)
__global__ void out_epilogue_kernel(const float* __restrict__ P,
                                    const float* __restrict__ G,
                                    const float* __restrict__ cnt,
                                    const float* __restrict__ b2,
                                    float* __restrict__ out) {
    int t = blockIdx.x * blockDim.x + threadIdx.x;
    int n = t >> 4;
    int l = t & 15;
    if (n >= N_NODES) return;
    float s0 = 1.0f / fmaxf(cnt[n], 1.0f);
    float s1 = 1.0f / fmaxf(cnt[N_NODES + n], 1.0f);
    float4 p  = *(const float4*)(P + (size_t)n * 192 + l * 4);
    float4 a0 = *(const float4*)(G + (size_t)n * KTOT + 128 + l * 4);
    float4 a1 = *(const float4*)(G + (size_t)n * KTOT + 192 + l * 4);
    float4 bb = *(const float4*)(b2 + l * 4);
    float4 v;
    v.x = p.x + a0.x * s0 + a1.x * s1 + bb.x;
    v.y = p.y + a0.y * s0 + a1.y * s1 + bb.y;
    v.z = p.z + a0.z * s0 + a1.z * s1 + bb.z;
    v.w = p.w + a0.w * s0 + a1.w * s1 + bb.w;
    float ss = v.x * v.x + v.y * v.y + v.z * v.z + v.w * v.w;
#pragma unroll
    for (int o = 8; o; o >>= 1) ss += __shfl_xor_sync(0xFFFFFFFFu, ss, o);
    float s = 1.0f / fmaxf(sqrtf(ss), 1e-12f);
    v.x *= s; v.y *= s; v.z *= s; v.w *= s;
    *(float4*)(out + (size_t)n * 64 + l * 4) = v;
}

// ---------------------------------------------------------------------------
extern "C" void kernel_launch(void* const* d_in, const int* in_sizes, int n_in,
                              void* d_out, int out_size) {
    const float* x       = (const float*)d_in[0];
    const int*   ei      = (const int*)d_in[1];
    const int*   et      = (const int*)d_in[2];
    const float* W1_rel  = (const float*)d_in[3];
    const float* W1_root = (const float*)d_in[4];
    const float* b1      = (const float*)d_in[5];
    const float* W2_rel  = (const float*)d_in[6];
    const float* W2_root = (const float*)d_in[7];
    const float* b2      = (const float*)d_in[8];
    float* out = (float*)d_out;

    float *G, *P, *cnt;
    __nv_bfloat16 *Hh, *Hl, *W1Th, *W1Tl, *W2Th, *W2Tl;
    cudaGetSymbolAddress((void**)&G,    g_G);
    cudaGetSymbolAddress((void**)&P,    g_P);
    cudaGetSymbolAddress((void**)&cnt,  g_cnt);
    cudaGetSymbolAddress((void**)&Hh,   g_H_hi);
    cudaGetSymbolAddress((void**)&Hl,   g_H_lo);
    cudaGetSymbolAddress((void**)&W1Th, g_W1T_hi);
    cudaGetSymbolAddress((void**)&W1Tl, g_W1T_lo);
    cudaGetSymbolAddress((void**)&W2Th, g_W2T_hi);
    cudaGetSymbolAddress((void**)&W2Tl, g_W2T_lo);

    // dynamic smem sizes: 4 A bufs + 4 B bufs (+sinv)
    const int SM1 = (4 * 128 * 40 + 4 * 128 * 40) * 2 + 2 * 128 * 4;   // 82944
    const int SM2 = (4 * 128 * 40 + 4 * 64 * 40) * 2;                  // 61440
    auto* k1 = gemm_db_kernel<128, 384, 2, 4, 4, 4, true,  true,  true,  true,  true>;
    auto* k2 = gemm_db_kernel<64,  128, 4, 2, 2, 4, false, false, false, false, false>;
    cudaFuncSetAttribute(k1, cudaFuncAttributeMaxDynamicSharedMemorySize, SM1);
    cudaFuncSetAttribute(k2, cudaFuncAttributeMaxDynamicSharedMemorySize, SM2);

    const int TB = 256;
    const int g_prep = (128 * KTOT + 192 * 128 + TB - 1) / TB;
    const int g_init = (N_NODES * 96 + TB - 1) / TB;
    const int g_sc1  = ((N_EDGES * 32) + TB - 1) / TB;
    const int g_sc2  = ((N_EDGES * 16) + TB - 1) / TB;
    const int g_gemm = (N_NODES + 127) / 128;
    const int g_epi  = (N_NODES * 16 + TB - 1) / TB;

    prep_w_kernel<<<g_prep, TB>>>(W1_rel, W1_root, W2_rel, W2_root);

    // ---- Layer 1 ----
    cudaMemsetAsync(cnt, 0, (size_t)2 * N_NODES * 4);
    init_G_kernel<<<g_init, TB>>>(x, G);
    scatter_kernel<<<g_sc1, TB>>>(ei, et, G, cnt);
    // H = relu(scale(G)@W1 + b1) -> pre-split bf16 Hh/Hl; zero G[:,128:256]
    k1<<<g_gemm, TB, SM1>>>(G, nullptr, nullptr, KTOT, W1Th, W1Tl, b1, cnt,
                            nullptr, N_NODES, 0, Hh, Hl, G);

    // ---- Layer 2 ----
    // P = H @ [W2_root|W2_rel0|W2_rel1]  (grid.y slices N by 64)
    k2<<<dim3(g_gemm, 3), TB, SM2>>>(nullptr, Hh, Hl, 128, W2Th, W2Tl, nullptr, nullptr,
                                     P, N_NODES, 192, nullptr, nullptr, nullptr);
    scatter2_kernel<<<g_sc2, TB>>>(ei, et, P, G);
    out_epilogue_kernel<<<g_epi, TB>>>(P, G, cnt, b2, out);
}

// round 8
// speedup vs baseline: 2.0548x; 1.2457x over previous
#include <cuda_runtime.h>
#include <cuda_bf16.h>
#include <cstdint>

#define N_NODES 100000
#define N_EDGES 1600000
#define KTOT 384

// ---------------------------------------------------------------------------
// Device-global scratch
__device__ float g_AGG[(size_t)N_NODES * 256];      // scaled A0|A1 (layer-1 agg out)
__device__ float g_P[(size_t)N_NODES * 192];        // layer-2 transformed [root|rel0|rel1] x 64
__device__ __nv_bfloat16 g_H_hi[(size_t)N_NODES * 128];
__device__ __nv_bfloat16 g_H_lo[(size_t)N_NODES * 128];
__device__ __nv_bfloat16 g_W1T_hi[128 * KTOT];
__device__ __nv_bfloat16 g_W1T_lo[128 * KTOT];
__device__ __nv_bfloat16 g_W2T_hi[192 * 128];
__device__ __nv_bfloat16 g_W2T_lo[192 * 128];
__device__ int g_deg[N_NODES];
__device__ int g_offs[N_NODES];
__device__ int g_cursor[N_NODES];
__device__ int g_csr[N_EDGES];                      // src | (rel<<30), grouped by dst

// ---------------------------------------------------------------------------
__global__ void __launch_bounds__(256)
prep_w_kernel(const float* __restrict__ W1_rel,
              const float* __restrict__ W1_root,
              const float* __restrict__ W2_rel,
              const float* __restrict__ W2_root) {
    int i = blockIdx.x * blockDim.x + threadIdx.x;
    const int SZ1 = 128 * KTOT;
    const int SZ2 = 192 * 128;
    if (i >= SZ1 + SZ2) return;
    float v;
    __nv_bfloat16 *dh, *dl;
    if (i < SZ1) {
        int n = i / KTOT, k = i % KTOT;
        if (k < 128) v = W1_root[k * 128 + n];
        else {
            int r = (k - 128) >> 7, kk = (k - 128) & 127;
            v = W1_rel[(size_t)r * 128 * 128 + kk * 128 + n];
        }
        dh = g_W1T_hi + i; dl = g_W1T_lo + i;
    } else {
        int j = i - SZ1;
        int n = j / 128, k = j % 128;
        if (n < 64)       v = W2_root[k * 64 + n];
        else if (n < 128) v = W2_rel[(size_t)0 * 128 * 64 + k * 64 + (n - 64)];
        else              v = W2_rel[(size_t)1 * 128 * 64 + k * 64 + (n - 128)];
        dh = g_W2T_hi + j; dl = g_W2T_lo + j;
    }
    __nv_bfloat16 h = __float2bfloat16(v);
    *dh = h;
    *dl = __float2bfloat16(v - __bfloat162float(h));
}

// ---------------------------------------------------------------------------
// CSR construction: degree histogram -> scan -> cursor fill
__global__ void __launch_bounds__(256)
deg_kernel(const int* __restrict__ ei, int* __restrict__ deg) {
    int e = blockIdx.x * blockDim.x + threadIdx.x;
    if (e < N_EDGES) atomicAdd(&deg[ei[N_EDGES + e]], 1);
}

__global__ void __launch_bounds__(1024)
scan_kernel(const int* __restrict__ deg, int* __restrict__ offs) {
    __shared__ int ssum[1024];
    const int t = threadIdx.x;
    const int CH = (N_NODES + 1023) / 1024;          // 98
    int b = t * CH;
    int s = 0;
    for (int i = 0; i < CH; i++) {
        int idx = b + i;
        if (idx < N_NODES) s += deg[idx];
    }
    ssum[t] = s;
    __syncthreads();
    for (int d = 1; d < 1024; d <<= 1) {
        int v = (t >= d) ? ssum[t - d] : 0;
        __syncthreads();
        ssum[t] += v;
        __syncthreads();
    }
    int excl = (t == 0) ? 0 : ssum[t - 1];
    for (int i = 0; i < CH; i++) {
        int idx = b + i;
        if (idx < N_NODES) { offs[idx] = excl; excl += deg[idx]; }
    }
}

__global__ void __launch_bounds__(256)
fill_csr_kernel(const int* __restrict__ ei, const int* __restrict__ et,
                const int* __restrict__ offs, int* __restrict__ cursor,
                int* __restrict__ csr) {
    int e = blockIdx.x * blockDim.x + threadIdx.x;
    if (e >= N_EDGES) return;
    int s = ei[e];
    int d = ei[N_EDGES + e];
    int r = et[e];
    int pos = offs[d] + atomicAdd(&cursor[d], 1);
    csr[pos] = s | (r << 30);
}

// ---------------------------------------------------------------------------
// Layer-1 aggregation: warp per dst node, register accumulation, mean folded.
__global__ void __launch_bounds__(256)
agg1_kernel(const float* __restrict__ x,
            const int* __restrict__ offs, const int* __restrict__ deg,
            const int* __restrict__ csr, float* __restrict__ AGG) {
    int w = (blockIdx.x * blockDim.x + threadIdx.x) >> 5;
    int lane = threadIdx.x & 31;
    if (w >= N_NODES) return;
    int off = offs[w], dg = deg[w];
    float4 a0 = make_float4(0.f, 0.f, 0.f, 0.f);
    float4 a1 = make_float4(0.f, 0.f, 0.f, 0.f);
    int c0 = 0, c1 = 0;
    for (int base = 0; base < dg; base += 32) {
        int v = (base + lane < dg) ? csr[off + base + lane] : 0;
        int mrem = min(32, dg - base);
        for (int j = 0; j < mrem; j++) {
            int ev = __shfl_sync(0xFFFFFFFFu, v, j);
            int s = ev & 0x3FFFFFFF;
            int r = ev >> 30;
            float4 xv = *(const float4*)(x + (size_t)s * 128 + lane * 4);
            if (r == 0) {
                a0.x += xv.x; a0.y += xv.y; a0.z += xv.z; a0.w += xv.w; c0++;
            } else {
                a1.x += xv.x; a1.y += xv.y; a1.z += xv.z; a1.w += xv.w; c1++;
            }
        }
    }
    float s0 = 1.0f / (float)max(c0, 1);
    float s1 = 1.0f / (float)max(c1, 1);
    a0.x *= s0; a0.y *= s0; a0.z *= s0; a0.w *= s0;
    a1.x *= s1; a1.y *= s1; a1.z *= s1; a1.w *= s1;
    *(float4*)(AGG + (size_t)w * 256 + lane * 4) = a0;
    *(float4*)(AGG + (size_t)w * 256 + 128 + lane * 4) = a1;
}

// Layer-2 aggregation + final epilogue: warp per node.
__global__ void __launch_bounds__(256)
agg2_kernel(const float* __restrict__ P,
            const int* __restrict__ offs, const int* __restrict__ deg,
            const int* __restrict__ csr,
            const float* __restrict__ b2, float* __restrict__ out) {
    int w = (blockIdx.x * blockDim.x + threadIdx.x) >> 5;
    int lane = threadIdx.x & 31;
    if (w >= N_NODES) return;
    int off = offs[w], dg = deg[w];
    float2 a0 = make_float2(0.f, 0.f), a1 = make_float2(0.f, 0.f);
    int c0 = 0, c1 = 0;
    for (int base = 0; base < dg; base += 32) {
        int v = (base + lane < dg) ? csr[off + base + lane] : 0;
        int mrem = min(32, dg - base);
        for (int j = 0; j < mrem; j++) {
            int ev = __shfl_sync(0xFFFFFFFFu, v, j);
            int s = ev & 0x3FFFFFFF;
            int r = ev >> 30;
            float2 pv = *(const float2*)(P + (size_t)s * 192 + 64 + r * 64 + lane * 2);
            if (r == 0) { a0.x += pv.x; a0.y += pv.y; c0++; }
            else        { a1.x += pv.x; a1.y += pv.y; c1++; }
        }
    }
    float s0 = 1.0f / (float)max(c0, 1);
    float s1 = 1.0f / (float)max(c1, 1);
    float2 p0 = *(const float2*)(P + (size_t)w * 192 + lane * 2);
    float2 bb = *(const float2*)(b2 + lane * 2);
    float2 v;
    v.x = p0.x + a0.x * s0 + a1.x * s1 + bb.x;
    v.y = p0.y + a0.y * s0 + a1.y * s1 + bb.y;
    float ss = v.x * v.x + v.y * v.y;
#pragma unroll
    for (int o = 16; o; o >>= 1) ss += __shfl_xor_sync(0xFFFFFFFFu, ss, o);
    float sc = 1.0f / fmaxf(sqrtf(ss), 1e-12f);
    v.x *= sc; v.y *= sc;
    *(float2*)(out + (size_t)w * 64 + lane * 2) = v;
}

// ---------------------------------------------------------------------------
__device__ __forceinline__ void mma_bf16(float* c, const unsigned* a, unsigned b0, unsigned b1) {
    asm volatile(
        "mma.sync.aligned.m16n8k16.row.col.f32.bf16.bf16.f32 "
        "{%0,%1,%2,%3}, {%4,%5,%6,%7}, {%8,%9}, {%0,%1,%2,%3};"
        : "+f"(c[0]), "+f"(c[1]), "+f"(c[2]), "+f"(c[3])
        : "r"(a[0]), "r"(a[1]), "r"(a[2]), "r"(a[3]), "r"(b0), "r"(b1));
}

__device__ __forceinline__ void ldsm4(uint32_t addr, unsigned& r0, unsigned& r1,
                                      unsigned& r2, unsigned& r3) {
    asm volatile("ldmatrix.sync.aligned.m8n8.x4.shared.b16 {%0,%1,%2,%3}, [%4];"
                 : "=r"(r0), "=r"(r1), "=r"(r2), "=r"(r3) : "r"(addr));
}

__device__ __forceinline__ void cp16(void* dst_smem, const void* src) {
    uint32_t d = (uint32_t)__cvta_generic_to_shared(dst_smem);
    asm volatile("cp.async.ca.shared.global [%0], [%1], 16;" :: "r"(d), "l"(src));
}

__device__ __forceinline__ unsigned pack2(__nv_bfloat16 a, __nv_bfloat16 b) {
    union { __nv_bfloat162 v; unsigned u; } c;
    c.v = __halves2bfloat162(a, b);
    return c.u;
}

__device__ __forceinline__ void split4(const float4 v,
                                       unsigned& hi0, unsigned& hi1,
                                       unsigned& lo0, unsigned& lo1) {
    __nv_bfloat16 h0 = __float2bfloat16(v.x), h1 = __float2bfloat16(v.y);
    __nv_bfloat16 h2 = __float2bfloat16(v.z), h3 = __float2bfloat16(v.w);
    __nv_bfloat16 l0 = __float2bfloat16(v.x - __bfloat162float(h0));
    __nv_bfloat16 l1 = __float2bfloat16(v.y - __bfloat162float(h1));
    __nv_bfloat16 l2 = __float2bfloat16(v.z - __bfloat162float(h2));
    __nv_bfloat16 l3 = __float2bfloat16(v.w - __bfloat162float(h3));
    hi0 = pack2(h0, h1); hi1 = pack2(h2, h3);
    lo0 = pack2(l0, l1); lo1 = pack2(l2, l3);
}

// ---------------------------------------------------------------------------
// Double-buffered tensor-core GEMM, bf16 3-term split.
template<int BN, int KDIM, int WM, int WN, int MT, int NT, bool AFP32, bool RELU, bool HOUT>
__global__ void __launch_bounds__(256, 2)
gemm_db_kernel(const float* __restrict__ Xp,
               const float* __restrict__ AGGp,
               const __nv_bfloat16* __restrict__ Ah,
               const __nv_bfloat16* __restrict__ Al, int lda,
               const __nv_bfloat16* __restrict__ WT_hi,
               const __nv_bfloat16* __restrict__ WT_lo,
               const float* __restrict__ bias,
               float* __restrict__ C, int M, int ldc,
               __nv_bfloat16* __restrict__ Hh,
               __nv_bfloat16* __restrict__ Hl) {
    constexpr int BM = 128, BK = 32, BKP = 40;
    constexpr int ASZ = BM * BKP;
    constexpr int BSZ = BN * BKP;
    constexpr int T = KDIM / BK;

    extern __shared__ __align__(16) char smem_raw[];
    __nv_bfloat16* As_hi[2]; __nv_bfloat16* As_lo[2];
    __nv_bfloat16* Bs_hi[2]; __nv_bfloat16* Bs_lo[2];
    {
        __nv_bfloat16* p = (__nv_bfloat16*)smem_raw;
        As_hi[0] = p;            As_lo[0] = p + ASZ;
        As_hi[1] = p + 2 * ASZ;  As_lo[1] = p + 3 * ASZ;
        p += 4 * ASZ;
        Bs_hi[0] = p;            Bs_lo[0] = p + BSZ;
        Bs_hi[1] = p + 2 * BSZ;  Bs_lo[1] = p + 3 * BSZ;
    }

    const int tid = threadIdx.x;
    const int lane = tid & 31;
    const int warp = tid >> 5;
    const int warpM = warp / WN;
    const int warpN = warp % WN;
    const int m0 = blockIdx.x * BM;
    const int g = lane >> 2;
    const int kq = (lane & 3) * 2;

    const __nv_bfloat16* Wh = WT_hi + (size_t)blockIdx.y * BN * KDIM;
    const __nv_bfloat16* Wl = WT_lo + (size_t)blockIdx.y * BN * KDIM;

    float acc[MT][NT][4];
#pragma unroll
    for (int i = 0; i < MT; i++)
#pragma unroll
        for (int j = 0; j < NT; j++)
#pragma unroll
            for (int q = 0; q < 4; q++) acc[i][j][q] = 0.f;

    const int rowT = tid >> 1, hfT = tid & 1;
    const int mClamp = (m0 + rowT < M) ? (m0 + rowT) : (M - 1);

    auto loadB = [&](int k0, int stg) {
#pragma unroll
        for (int i = tid; i < BN * 4; i += 256) {
            int n = i >> 2, q = i & 3;
            cp16(Bs_hi[stg] + n * BKP + q * 8, Wh + (size_t)n * KDIM + k0 + q * 8);
            cp16(Bs_lo[stg] + n * BKP + q * 8, Wl + (size_t)n * KDIM + k0 + q * 8);
        }
    };
    auto loadA_cp = [&](int k0, int stg) {
#pragma unroll
        for (int i = tid; i < BM * 4; i += 256) {
            int row = i >> 2, q = i & 3;
            int m = (m0 + row < M) ? (m0 + row) : (M - 1);
            cp16(As_hi[stg] + row * BKP + q * 8, Ah + (size_t)m * lda + k0 + q * 8);
            cp16(As_lo[stg] + row * BKP + q * 8, Al + (size_t)m * lda + k0 + q * 8);
        }
    };
    float4 pref[4];
    auto ldgA = [&](int k0) {
        const float* base = (k0 < 128) ? (Xp + (size_t)mClamp * 128 + k0)
                                       : (AGGp + (size_t)mClamp * 256 + (k0 - 128));
        const float4* src = (const float4*)(base + hfT * 16);
#pragma unroll
        for (int j = 0; j < 4; j++) pref[j] = src[j];
    };
    auto convA = [&](int stg) {
        unsigned hibuf[8], lobuf[8];
#pragma unroll
        for (int j = 0; j < 4; j++)
            split4(pref[j], hibuf[j * 2], hibuf[j * 2 + 1], lobuf[j * 2], lobuf[j * 2 + 1]);
        __nv_bfloat16* dh = As_hi[stg] + rowT * BKP + hfT * 16;
        __nv_bfloat16* dl = As_lo[stg] + rowT * BKP + hfT * 16;
        ((uint4*)dh)[0] = *(uint4*)(hibuf);
        ((uint4*)dh)[1] = *(uint4*)(hibuf + 4);
        ((uint4*)dl)[0] = *(uint4*)(lobuf);
        ((uint4*)dl)[1] = *(uint4*)(lobuf + 4);
    };

    const int rowA = (lane & 7) + (lane & 8);
    const int colA = (lane & 16) ? 8 : 0;
    const int gB = lane >> 3;
    const int rowB = (lane & 7) + ((gB & 1) ? 8 : 0);
    const int colB = (gB >> 1) * 8;

    uint32_t sAhi[2], sAlo[2], sBhi[2], sBlo[2];
#pragma unroll
    for (int s = 0; s < 2; s++) {
        sAhi[s] = (uint32_t)__cvta_generic_to_shared(As_hi[s]);
        sAlo[s] = (uint32_t)__cvta_generic_to_shared(As_lo[s]);
        sBhi[s] = (uint32_t)__cvta_generic_to_shared(Bs_hi[s]);
        sBlo[s] = (uint32_t)__cvta_generic_to_shared(Bs_lo[s]);
    }

    auto compute = [&](int stg) {
#pragma unroll
        for (int ks = 0; ks < BK; ks += 16) {
            unsigned ah[MT][4], al[MT][4];
#pragma unroll
            for (int mt = 0; mt < MT; mt++) {
                uint32_t off = (uint32_t)(2 * ((warpM * MT * 16 + mt * 16 + rowA) * BKP + ks + colA));
                ldsm4(sAhi[stg] + off, ah[mt][0], ah[mt][1], ah[mt][2], ah[mt][3]);
                ldsm4(sAlo[stg] + off, al[mt][0], al[mt][1], al[mt][2], al[mt][3]);
            }
            unsigned bh0[NT], bh1[NT], bl0[NT], bl1[NT];
#pragma unroll
            for (int np = 0; np < NT / 2; np++) {
                uint32_t off = (uint32_t)(2 * ((warpN * NT * 8 + np * 16 + rowB) * BKP + ks + colB));
                ldsm4(sBhi[stg] + off, bh0[np * 2], bh0[np * 2 + 1], bh1[np * 2], bh1[np * 2 + 1]);
                ldsm4(sBlo[stg] + off, bl0[np * 2], bl0[np * 2 + 1], bl1[np * 2], bl1[np * 2 + 1]);
            }
#pragma unroll
            for (int mt = 0; mt < MT; mt++)
#pragma unroll
                for (int nt = 0; nt < NT; nt++) {
                    mma_bf16(acc[mt][nt], ah[mt], bh0[nt], bh1[nt]);
                    mma_bf16(acc[mt][nt], ah[mt], bl0[nt], bl1[nt]);
                    mma_bf16(acc[mt][nt], al[mt], bh0[nt], bh1[nt]);
                }
        }
    };

    loadB(0, 0);
    if (AFP32) { ldgA(0); convA(0); }
    else loadA_cp(0, 0);
    asm volatile("cp.async.commit_group;\ncp.async.wait_group 0;" ::: "memory");
    __syncthreads();

    for (int t = 0; t < T; t++) {
        int cur = t & 1, nxt = cur ^ 1;
        bool hasNext = (t + 1 < T);
        int k1 = (t + 1) * BK;
        if (hasNext) {
            loadB(k1, nxt);
            if (AFP32) ldgA(k1);
            else loadA_cp(k1, nxt);
        }
        compute(cur);
        if (AFP32 && hasNext) convA(nxt);
        asm volatile("cp.async.commit_group;\ncp.async.wait_group 0;" ::: "memory");
        __syncthreads();
    }

#pragma unroll
    for (int nt = 0; nt < NT; nt++) {
        int n = warpN * NT * 8 + nt * 8 + kq;
        float b0 = bias ? bias[n] : 0.f;
        float b1 = bias ? bias[n + 1] : 0.f;
#pragma unroll
        for (int mt = 0; mt < MT; mt++) {
            float* c = acc[mt][nt];
            c[0] += b0; c[1] += b1; c[2] += b0; c[3] += b1;
            if (RELU) {
                c[0] = fmaxf(c[0], 0.f); c[1] = fmaxf(c[1], 0.f);
                c[2] = fmaxf(c[2], 0.f); c[3] = fmaxf(c[3], 0.f);
            }
        }
    }

    if (HOUT) {
#pragma unroll
        for (int mt = 0; mt < MT; mt++) {
            int r0 = m0 + warpM * MT * 16 + mt * 16 + g;
#pragma unroll
            for (int nt = 0; nt < NT; nt++) {
                int n = warpN * NT * 8 + nt * 8 + kq;
                float* c = acc[mt][nt];
                if (r0 < M) {
                    __nv_bfloat16 h0 = __float2bfloat16(c[0]);
                    __nv_bfloat16 h1 = __float2bfloat16(c[1]);
                    *(unsigned*)(Hh + (size_t)r0 * 128 + n) = pack2(h0, h1);
                    *(unsigned*)(Hl + (size_t)r0 * 128 + n) =
                        pack2(__float2bfloat16(c[0] - __bfloat162float(h0)),
                              __float2bfloat16(c[1] - __bfloat162float(h1)));
                }
                if (r0 + 8 < M) {
                    __nv_bfloat16 h2 = __float2bfloat16(c[2]);
                    __nv_bfloat16 h3 = __float2bfloat16(c[3]);
                    *(unsigned*)(Hh + (size_t)(r0 + 8) * 128 + n) = pack2(h2, h3);
                    *(unsigned*)(Hl + (size_t)(r0 + 8) * 128 + n) =
                        pack2(__float2bfloat16(c[2] - __bfloat162float(h2)),
                              __float2bfloat16(c[3] - __bfloat162float(h3)));
                }
            }
        }
    } else {
        float* Cb = C + (size_t)blockIdx.y * BN;
#pragma unroll
        for (int mt = 0; mt < MT; mt++) {
            int r0 = m0 + warpM * MT * 16 + mt * 16 + g;
#pragma unroll
            for (int nt = 0; nt < NT; nt++) {
                int n = warpN * NT * 8 + nt * 8 + kq;
                float* c = acc[mt][nt];
                if (r0 < M)
                    *(float2*)(Cb + (size_t)r0 * ldc + n) = make_float2(c[0], c[1]);
                if (r0 + 8 < M)
                    *(float2*)(Cb + (size_t)(r0 + 8) * ldc + n) = make_float2(c[2], c[3]);
            }
        }
    }
}

// ---------------------------------------------------------------------------
extern "C" void kernel_launch(void* const* d_in, const int* in_sizes, int n_in,
                              void* d_out, int out_size) {
    const float* x       = (const float*)d_in[0];
    const int*   ei      = (const int*)d_in[1];
    const int*   et      = (const int*)d_in[2];
    const float* W1_rel  = (const float*)d_in[3];
    const float* W1_root = (const float*)d_in[4];
    const float* b1      = (const float*)d_in[5];
    const float* W2_rel  = (const float*)d_in[6];
    const float* W2_root = (const float*)d_in[7];
    const float* b2      = (const float*)d_in[8];
    float* out = (float*)d_out;

    float *AGG, *P;
    __nv_bfloat16 *Hh, *Hl, *W1Th, *W1Tl, *W2Th, *W2Tl;
    int *deg, *offs, *cursor, *csr;
    cudaGetSymbolAddress((void**)&AGG,  g_AGG);
    cudaGetSymbolAddress((void**)&P,    g_P);
    cudaGetSymbolAddress((void**)&Hh,   g_H_hi);
    cudaGetSymbolAddress((void**)&Hl,   g_H_lo);
    cudaGetSymbolAddress((void**)&W1Th, g_W1T_hi);
    cudaGetSymbolAddress((void**)&W1Tl, g_W1T_lo);
    cudaGetSymbolAddress((void**)&W2Th, g_W2T_hi);
    cudaGetSymbolAddress((void**)&W2Tl, g_W2T_lo);
    cudaGetSymbolAddress((void**)&deg,    g_deg);
    cudaGetSymbolAddress((void**)&offs,   g_offs);
    cudaGetSymbolAddress((void**)&cursor, g_cursor);
    cudaGetSymbolAddress((void**)&csr,    g_csr);

    const int SM1 = (4 * 128 * 40 + 4 * 128 * 40) * 2;   // 81920
    const int SM2 = (4 * 128 * 40 + 4 * 64 * 40) * 2;    // 61440
    auto* k1 = gemm_db_kernel<128, 384, 2, 4, 4, 4, true,  true,  true>;
    auto* k2 = gemm_db_kernel<64,  128, 4, 2, 2, 4, false, false, false>;
    cudaFuncSetAttribute(k1, cudaFuncAttributeMaxDynamicSharedMemorySize, SM1);
    cudaFuncSetAttribute(k2, cudaFuncAttributeMaxDynamicSharedMemorySize, SM2);

    const int TB = 256;
    const int g_prep = (128 * KTOT + 192 * 128 + TB - 1) / TB;
    const int g_edge = (N_EDGES + TB - 1) / TB;
    const int g_agg  = (N_NODES * 32 + TB - 1) / TB;
    const int g_gemm = (N_NODES + 127) / 128;

    prep_w_kernel<<<g_prep, TB>>>(W1_rel, W1_root, W2_rel, W2_root);

    // ---- CSR build (shared by both layers) ----
    cudaMemsetAsync(deg, 0, N_NODES * 4);
    cudaMemsetAsync(cursor, 0, N_NODES * 4);
    deg_kernel<<<g_edge, TB>>>(ei, deg);
    scan_kernel<<<1, 1024>>>(deg, offs);
    fill_csr_kernel<<<g_edge, TB>>>(ei, et, offs, cursor, csr);

    // ---- Layer 1 ----
    agg1_kernel<<<g_agg, TB>>>(x, offs, deg, csr, AGG);
    k1<<<g_gemm, TB, SM1>>>(x, AGG, nullptr, nullptr, 0, W1Th, W1Tl, b1,
                            nullptr, N_NODES, 0, Hh, Hl);

    // ---- Layer 2 ----
    k2<<<dim3(g_gemm, 3), TB, SM2>>>(nullptr, nullptr, Hh, Hl, 128, W2Th, W2Tl, nullptr,
                                     P, N_NODES, 192, nullptr, nullptr);
    agg2_kernel<<<g_agg, TB>>>(P, offs, deg, csr, b2, out);
}

// round 9
// speedup vs baseline: 2.2366x; 1.0885x over previous
#include <cuda_runtime.h>
#include <cuda_bf16.h>
#include <cstdint>

#define N_NODES 100000
#define N_EDGES 1600000
#define KTOT 384

// ---------------------------------------------------------------------------
// Device-global scratch
__device__ float g_P[(size_t)N_NODES * 192];            // layer-2 transformed
__device__ __nv_bfloat16 g_X_hi[(size_t)N_NODES * 128]; // x pre-split
__device__ __nv_bfloat16 g_X_lo[(size_t)N_NODES * 128];
__device__ __nv_bfloat16 g_AGG_hi[(size_t)N_NODES * 256]; // A0|A1 mean-scaled, pre-split
__device__ __nv_bfloat16 g_AGG_lo[(size_t)N_NODES * 256];
__device__ __nv_bfloat16 g_H_hi[(size_t)N_NODES * 128];
__device__ __nv_bfloat16 g_H_lo[(size_t)N_NODES * 128];
__device__ __nv_bfloat16 g_W1T_hi[128 * KTOT];
__device__ __nv_bfloat16 g_W1T_lo[128 * KTOT];
__device__ __nv_bfloat16 g_W2T_hi[192 * 128];
__device__ __nv_bfloat16 g_W2T_lo[192 * 128];
__device__ int g_deg[N_NODES];
__device__ int g_offs[N_NODES];
__device__ int g_epos[N_EDGES];
__device__ int g_csr[N_EDGES];                          // src | (rel<<30), grouped by dst

// ---------------------------------------------------------------------------
__device__ __forceinline__ unsigned pack2(__nv_bfloat16 a, __nv_bfloat16 b) {
    union { __nv_bfloat162 v; unsigned u; } c;
    c.v = __halves2bfloat162(a, b);
    return c.u;
}

__device__ __forceinline__ void split4(const float4 v,
                                       unsigned& hi0, unsigned& hi1,
                                       unsigned& lo0, unsigned& lo1) {
    __nv_bfloat16 h0 = __float2bfloat16(v.x), h1 = __float2bfloat16(v.y);
    __nv_bfloat16 h2 = __float2bfloat16(v.z), h3 = __float2bfloat16(v.w);
    __nv_bfloat16 l0 = __float2bfloat16(v.x - __bfloat162float(h0));
    __nv_bfloat16 l1 = __float2bfloat16(v.y - __bfloat162float(h1));
    __nv_bfloat16 l2 = __float2bfloat16(v.z - __bfloat162float(h2));
    __nv_bfloat16 l3 = __float2bfloat16(v.w - __bfloat162float(h3));
    hi0 = pack2(h0, h1); hi1 = pack2(h2, h3);
    lo0 = pack2(l0, l1); lo1 = pack2(l2, l3);
}

// ---------------------------------------------------------------------------
__global__ void __launch_bounds__(256)
prep_w_kernel(const float* __restrict__ W1_rel,
              const float* __restrict__ W1_root,
              const float* __restrict__ W2_rel,
              const float* __restrict__ W2_root) {
    int i = blockIdx.x * blockDim.x + threadIdx.x;
    const int SZ1 = 128 * KTOT;
    const int SZ2 = 192 * 128;
    if (i >= SZ1 + SZ2) return;
    float v;
    __nv_bfloat16 *dh, *dl;
    if (i < SZ1) {
        int n = i / KTOT, k = i % KTOT;
        if (k < 128) v = W1_root[k * 128 + n];
        else {
            int r = (k - 128) >> 7, kk = (k - 128) & 127;
            v = W1_rel[(size_t)r * 128 * 128 + kk * 128 + n];
        }
        dh = g_W1T_hi + i; dl = g_W1T_lo + i;
    } else {
        int j = i - SZ1;
        int n = j / 128, k = j % 128;
        if (n < 64)       v = W2_root[k * 64 + n];
        else if (n < 128) v = W2_rel[(size_t)0 * 128 * 64 + k * 64 + (n - 64)];
        else              v = W2_rel[(size_t)1 * 128 * 64 + k * 64 + (n - 128)];
        dh = g_W2T_hi + j; dl = g_W2T_lo + j;
    }
    __nv_bfloat16 h = __float2bfloat16(v);
    *dh = h;
    *dl = __float2bfloat16(v - __bfloat162float(h));
}

// Pre-split x into bf16 hi/lo
__global__ void __launch_bounds__(256)
prep_x_kernel(const float* __restrict__ x,
              __nv_bfloat16* __restrict__ Xh, __nv_bfloat16* __restrict__ Xl) {
    int i = blockIdx.x * blockDim.x + threadIdx.x;      // over N*32 float4
    if (i >= N_NODES * 32) return;
    float4 v = ((const float4*)x)[i];
    unsigned h0, h1, l0, l1;
    split4(v, h0, h1, l0, l1);
    ((uint2*)Xh)[i] = make_uint2(h0, h1);
    ((uint2*)Xl)[i] = make_uint2(l0, l1);
}

// ---------------------------------------------------------------------------
// CSR construction: degree histogram (records per-edge slot) -> scan -> plain fill
__global__ void __launch_bounds__(256)
deg_kernel(const int* __restrict__ ei, int* __restrict__ deg, int* __restrict__ epos) {
    int e = blockIdx.x * blockDim.x + threadIdx.x;
    if (e < N_EDGES) epos[e] = atomicAdd(&deg[ei[N_EDGES + e]], 1);
}

__global__ void __launch_bounds__(1024)
scan_kernel(const int* __restrict__ deg, int* __restrict__ offs) {
    __shared__ int ssum[1024];
    const int t = threadIdx.x;
    const int CH = (N_NODES + 1023) / 1024;
    int b = t * CH;
    int s = 0;
    for (int i = 0; i < CH; i++) {
        int idx = b + i;
        if (idx < N_NODES) s += deg[idx];
    }
    ssum[t] = s;
    __syncthreads();
    for (int d = 1; d < 1024; d <<= 1) {
        int v = (t >= d) ? ssum[t - d] : 0;
        __syncthreads();
        ssum[t] += v;
        __syncthreads();
    }
    int excl = (t == 0) ? 0 : ssum[t - 1];
    for (int i = 0; i < CH; i++) {
        int idx = b + i;
        if (idx < N_NODES) { offs[idx] = excl; excl += deg[idx]; }
    }
}

__global__ void __launch_bounds__(256)
fill_csr_kernel(const int* __restrict__ ei, const int* __restrict__ et,
                const int* __restrict__ offs, const int* __restrict__ epos,
                int* __restrict__ csr) {
    int e = blockIdx.x * blockDim.x + threadIdx.x;
    if (e >= N_EDGES) return;
    int s = ei[e];
    int d = ei[N_EDGES + e];
    int r = et[e];
    csr[offs[d] + epos[e]] = s | (r << 30);
}

// ---------------------------------------------------------------------------
// Layer-1 aggregation: warp per dst node, unroll-4 gathers, mean folded,
// writes AGG as pre-split bf16 hi/lo (bit-identical to later split of fp32).
__global__ void __launch_bounds__(256)
agg1_kernel(const float* __restrict__ x,
            const int* __restrict__ offs, const int* __restrict__ deg,
            const int* __restrict__ csr,
            __nv_bfloat16* __restrict__ AGGh, __nv_bfloat16* __restrict__ AGGl) {
    int w = (blockIdx.x * blockDim.x + threadIdx.x) >> 5;
    int lane = threadIdx.x & 31;
    if (w >= N_NODES) return;
    int off = offs[w], dg = deg[w];
    float4 a0 = make_float4(0.f, 0.f, 0.f, 0.f);
    float4 a1 = make_float4(0.f, 0.f, 0.f, 0.f);
    int c0 = 0;
    int j = 0;
    const int col = lane * 4;
    for (; j + 4 <= dg; j += 4) {
        int e0 = csr[off + j], e1 = csr[off + j + 1];
        int e2 = csr[off + j + 2], e3 = csr[off + j + 3];
        float4 v0 = *(const float4*)(x + (size_t)(e0 & 0x3FFFFFFF) * 128 + col);
        float4 v1 = *(const float4*)(x + (size_t)(e1 & 0x3FFFFFFF) * 128 + col);
        float4 v2 = *(const float4*)(x + (size_t)(e2 & 0x3FFFFFFF) * 128 + col);
        float4 v3 = *(const float4*)(x + (size_t)(e3 & 0x3FFFFFFF) * 128 + col);
        if ((e0 >> 30) == 0) { a0.x += v0.x; a0.y += v0.y; a0.z += v0.z; a0.w += v0.w; c0++; }
        else                 { a1.x += v0.x; a1.y += v0.y; a1.z += v0.z; a1.w += v0.w; }
        if ((e1 >> 30) == 0) { a0.x += v1.x; a0.y += v1.y; a0.z += v1.z; a0.w += v1.w; c0++; }
        else                 { a1.x += v1.x; a1.y += v1.y; a1.z += v1.z; a1.w += v1.w; }
        if ((e2 >> 30) == 0) { a0.x += v2.x; a0.y += v2.y; a0.z += v2.z; a0.w += v2.w; c0++; }
        else                 { a1.x += v2.x; a1.y += v2.y; a1.z += v2.z; a1.w += v2.w; }
        if ((e3 >> 30) == 0) { a0.x += v3.x; a0.y += v3.y; a0.z += v3.z; a0.w += v3.w; c0++; }
        else                 { a1.x += v3.x; a1.y += v3.y; a1.z += v3.z; a1.w += v3.w; }
    }
    for (; j < dg; j++) {
        int e0 = csr[off + j];
        float4 v0 = *(const float4*)(x + (size_t)(e0 & 0x3FFFFFFF) * 128 + col);
        if ((e0 >> 30) == 0) { a0.x += v0.x; a0.y += v0.y; a0.z += v0.z; a0.w += v0.w; c0++; }
        else                 { a1.x += v0.x; a1.y += v0.y; a1.z += v0.z; a1.w += v0.w; }
    }
    int c1 = dg - c0;
    float s0 = 1.0f / (float)max(c0, 1);
    float s1 = 1.0f / (float)max(c1, 1);
    a0.x *= s0; a0.y *= s0; a0.z *= s0; a0.w *= s0;
    a1.x *= s1; a1.y *= s1; a1.z *= s1; a1.w *= s1;
    unsigned h0, h1, l0, l1;
    split4(a0, h0, h1, l0, l1);
    *(uint2*)(AGGh + (size_t)w * 256 + col) = make_uint2(h0, h1);
    *(uint2*)(AGGl + (size_t)w * 256 + col) = make_uint2(l0, l1);
    split4(a1, h0, h1, l0, l1);
    *(uint2*)(AGGh + (size_t)w * 256 + 128 + col) = make_uint2(h0, h1);
    *(uint2*)(AGGl + (size_t)w * 256 + 128 + col) = make_uint2(l0, l1);
}

// Layer-2 aggregation + final epilogue: warp per node, unroll-4.
__global__ void __launch_bounds__(256)
agg2_kernel(const float* __restrict__ P,
            const int* __restrict__ offs, const int* __restrict__ deg,
            const int* __restrict__ csr,
            const float* __restrict__ b2, float* __restrict__ out) {
    int w = (blockIdx.x * blockDim.x + threadIdx.x) >> 5;
    int lane = threadIdx.x & 31;
    if (w >= N_NODES) return;
    int off = offs[w], dg = deg[w];
    float2 a0 = make_float2(0.f, 0.f), a1 = make_float2(0.f, 0.f);
    int c0 = 0;
    int j = 0;
    const int col = lane * 2;
    for (; j + 4 <= dg; j += 4) {
        int e0 = csr[off + j], e1 = csr[off + j + 1];
        int e2 = csr[off + j + 2], e3 = csr[off + j + 3];
        float2 v0 = *(const float2*)(P + (size_t)(e0 & 0x3FFFFFFF) * 192 + 64 + (e0 >> 30) * 64 + col);
        float2 v1 = *(const float2*)(P + (size_t)(e1 & 0x3FFFFFFF) * 192 + 64 + (e1 >> 30) * 64 + col);
        float2 v2 = *(const float2*)(P + (size_t)(e2 & 0x3FFFFFFF) * 192 + 64 + (e2 >> 30) * 64 + col);
        float2 v3 = *(const float2*)(P + (size_t)(e3 & 0x3FFFFFFF) * 192 + 64 + (e3 >> 30) * 64 + col);
        if ((e0 >> 30) == 0) { a0.x += v0.x; a0.y += v0.y; c0++; } else { a1.x += v0.x; a1.y += v0.y; }
        if ((e1 >> 30) == 0) { a0.x += v1.x; a0.y += v1.y; c0++; } else { a1.x += v1.x; a1.y += v1.y; }
        if ((e2 >> 30) == 0) { a0.x += v2.x; a0.y += v2.y; c0++; } else { a1.x += v2.x; a1.y += v2.y; }
        if ((e3 >> 30) == 0) { a0.x += v3.x; a0.y += v3.y; c0++; } else { a1.x += v3.x; a1.y += v3.y; }
    }
    for (; j < dg; j++) {
        int e0 = csr[off + j];
        float2 v0 = *(const float2*)(P + (size_t)(e0 & 0x3FFFFFFF) * 192 + 64 + (e0 >> 30) * 64 + col);
        if ((e0 >> 30) == 0) { a0.x += v0.x; a0.y += v0.y; c0++; } else { a1.x += v0.x; a1.y += v0.y; }
    }
    int c1 = dg - c0;
    float s0 = 1.0f / (float)max(c0, 1);
    float s1 = 1.0f / (float)max(c1, 1);
    float2 p0 = *(const float2*)(P + (size_t)w * 192 + col);
    float2 bb = *(const float2*)(b2 + col);
    float2 v;
    v.x = p0.x + a0.x * s0 + a1.x * s1 + bb.x;
    v.y = p0.y + a0.y * s0 + a1.y * s1 + bb.y;
    float ss = v.x * v.x + v.y * v.y;
#pragma unroll
    for (int o = 16; o; o >>= 1) ss += __shfl_xor_sync(0xFFFFFFFFu, ss, o);
    float sc = 1.0f / fmaxf(sqrtf(ss), 1e-12f);
    v.x *= sc; v.y *= sc;
    *(float2*)(out + (size_t)w * 64 + col) = v;
}

// ---------------------------------------------------------------------------
__device__ __forceinline__ void mma_bf16(float* c, const unsigned* a, unsigned b0, unsigned b1) {
    asm volatile(
        "mma.sync.aligned.m16n8k16.row.col.f32.bf16.bf16.f32 "
        "{%0,%1,%2,%3}, {%4,%5,%6,%7}, {%8,%9}, {%0,%1,%2,%3};"
        : "+f"(c[0]), "+f"(c[1]), "+f"(c[2]), "+f"(c[3])
        : "r"(a[0]), "r"(a[1]), "r"(a[2]), "r"(a[3]), "r"(b0), "r"(b1));
}

__device__ __forceinline__ void ldsm4(uint32_t addr, unsigned& r0, unsigned& r1,
                                      unsigned& r2, unsigned& r3) {
    asm volatile("ldmatrix.sync.aligned.m8n8.x4.shared.b16 {%0,%1,%2,%3}, [%4];"
                 : "=r"(r0), "=r"(r1), "=r"(r2), "=r"(r3) : "r"(addr));
}

__device__ __forceinline__ void cp16(void* dst_smem, const void* src) {
    uint32_t d = (uint32_t)__cvta_generic_to_shared(dst_smem);
    asm volatile("cp.async.ca.shared.global [%0], [%1], 16;" :: "r"(d), "l"(src));
}

// ---------------------------------------------------------------------------
// Double-buffered tensor-core GEMM, bf16 3-term split, pure cp.async A path.
// DUAL: A cols k<128 from Ah/Al (stride lda), k>=128 from Gh/Gl (stride 256).
// HOUT: write pre-split bf16 H (+relu). Else fp32 C (grid.y slices BN).
template<int BN, int KDIM, int WM, int WN, int MT, int NT, bool DUAL, bool RELU, bool HOUT>
__global__ void __launch_bounds__(256, 2)
gemm_db_kernel(const __nv_bfloat16* __restrict__ Ah,
               const __nv_bfloat16* __restrict__ Al, int lda,
               const __nv_bfloat16* __restrict__ Gh,
               const __nv_bfloat16* __restrict__ Gl,
               const __nv_bfloat16* __restrict__ WT_hi,
               const __nv_bfloat16* __restrict__ WT_lo,
               const float* __restrict__ bias,
               float* __restrict__ C, int M, int ldc,
               __nv_bfloat16* __restrict__ Hh,
               __nv_bfloat16* __restrict__ Hl) {
    constexpr int BM = 128, BK = 32, BKP = 40;
    constexpr int ASZ = BM * BKP;
    constexpr int BSZ = BN * BKP;
    constexpr int T = KDIM / BK;

    extern __shared__ __align__(16) char smem_raw[];
    __nv_bfloat16* As_hi[2]; __nv_bfloat16* As_lo[2];
    __nv_bfloat16* Bs_hi[2]; __nv_bfloat16* Bs_lo[2];
    {
        __nv_bfloat16* p = (__nv_bfloat16*)smem_raw;
        As_hi[0] = p;            As_lo[0] = p + ASZ;
        As_hi[1] = p + 2 * ASZ;  As_lo[1] = p + 3 * ASZ;
        p += 4 * ASZ;
        Bs_hi[0] = p;            Bs_lo[0] = p + BSZ;
        Bs_hi[1] = p + 2 * BSZ;  Bs_lo[1] = p + 3 * BSZ;
    }

    const int tid = threadIdx.x;
    const int lane = tid & 31;
    const int warp = tid >> 5;
    const int warpM = warp / WN;
    const int warpN = warp % WN;
    const int m0 = blockIdx.x * BM;
    const int g = lane >> 2;
    const int kq = (lane & 3) * 2;

    const __nv_bfloat16* Wh = WT_hi + (size_t)blockIdx.y * BN * KDIM;
    const __nv_bfloat16* Wl = WT_lo + (size_t)blockIdx.y * BN * KDIM;

    float acc[MT][NT][4];
#pragma unroll
    for (int i = 0; i < MT; i++)
#pragma unroll
        for (int j = 0; j < NT; j++)
#pragma unroll
            for (int q = 0; q < 4; q++) acc[i][j][q] = 0.f;

    auto loadB = [&](int k0, int stg) {
#pragma unroll
        for (int i = tid; i < BN * 4; i += 256) {
            int n = i >> 2, q = i & 3;
            cp16(Bs_hi[stg] + n * BKP + q * 8, Wh + (size_t)n * KDIM + k0 + q * 8);
            cp16(Bs_lo[stg] + n * BKP + q * 8, Wl + (size_t)n * KDIM + k0 + q * 8);
        }
    };
    auto loadA = [&](int k0, int stg) {
#pragma unroll
        for (int i = tid; i < BM * 4; i += 256) {
            int row = i >> 2, q = i & 3;
            int m = (m0 + row < M) ? (m0 + row) : (M - 1);
            const __nv_bfloat16 *sh, *sl;
            if (DUAL && k0 >= 128) {
                sh = Gh + (size_t)m * 256 + (k0 - 128) + q * 8;
                sl = Gl + (size_t)m * 256 + (k0 - 128) + q * 8;
            } else {
                sh = Ah + (size_t)m * lda + k0 + q * 8;
                sl = Al + (size_t)m * lda + k0 + q * 8;
            }
            cp16(As_hi[stg] + row * BKP + q * 8, sh);
            cp16(As_lo[stg] + row * BKP + q * 8, sl);
        }
    };

    const int rowA = (lane & 7) + (lane & 8);
    const int colA = (lane & 16) ? 8 : 0;
    const int gB = lane >> 3;
    const int rowB = (lane & 7) + ((gB & 1) ? 8 : 0);
    const int colB = (gB >> 1) * 8;

    uint32_t sAhi[2], sAlo[2], sBhi[2], sBlo[2];
#pragma unroll
    for (int s = 0; s < 2; s++) {
        sAhi[s] = (uint32_t)__cvta_generic_to_shared(As_hi[s]);
        sAlo[s] = (uint32_t)__cvta_generic_to_shared(As_lo[s]);
        sBhi[s] = (uint32_t)__cvta_generic_to_shared(Bs_hi[s]);
        sBlo[s] = (uint32_t)__cvta_generic_to_shared(Bs_lo[s]);
    }

    auto compute = [&](int stg) {
#pragma unroll
        for (int ks = 0; ks < BK; ks += 16) {
            unsigned ah[MT][4], al[MT][4];
#pragma unroll
            for (int mt = 0; mt < MT; mt++) {
                uint32_t off = (uint32_t)(2 * ((warpM * MT * 16 + mt * 16 + rowA) * BKP + ks + colA));
                ldsm4(sAhi[stg] + off, ah[mt][0], ah[mt][1], ah[mt][2], ah[mt][3]);
                ldsm4(sAlo[stg] + off, al[mt][0], al[mt][1], al[mt][2], al[mt][3]);
            }
            unsigned bh0[NT], bh1[NT], bl0[NT], bl1[NT];
#pragma unroll
            for (int np = 0; np < NT / 2; np++) {
                uint32_t off = (uint32_t)(2 * ((warpN * NT * 8 + np * 16 + rowB) * BKP + ks + colB));
                ldsm4(sBhi[stg] + off, bh0[np * 2], bh0[np * 2 + 1], bh1[np * 2], bh1[np * 2 + 1]);
                ldsm4(sBlo[stg] + off, bl0[np * 2], bl0[np * 2 + 1], bl1[np * 2], bl1[np * 2 + 1]);
            }
#pragma unroll
            for (int mt = 0; mt < MT; mt++)
#pragma unroll
                for (int nt = 0; nt < NT; nt++) {
                    mma_bf16(acc[mt][nt], ah[mt], bh0[nt], bh1[nt]);
                    mma_bf16(acc[mt][nt], ah[mt], bl0[nt], bl1[nt]);
                    mma_bf16(acc[mt][nt], al[mt], bh0[nt], bh1[nt]);
                }
        }
    };

    loadB(0, 0);
    loadA(0, 0);
    asm volatile("cp.async.commit_group;\ncp.async.wait_group 0;" ::: "memory");
    __syncthreads();

    for (int t = 0; t < T; t++) {
        int cur = t & 1, nxt = cur ^ 1;
        bool hasNext = (t + 1 < T);
        int k1 = (t + 1) * BK;
        if (hasNext) {
            loadB(k1, nxt);
            loadA(k1, nxt);
        }
        compute(cur);
        asm volatile("cp.async.commit_group;\ncp.async.wait_group 0;" ::: "memory");
        __syncthreads();
    }

#pragma unroll
    for (int nt = 0; nt < NT; nt++) {
        int n = warpN * NT * 8 + nt * 8 + kq;
        float b0 = bias ? bias[n] : 0.f;
        float b1 = bias ? bias[n + 1] : 0.f;
#pragma unroll
        for (int mt = 0; mt < MT; mt++) {
            float* c = acc[mt][nt];
            c[0] += b0; c[1] += b1; c[2] += b0; c[3] += b1;
            if (RELU) {
                c[0] = fmaxf(c[0], 0.f); c[1] = fmaxf(c[1], 0.f);
                c[2] = fmaxf(c[2], 0.f); c[3] = fmaxf(c[3], 0.f);
            }
        }
    }

    if (HOUT) {
#pragma unroll
        for (int mt = 0; mt < MT; mt++) {
            int r0 = m0 + warpM * MT * 16 + mt * 16 + g;
#pragma unroll
            for (int nt = 0; nt < NT; nt++) {
                int n = warpN * NT * 8 + nt * 8 + kq;
                float* c = acc[mt][nt];
                if (r0 < M) {
                    __nv_bfloat16 h0 = __float2bfloat16(c[0]);
                    __nv_bfloat16 h1 = __float2bfloat16(c[1]);
                    *(unsigned*)(Hh + (size_t)r0 * 128 + n) = pack2(h0, h1);
                    *(unsigned*)(Hl + (size_t)r0 * 128 + n) =
                        pack2(__float2bfloat16(c[0] - __bfloat162float(h0)),
                              __float2bfloat16(c[1] - __bfloat162float(h1)));
                }
                if (r0 + 8 < M) {
                    __nv_bfloat16 h2 = __float2bfloat16(c[2]);
                    __nv_bfloat16 h3 = __float2bfloat16(c[3]);
                    *(unsigned*)(Hh + (size_t)(r0 + 8) * 128 + n) = pack2(h2, h3);
                    *(unsigned*)(Hl + (size_t)(r0 + 8) * 128 + n) =
                        pack2(__float2bfloat16(c[2] - __bfloat162float(h2)),
                              __float2bfloat16(c[3] - __bfloat162float(h3)));
                }
            }
        }
    } else {
        float* Cb = C + (size_t)blockIdx.y * BN;
#pragma unroll
        for (int mt = 0; mt < MT; mt++) {
            int r0 = m0 + warpM * MT * 16 + mt * 16 + g;
#pragma unroll
            for (int nt = 0; nt < NT; nt++) {
                int n = warpN * NT * 8 + nt * 8 + kq;
                float* c = acc[mt][nt];
                if (r0 < M)
                    *(float2*)(Cb + (size_t)r0 * ldc + n) = make_float2(c[0], c[1]);
                if (r0 + 8 < M)
                    *(float2*)(Cb + (size_t)(r0 + 8) * ldc + n) = make_float2(c[2], c[3]);
            }
        }
    }
}

// ---------------------------------------------------------------------------
extern "C" void kernel_launch(void* const* d_in, const int* in_sizes, int n_in,
                              void* d_out, int out_size) {
    const float* x       = (const float*)d_in[0];
    const int*   ei      = (const int*)d_in[1];
    const int*   et      = (const int*)d_in[2];
    const float* W1_rel  = (const float*)d_in[3];
    const float* W1_root = (const float*)d_in[4];
    const float* b1      = (const float*)d_in[5];
    const float* W2_rel  = (const float*)d_in[6];
    const float* W2_root = (const float*)d_in[7];
    const float* b2      = (const float*)d_in[8];
    float* out = (float*)d_out;

    float* P;
    __nv_bfloat16 *Xh, *Xl, *Ah, *Al, *Hh, *Hl, *W1Th, *W1Tl, *W2Th, *W2Tl;
    int *deg, *offs, *epos, *csr;
    cudaGetSymbolAddress((void**)&P,    g_P);
    cudaGetSymbolAddress((void**)&Xh,   g_X_hi);
    cudaGetSymbolAddress((void**)&Xl,   g_X_lo);
    cudaGetSymbolAddress((void**)&Ah,   g_AGG_hi);
    cudaGetSymbolAddress((void**)&Al,   g_AGG_lo);
    cudaGetSymbolAddress((void**)&Hh,   g_H_hi);
    cudaGetSymbolAddress((void**)&Hl,   g_H_lo);
    cudaGetSymbolAddress((void**)&W1Th, g_W1T_hi);
    cudaGetSymbolAddress((void**)&W1Tl, g_W1T_lo);
    cudaGetSymbolAddress((void**)&W2Th, g_W2T_hi);
    cudaGetSymbolAddress((void**)&W2Tl, g_W2T_lo);
    cudaGetSymbolAddress((void**)&deg,  g_deg);
    cudaGetSymbolAddress((void**)&offs, g_offs);
    cudaGetSymbolAddress((void**)&epos, g_epos);
    cudaGetSymbolAddress((void**)&csr,  g_csr);

    const int SM1 = (4 * 128 * 40 + 4 * 128 * 40) * 2;   // 81920
    const int SM2 = (4 * 128 * 40 + 4 * 64 * 40) * 2;    // 61440
    auto* k1 = gemm_db_kernel<128, 384, 2, 4, 4, 4, true,  true,  true>;
    auto* k2 = gemm_db_kernel<64,  128, 4, 2, 2, 4, false, false, false>;
    cudaFuncSetAttribute(k1, cudaFuncAttributeMaxDynamicSharedMemorySize, SM1);
    cudaFuncSetAttribute(k2, cudaFuncAttributeMaxDynamicSharedMemorySize, SM2);

    const int TB = 256;
    const int g_prep  = (128 * KTOT + 192 * 128 + TB - 1) / TB;
    const int g_prepx = (N_NODES * 32 + TB - 1) / TB;
    const int g_edge  = (N_EDGES + TB - 1) / TB;
    const int g_agg   = (N_NODES * 32 + TB - 1) / TB;
    const int g_gemm  = (N_NODES + 127) / 128;

    prep_w_kernel<<<g_prep, TB>>>(W1_rel, W1_root, W2_rel, W2_root);
    prep_x_kernel<<<g_prepx, TB>>>(x, Xh, Xl);

    // ---- CSR build (shared by both layers) ----
    cudaMemsetAsync(deg, 0, N_NODES * 4);
    deg_kernel<<<g_edge, TB>>>(ei, deg, epos);
    scan_kernel<<<1, 1024>>>(deg, offs);
    fill_csr_kernel<<<g_edge, TB>>>(ei, et, offs, epos, csr);

    // ---- Layer 1 ----
    agg1_kernel<<<g_agg, TB>>>(x, offs, deg, csr, Ah, Al);
    k1<<<g_gemm, TB, SM1>>>(Xh, Xl, 128, Ah, Al, W1Th, W1Tl, b1,
                            nullptr, N_NODES, 0, Hh, Hl);

    // ---- Layer 2 ----
    k2<<<dim3(g_gemm, 3), TB, SM2>>>(Hh, Hl, 128, nullptr, nullptr, W2Th, W2Tl, nullptr,
                                     P, N_NODES, 192, nullptr, nullptr);
    agg2_kernel<<<g_agg, TB>>>(P, offs, deg, csr, b2, out);
}

// round 10
// speedup vs baseline: 2.7865x; 1.2459x over previous
#include <cuda_runtime.h>
#include <cuda_bf16.h>
#include <cstdint>

#define N_NODES 100000
#define N_EDGES 1600000
#define KTOT 384
#define SCAN_CHUNKS ((N_NODES + 1023) / 1024)   // 98

// ---------------------------------------------------------------------------
// Device-global scratch
__device__ float g_P[(size_t)N_NODES * 192];            // layer-2 transformed
__device__ __nv_bfloat16 g_X_hi[(size_t)N_NODES * 128]; // x pre-split
__device__ __nv_bfloat16 g_X_lo[(size_t)N_NODES * 128];
__device__ __nv_bfloat16 g_AGG_hi[(size_t)N_NODES * 256]; // A0|A1 mean-scaled, pre-split
__device__ __nv_bfloat16 g_AGG_lo[(size_t)N_NODES * 256];
__device__ __nv_bfloat16 g_H_hi[(size_t)N_NODES * 128];
__device__ __nv_bfloat16 g_H_lo[(size_t)N_NODES * 128];
__device__ __nv_bfloat16 g_W1T_hi[128 * KTOT];
__device__ __nv_bfloat16 g_W1T_lo[128 * KTOT];
__device__ __nv_bfloat16 g_W2T_hi[192 * 128];
__device__ __nv_bfloat16 g_W2T_lo[192 * 128];
__device__ int g_deg[N_NODES];
__device__ int g_offs[N_NODES];
__device__ int g_epos[N_EDGES];
__device__ int g_part[SCAN_CHUNKS];
__device__ int g_csr[N_EDGES];                          // src | (rel<<30), grouped by dst

// ---------------------------------------------------------------------------
__device__ __forceinline__ unsigned pack2(__nv_bfloat16 a, __nv_bfloat16 b) {
    union { __nv_bfloat162 v; unsigned u; } c;
    c.v = __halves2bfloat162(a, b);
    return c.u;
}

__device__ __forceinline__ void split4(const float4 v,
                                       unsigned& hi0, unsigned& hi1,
                                       unsigned& lo0, unsigned& lo1) {
    __nv_bfloat16 h0 = __float2bfloat16(v.x), h1 = __float2bfloat16(v.y);
    __nv_bfloat16 h2 = __float2bfloat16(v.z), h3 = __float2bfloat16(v.w);
    __nv_bfloat16 l0 = __float2bfloat16(v.x - __bfloat162float(h0));
    __nv_bfloat16 l1 = __float2bfloat16(v.y - __bfloat162float(h1));
    __nv_bfloat16 l2 = __float2bfloat16(v.z - __bfloat162float(h2));
    __nv_bfloat16 l3 = __float2bfloat16(v.w - __bfloat162float(h3));
    hi0 = pack2(h0, h1); hi1 = pack2(h2, h3);
    lo0 = pack2(l0, l1); lo1 = pack2(l2, l3);
}

// ---------------------------------------------------------------------------
__global__ void __launch_bounds__(256)
prep_w_kernel(const float* __restrict__ W1_rel,
              const float* __restrict__ W1_root,
              const float* __restrict__ W2_rel,
              const float* __restrict__ W2_root) {
    int i = blockIdx.x * blockDim.x + threadIdx.x;
    const int SZ1 = 128 * KTOT;
    const int SZ2 = 192 * 128;
    if (i >= SZ1 + SZ2) return;
    float v;
    __nv_bfloat16 *dh, *dl;
    if (i < SZ1) {
        int n = i / KTOT, k = i % KTOT;
        if (k < 128) v = W1_root[k * 128 + n];
        else {
            int r = (k - 128) >> 7, kk = (k - 128) & 127;
            v = W1_rel[(size_t)r * 128 * 128 + kk * 128 + n];
        }
        dh = g_W1T_hi + i; dl = g_W1T_lo + i;
    } else {
        int j = i - SZ1;
        int n = j / 128, k = j % 128;
        if (n < 64)       v = W2_root[k * 64 + n];
        else if (n < 128) v = W2_rel[(size_t)0 * 128 * 64 + k * 64 + (n - 64)];
        else              v = W2_rel[(size_t)1 * 128 * 64 + k * 64 + (n - 128)];
        dh = g_W2T_hi + j; dl = g_W2T_lo + j;
    }
    __nv_bfloat16 h = __float2bfloat16(v);
    *dh = h;
    *dl = __float2bfloat16(v - __bfloat162float(h));
}

// Pre-split x into bf16 hi/lo
__global__ void __launch_bounds__(256)
prep_x_kernel(const float* __restrict__ x,
              __nv_bfloat16* __restrict__ Xh, __nv_bfloat16* __restrict__ Xl) {
    int i = blockIdx.x * blockDim.x + threadIdx.x;      // over N*32 float4
    if (i >= N_NODES * 32) return;
    float4 v = ((const float4*)x)[i];
    unsigned h0, h1, l0, l1;
    split4(v, h0, h1, l0, l1);
    ((uint2*)Xh)[i] = make_uint2(h0, h1);
    ((uint2*)Xl)[i] = make_uint2(l0, l1);
}

// ---------------------------------------------------------------------------
// CSR construction: degree histogram (records per-edge slot) -> 3-phase scan -> fill
__global__ void __launch_bounds__(256)
deg_kernel(const int* __restrict__ ei, int* __restrict__ deg, int* __restrict__ epos) {
    int e = blockIdx.x * blockDim.x + threadIdx.x;
    if (e < N_EDGES) epos[e] = atomicAdd(&deg[ei[N_EDGES + e]], 1);
}

// Phase 1: per-chunk sums (98 blocks x 1024)
__global__ void __launch_bounds__(1024)
scan_partial_kernel(const int* __restrict__ deg, int* __restrict__ part) {
    __shared__ int red[32];
    int idx = blockIdx.x * 1024 + threadIdx.x;
    int v = (idx < N_NODES) ? deg[idx] : 0;
#pragma unroll
    for (int o = 16; o; o >>= 1) v += __shfl_xor_sync(0xFFFFFFFFu, v, o);
    if ((threadIdx.x & 31) == 0) red[threadIdx.x >> 5] = v;
    __syncthreads();
    if (threadIdx.x < 32) {
        int s = red[threadIdx.x];
#pragma unroll
        for (int o = 16; o; o >>= 1) s += __shfl_xor_sync(0xFFFFFFFFu, s, o);
        if (threadIdx.x == 0) part[blockIdx.x] = s;
    }
}

// Phase 2: exclusive scan of the 98 partials (one tiny block)
__global__ void __launch_bounds__(128)
scan_part_kernel(int* __restrict__ part) {
    __shared__ int buf[SCAN_CHUNKS];
    int t = threadIdx.x;
    if (t < SCAN_CHUNKS) buf[t] = part[t];
    __syncthreads();
    if (t == 0) {
        int run = 0;
        for (int i = 0; i < SCAN_CHUNKS; i++) {
            int v = buf[i];
            buf[i] = run;
            run += v;
        }
    }
    __syncthreads();
    if (t < SCAN_CHUNKS) part[t] = buf[t];
}

// Phase 3: per-chunk exclusive scan + chunk offset -> offs
__global__ void __launch_bounds__(1024)
scan_final_kernel(const int* __restrict__ deg, const int* __restrict__ part,
                  int* __restrict__ offs) {
    __shared__ int warpsum[32];
    int t = threadIdx.x;
    int idx = blockIdx.x * 1024 + t;
    int v = (idx < N_NODES) ? deg[idx] : 0;
    int lane = t & 31, wid = t >> 5;
    // inclusive warp scan
    int sc = v;
#pragma unroll
    for (int o = 1; o < 32; o <<= 1) {
        int u = __shfl_up_sync(0xFFFFFFFFu, sc, o);
        if (lane >= o) sc += u;
    }
    if (lane == 31) warpsum[wid] = sc;
    __syncthreads();
    if (wid == 0) {
        int s = (lane < 32) ? warpsum[lane] : 0;
#pragma unroll
        for (int o = 1; o < 32; o <<= 1) {
            int u = __shfl_up_sync(0xFFFFFFFFu, s, o);
            if (lane >= o) s += u;
        }
        warpsum[lane] = s;
    }
    __syncthreads();
    int base = part[blockIdx.x] + ((wid > 0) ? warpsum[wid - 1] : 0);
    if (idx < N_NODES) offs[idx] = base + sc - v;       // exclusive
}

__global__ void __launch_bounds__(256)
fill_csr_kernel(const int* __restrict__ ei, const int* __restrict__ et,
                const int* __restrict__ offs, const int* __restrict__ epos,
                int* __restrict__ csr) {
    int e = blockIdx.x * blockDim.x + threadIdx.x;
    if (e >= N_EDGES) return;
    int s = ei[e];
    int d = ei[N_EDGES + e];
    int r = et[e];
    csr[offs[d] + epos[e]] = s | (r << 30);
}

// ---------------------------------------------------------------------------
// Layer-1 aggregation: warp per dst node, unroll-4 gathers, mean folded,
// writes AGG as pre-split bf16 hi/lo.
__global__ void __launch_bounds__(256)
agg1_kernel(const float* __restrict__ x,
            const int* __restrict__ offs, const int* __restrict__ deg,
            const int* __restrict__ csr,
            __nv_bfloat16* __restrict__ AGGh, __nv_bfloat16* __restrict__ AGGl) {
    int w = (blockIdx.x * blockDim.x + threadIdx.x) >> 5;
    int lane = threadIdx.x & 31;
    if (w >= N_NODES) return;
    int off = offs[w], dg = deg[w];
    float4 a0 = make_float4(0.f, 0.f, 0.f, 0.f);
    float4 a1 = make_float4(0.f, 0.f, 0.f, 0.f);
    int c0 = 0;
    int j = 0;
    const int col = lane * 4;
    for (; j + 4 <= dg; j += 4) {
        int e0 = csr[off + j], e1 = csr[off + j + 1];
        int e2 = csr[off + j + 2], e3 = csr[off + j + 3];
        float4 v0 = *(const float4*)(x + (size_t)(e0 & 0x3FFFFFFF) * 128 + col);
        float4 v1 = *(const float4*)(x + (size_t)(e1 & 0x3FFFFFFF) * 128 + col);
        float4 v2 = *(const float4*)(x + (size_t)(e2 & 0x3FFFFFFF) * 128 + col);
        float4 v3 = *(const float4*)(x + (size_t)(e3 & 0x3FFFFFFF) * 128 + col);
        if ((e0 >> 30) == 0) { a0.x += v0.x; a0.y += v0.y; a0.z += v0.z; a0.w += v0.w; c0++; }
        else                 { a1.x += v0.x; a1.y += v0.y; a1.z += v0.z; a1.w += v0.w; }
        if ((e1 >> 30) == 0) { a0.x += v1.x; a0.y += v1.y; a0.z += v1.z; a0.w += v1.w; c0++; }
        else                 { a1.x += v1.x; a1.y += v1.y; a1.z += v1.z; a1.w += v1.w; }
        if ((e2 >> 30) == 0) { a0.x += v2.x; a0.y += v2.y; a0.z += v2.z; a0.w += v2.w; c0++; }
        else                 { a1.x += v2.x; a1.y += v2.y; a1.z += v2.z; a1.w += v2.w; }
        if ((e3 >> 30) == 0) { a0.x += v3.x; a0.y += v3.y; a0.z += v3.z; a0.w += v3.w; c0++; }
        else                 { a1.x += v3.x; a1.y += v3.y; a1.z += v3.z; a1.w += v3.w; }
    }
    for (; j < dg; j++) {
        int e0 = csr[off + j];
        float4 v0 = *(const float4*)(x + (size_t)(e0 & 0x3FFFFFFF) * 128 + col);
        if ((e0 >> 30) == 0) { a0.x += v0.x; a0.y += v0.y; a0.z += v0.z; a0.w += v0.w; c0++; }
        else                 { a1.x += v0.x; a1.y += v0.y; a1.z += v0.z; a1.w += v0.w; }
    }
    int c1 = dg - c0;
    float s0 = 1.0f / (float)max(c0, 1);
    float s1 = 1.0f / (float)max(c1, 1);
    a0.x *= s0; a0.y *= s0; a0.z *= s0; a0.w *= s0;
    a1.x *= s1; a1.y *= s1; a1.z *= s1; a1.w *= s1;
    unsigned h0, h1, l0, l1;
    split4(a0, h0, h1, l0, l1);
    *(uint2*)(AGGh + (size_t)w * 256 + col) = make_uint2(h0, h1);
    *(uint2*)(AGGl + (size_t)w * 256 + col) = make_uint2(l0, l1);
    split4(a1, h0, h1, l0, l1);
    *(uint2*)(AGGh + (size_t)w * 256 + 128 + col) = make_uint2(h0, h1);
    *(uint2*)(AGGl + (size_t)w * 256 + 128 + col) = make_uint2(l0, l1);
}

// Layer-2 aggregation + final epilogue: warp per node, unroll-4.
__global__ void __launch_bounds__(256)
agg2_kernel(const float* __restrict__ P,
            const int* __restrict__ offs, const int* __restrict__ deg,
            const int* __restrict__ csr,
            const float* __restrict__ b2, float* __restrict__ out) {
    int w = (blockIdx.x * blockDim.x + threadIdx.x) >> 5;
    int lane = threadIdx.x & 31;
    if (w >= N_NODES) return;
    int off = offs[w], dg = deg[w];
    float2 a0 = make_float2(0.f, 0.f), a1 = make_float2(0.f, 0.f);
    int c0 = 0;
    int j = 0;
    const int col = lane * 2;
    for (; j + 4 <= dg; j += 4) {
        int e0 = csr[off + j], e1 = csr[off + j + 1];
        int e2 = csr[off + j + 2], e3 = csr[off + j + 3];
        float2 v0 = *(const float2*)(P + (size_t)(e0 & 0x3FFFFFFF) * 192 + 64 + (e0 >> 30) * 64 + col);
        float2 v1 = *(const float2*)(P + (size_t)(e1 & 0x3FFFFFFF) * 192 + 64 + (e1 >> 30) * 64 + col);
        float2 v2 = *(const float2*)(P + (size_t)(e2 & 0x3FFFFFFF) * 192 + 64 + (e2 >> 30) * 64 + col);
        float2 v3 = *(const float2*)(P + (size_t)(e3 & 0x3FFFFFFF) * 192 + 64 + (e3 >> 30) * 64 + col);
        if ((e0 >> 30) == 0) { a0.x += v0.x; a0.y += v0.y; c0++; } else { a1.x += v0.x; a1.y += v0.y; }
        if ((e1 >> 30) == 0) { a0.x += v1.x; a0.y += v1.y; c0++; } else { a1.x += v1.x; a1.y += v1.y; }
        if ((e2 >> 30) == 0) { a0.x += v2.x; a0.y += v2.y; c0++; } else { a1.x += v2.x; a1.y += v2.y; }
        if ((e3 >> 30) == 0) { a0.x += v3.x; a0.y += v3.y; c0++; } else { a1.x += v3.x; a1.y += v3.y; }
    }
    for (; j < dg; j++) {
        int e0 = csr[off + j];
        float2 v0 = *(const float2*)(P + (size_t)(e0 & 0x3FFFFFFF) * 192 + 64 + (e0 >> 30) * 64 + col);
        if ((e0 >> 30) == 0) { a0.x += v0.x; a0.y += v0.y; c0++; } else { a1.x += v0.x; a1.y += v0.y; }
    }
    int c1 = dg - c0;
    float s0 = 1.0f / (float)max(c0, 1);
    float s1 = 1.0f / (float)max(c1, 1);
    float2 p0 = *(const float2*)(P + (size_t)w * 192 + col);
    float2 bb = *(const float2*)(b2 + col);
    float2 v;
    v.x = p0.x + a0.x * s0 + a1.x * s1 + bb.x;
    v.y = p0.y + a0.y * s0 + a1.y * s1 + bb.y;
    float ss = v.x * v.x + v.y * v.y;
#pragma unroll
    for (int o = 16; o; o >>= 1) ss += __shfl_xor_sync(0xFFFFFFFFu, ss, o);
    float sc = 1.0f / fmaxf(sqrtf(ss), 1e-12f);
    v.x *= sc; v.y *= sc;
    *(float2*)(out + (size_t)w * 64 + col) = v;
}

// ---------------------------------------------------------------------------
__device__ __forceinline__ void mma_bf16(float* c, const unsigned* a, unsigned b0, unsigned b1) {
    asm volatile(
        "mma.sync.aligned.m16n8k16.row.col.f32.bf16.bf16.f32 "
        "{%0,%1,%2,%3}, {%4,%5,%6,%7}, {%8,%9}, {%0,%1,%2,%3};"
        : "+f"(c[0]), "+f"(c[1]), "+f"(c[2]), "+f"(c[3])
        : "r"(a[0]), "r"(a[1]), "r"(a[2]), "r"(a[3]), "r"(b0), "r"(b1));
}

__device__ __forceinline__ void ldsm4(uint32_t addr, unsigned& r0, unsigned& r1,
                                      unsigned& r2, unsigned& r3) {
    asm volatile("ldmatrix.sync.aligned.m8n8.x4.shared.b16 {%0,%1,%2,%3}, [%4];"
                 : "=r"(r0), "=r"(r1), "=r"(r2), "=r"(r3) : "r"(addr));
}

__device__ __forceinline__ void cp16(void* dst_smem, const void* src) {
    uint32_t d = (uint32_t)__cvta_generic_to_shared(dst_smem);
    asm volatile("cp.async.ca.shared.global [%0], [%1], 16;" :: "r"(d), "l"(src));
}

// ---------------------------------------------------------------------------
// Double-buffered tensor-core GEMM, bf16 3-term split, pure cp.async A path.
template<int BN, int KDIM, int WM, int WN, int MT, int NT, bool DUAL, bool RELU, bool HOUT>
__global__ void __launch_bounds__(256, 2)
gemm_db_kernel(const __nv_bfloat16* __restrict__ Ah,
               const __nv_bfloat16* __restrict__ Al, int lda,
               const __nv_bfloat16* __restrict__ Gh,
               const __nv_bfloat16* __restrict__ Gl,
               const __nv_bfloat16* __restrict__ WT_hi,
               const __nv_bfloat16* __restrict__ WT_lo,
               const float* __restrict__ bias,
               float* __restrict__ C, int M, int ldc,
               __nv_bfloat16* __restrict__ Hh,
               __nv_bfloat16* __restrict__ Hl) {
    constexpr int BM = 128, BK = 32, BKP = 40;
    constexpr int ASZ = BM * BKP;
    constexpr int BSZ = BN * BKP;
    constexpr int T = KDIM / BK;

    extern __shared__ __align__(16) char smem_raw[];
    __nv_bfloat16* As_hi[2]; __nv_bfloat16* As_lo[2];
    __nv_bfloat16* Bs_hi[2]; __nv_bfloat16* Bs_lo[2];
    {
        __nv_bfloat16* p = (__nv_bfloat16*)smem_raw;
        As_hi[0] = p;            As_lo[0] = p + ASZ;
        As_hi[1] = p + 2 * ASZ;  As_lo[1] = p + 3 * ASZ;
        p += 4 * ASZ;
        Bs_hi[0] = p;            Bs_lo[0] = p + BSZ;
        Bs_hi[1] = p + 2 * BSZ;  Bs_lo[1] = p + 3 * BSZ;
    }

    const int tid = threadIdx.x;
    const int lane = tid & 31;
    const int warp = tid >> 5;
    const int warpM = warp / WN;
    const int warpN = warp % WN;
    const int m0 = blockIdx.x * BM;
    const int g = lane >> 2;
    const int kq = (lane & 3) * 2;

    const __nv_bfloat16* Wh = WT_hi + (size_t)blockIdx.y * BN * KDIM;
    const __nv_bfloat16* Wl = WT_lo + (size_t)blockIdx.y * BN * KDIM;

    float acc[MT][NT][4];
#pragma unroll
    for (int i = 0; i < MT; i++)
#pragma unroll
        for (int j = 0; j < NT; j++)
#pragma unroll
            for (int q = 0; q < 4; q++) acc[i][j][q] = 0.f;

    auto loadB = [&](int k0, int stg) {
#pragma unroll
        for (int i = tid; i < BN * 4; i += 256) {
            int n = i >> 2, q = i & 3;
            cp16(Bs_hi[stg] + n * BKP + q * 8, Wh + (size_t)n * KDIM + k0 + q * 8);
            cp16(Bs_lo[stg] + n * BKP + q * 8, Wl + (size_t)n * KDIM + k0 + q * 8);
        }
    };
    auto loadA = [&](int k0, int stg) {
#pragma unroll
        for (int i = tid; i < BM * 4; i += 256) {
            int row = i >> 2, q = i & 3;
            int m = (m0 + row < M) ? (m0 + row) : (M - 1);
            const __nv_bfloat16 *sh, *sl;
            if (DUAL && k0 >= 128) {
                sh = Gh + (size_t)m * 256 + (k0 - 128) + q * 8;
                sl = Gl + (size_t)m * 256 + (k0 - 128) + q * 8;
            } else {
                sh = Ah + (size_t)m * lda + k0 + q * 8;
                sl = Al + (size_t)m * lda + k0 + q * 8;
            }
            cp16(As_hi[stg] + row * BKP + q * 8, sh);
            cp16(As_lo[stg] + row * BKP + q * 8, sl);
        }
    };

    const int rowA = (lane & 7) + (lane & 8);
    const int colA = (lane & 16) ? 8 : 0;
    const int gB = lane >> 3;
    const int rowB = (lane & 7) + ((gB & 1) ? 8 : 0);
    const int colB = (gB >> 1) * 8;

    uint32_t sAhi[2], sAlo[2], sBhi[2], sBlo[2];
#pragma unroll
    for (int s = 0; s < 2; s++) {
        sAhi[s] = (uint32_t)__cvta_generic_to_shared(As_hi[s]);
        sAlo[s] = (uint32_t)__cvta_generic_to_shared(As_lo[s]);
        sBhi[s] = (uint32_t)__cvta_generic_to_shared(Bs_hi[s]);
        sBlo[s] = (uint32_t)__cvta_generic_to_shared(Bs_lo[s]);
    }

    auto compute = [&](int stg) {
#pragma unroll
        for (int ks = 0; ks < BK; ks += 16) {
            unsigned ah[MT][4], al[MT][4];
#pragma unroll
            for (int mt = 0; mt < MT; mt++) {
                uint32_t off = (uint32_t)(2 * ((warpM * MT * 16 + mt * 16 + rowA) * BKP + ks + colA));
                ldsm4(sAhi[stg] + off, ah[mt][0], ah[mt][1], ah[mt][2], ah[mt][3]);
                ldsm4(sAlo[stg] + off, al[mt][0], al[mt][1], al[mt][2], al[mt][3]);
            }
            unsigned bh0[NT], bh1[NT], bl0[NT], bl1[NT];
#pragma unroll
            for (int np = 0; np < NT / 2; np++) {
                uint32_t off = (uint32_t)(2 * ((warpN * NT * 8 + np * 16 + rowB) * BKP + ks + colB));
                ldsm4(sBhi[stg] + off, bh0[np * 2], bh0[np * 2 + 1], bh1[np * 2], bh1[np * 2 + 1]);
                ldsm4(sBlo[stg] + off, bl0[np * 2], bl0[np * 2 + 1], bl1[np * 2], bl1[np * 2 + 1]);
            }
#pragma unroll
            for (int mt = 0; mt < MT; mt++)
#pragma unroll
                for (int nt = 0; nt < NT; nt++) {
                    mma_bf16(acc[mt][nt], ah[mt], bh0[nt], bh1[nt]);
                    mma_bf16(acc[mt][nt], ah[mt], bl0[nt], bl1[nt]);
                    mma_bf16(acc[mt][nt], al[mt], bh0[nt], bh1[nt]);
                }
        }
    };

    loadB(0, 0);
    loadA(0, 0);
    asm volatile("cp.async.commit_group;\ncp.async.wait_group 0;" ::: "memory");
    __syncthreads();

    for (int t = 0; t < T; t++) {
        int cur = t & 1, nxt = cur ^ 1;
        bool hasNext = (t + 1 < T);
        int k1 = (t + 1) * BK;
        if (hasNext) {
            loadB(k1, nxt);
            loadA(k1, nxt);
        }
        compute(cur);
        asm volatile("cp.async.commit_group;\ncp.async.wait_group 0;" ::: "memory");
        __syncthreads();
    }

#pragma unroll
    for (int nt = 0; nt < NT; nt++) {
        int n = warpN * NT * 8 + nt * 8 + kq;
        float b0 = bias ? bias[n] : 0.f;
        float b1 = bias ? bias[n + 1] : 0.f;
#pragma unroll
        for (int mt = 0; mt < MT; mt++) {
            float* c = acc[mt][nt];
            c[0] += b0; c[1] += b1; c[2] += b0; c[3] += b1;
            if (RELU) {
                c[0] = fmaxf(c[0], 0.f); c[1] = fmaxf(c[1], 0.f);
                c[2] = fmaxf(c[2], 0.f); c[3] = fmaxf(c[3], 0.f);
            }
        }
    }

    if (HOUT) {
#pragma unroll
        for (int mt = 0; mt < MT; mt++) {
            int r0 = m0 + warpM * MT * 16 + mt * 16 + g;
#pragma unroll
            for (int nt = 0; nt < NT; nt++) {
                int n = warpN * NT * 8 + nt * 8 + kq;
                float* c = acc[mt][nt];
                if (r0 < M) {
                    __nv_bfloat16 h0 = __float2bfloat16(c[0]);
                    __nv_bfloat16 h1 = __float2bfloat16(c[1]);
                    *(unsigned*)(Hh + (size_t)r0 * 128 + n) = pack2(h0, h1);
                    *(unsigned*)(Hl + (size_t)r0 * 128 + n) =
                        pack2(__float2bfloat16(c[0] - __bfloat162float(h0)),
                              __float2bfloat16(c[1] - __bfloat162float(h1)));
                }
                if (r0 + 8 < M) {
                    __nv_bfloat16 h2 = __float2bfloat16(c[2]);
                    __nv_bfloat16 h3 = __float2bfloat16(c[3]);
                    *(unsigned*)(Hh + (size_t)(r0 + 8) * 128 + n) = pack2(h2, h3);
                    *(unsigned*)(Hl + (size_t)(r0 + 8) * 128 + n) =
                        pack2(__float2bfloat16(c[2] - __bfloat162float(h2)),
                              __float2bfloat16(c[3] - __bfloat162float(h3)));
                }
            }
        }
    } else {
        float* Cb = C + (size_t)blockIdx.y * BN;
#pragma unroll
        for (int mt = 0; mt < MT; mt++) {
            int r0 = m0 + warpM * MT * 16 + mt * 16 + g;
#pragma unroll
            for (int nt = 0; nt < NT; nt++) {
                int n = warpN * NT * 8 + nt * 8 + kq;
                float* c = acc[mt][nt];
                if (r0 < M)
                    *(float2*)(Cb + (size_t)r0 * ldc + n) = make_float2(c[0], c[1]);
                if (r0 + 8 < M)
                    *(float2*)(Cb + (size_t)(r0 + 8) * ldc + n) = make_float2(c[2], c[3]);
            }
        }
    }
}

// ---------------------------------------------------------------------------
extern "C" void kernel_launch(void* const* d_in, const int* in_sizes, int n_in,
                              void* d_out, int out_size) {
    const float* x       = (const float*)d_in[0];
    const int*   ei      = (const int*)d_in[1];
    const int*   et      = (const int*)d_in[2];
    const float* W1_rel  = (const float*)d_in[3];
    const float* W1_root = (const float*)d_in[4];
    const float* b1      = (const float*)d_in[5];
    const float* W2_rel  = (const float*)d_in[6];
    const float* W2_root = (const float*)d_in[7];
    const float* b2      = (const float*)d_in[8];
    float* out = (float*)d_out;

    float* P;
    __nv_bfloat16 *Xh, *Xl, *Ah, *Al, *Hh, *Hl, *W1Th, *W1Tl, *W2Th, *W2Tl;
    int *deg, *offs, *epos, *part, *csr;
    cudaGetSymbolAddress((void**)&P,    g_P);
    cudaGetSymbolAddress((void**)&Xh,   g_X_hi);
    cudaGetSymbolAddress((void**)&Xl,   g_X_lo);
    cudaGetSymbolAddress((void**)&Ah,   g_AGG_hi);
    cudaGetSymbolAddress((void**)&Al,   g_AGG_lo);
    cudaGetSymbolAddress((void**)&Hh,   g_H_hi);
    cudaGetSymbolAddress((void**)&Hl,   g_H_lo);
    cudaGetSymbolAddress((void**)&W1Th, g_W1T_hi);
    cudaGetSymbolAddress((void**)&W1Tl, g_W1T_lo);
    cudaGetSymbolAddress((void**)&W2Th, g_W2T_hi);
    cudaGetSymbolAddress((void**)&W2Tl, g_W2T_lo);
    cudaGetSymbolAddress((void**)&deg,  g_deg);
    cudaGetSymbolAddress((void**)&offs, g_offs);
    cudaGetSymbolAddress((void**)&epos, g_epos);
    cudaGetSymbolAddress((void**)&part, g_part);
    cudaGetSymbolAddress((void**)&csr,  g_csr);

    const int SM1 = (4 * 128 * 40 + 4 * 128 * 40) * 2;   // 81920
    const int SM2 = (4 * 128 * 40 + 4 * 64 * 40) * 2;    // 61440
    auto* k1 = gemm_db_kernel<128, 384, 2, 4, 4, 4, true,  true,  true>;
    auto* k2 = gemm_db_kernel<64,  128, 4, 2, 2, 4, false, false, false>;
    cudaFuncSetAttribute(k1, cudaFuncAttributeMaxDynamicSharedMemorySize, SM1);
    cudaFuncSetAttribute(k2, cudaFuncAttributeMaxDynamicSharedMemorySize, SM2);

    const int TB = 256;
    const int g_prep  = (128 * KTOT + 192 * 128 + TB - 1) / TB;
    const int g_prepx = (N_NODES * 32 + TB - 1) / TB;
    const int g_edge  = (N_EDGES + TB - 1) / TB;
    const int g_agg   = (N_NODES * 32 + TB - 1) / TB;
    const int g_gemm  = (N_NODES + 127) / 128;

    prep_w_kernel<<<g_prep, TB>>>(W1_rel, W1_root, W2_rel, W2_root);
    prep_x_kernel<<<g_prepx, TB>>>(x, Xh, Xl);

    // ---- CSR build (3-phase parallel scan) ----
    cudaMemsetAsync(deg, 0, N_NODES * 4);
    deg_kernel<<<g_edge, TB>>>(ei, deg, epos);
    scan_partial_kernel<<<SCAN_CHUNKS, 1024>>>(deg, part);
    scan_part_kernel<<<1, 128>>>(part);
    scan_final_kernel<<<SCAN_CHUNKS, 1024>>>(deg, part, offs);
    fill_csr_kernel<<<g_edge, TB>>>(ei, et, offs, epos, csr);

    // ---- Layer 1 ----
    agg1_kernel<<<g_agg, TB>>>(x, offs, deg, csr, Ah, Al);
    k1<<<g_gemm, TB, SM1>>>(Xh, Xl, 128, Ah, Al, W1Th, W1Tl, b1,
                            nullptr, N_NODES, 0, Hh, Hl);

    // ---- Layer 2 ----
    k2<<<dim3(g_gemm, 3), TB, SM2>>>(Hh, Hl, 128, nullptr, nullptr, W2Th, W2Tl, nullptr,
                                     P, N_NODES, 192, nullptr, nullptr);
    agg2_kernel<<<g_agg, TB>>>(P, offs, deg, csr, b2, out);
}

// round 13
// speedup vs baseline: 2.8069x; 1.0073x over previous
#include <cuda_runtime.h>
#include <cuda_bf16.h>
#include <cstdint>

#define N_NODES 100000
#define N_EDGES 1600000
#define KTOT 384
#define SCAN_CHUNKS ((N_NODES + 1023) / 1024)   // 98

// ---------------------------------------------------------------------------
// Device-global scratch
__device__ float g_P[(size_t)N_NODES * 192];            // layer-2 transformed
__device__ float g_C1[(size_t)N_NODES * 128];           // gemm1a partial (x @ W1[0:128])
__device__ __nv_bfloat16 g_X_hi[(size_t)N_NODES * 128]; // x pre-split
__device__ __nv_bfloat16 g_X_lo[(size_t)N_NODES * 128];
__device__ __nv_bfloat16 g_AGG_hi[(size_t)N_NODES * 256]; // A0|A1 mean-scaled, pre-split
__device__ __nv_bfloat16 g_AGG_lo[(size_t)N_NODES * 256];
__device__ __nv_bfloat16 g_H_hi[(size_t)N_NODES * 128];
__device__ __nv_bfloat16 g_H_lo[(size_t)N_NODES * 128];
__device__ __nv_bfloat16 g_W1T_hi[128 * KTOT];
__device__ __nv_bfloat16 g_W1T_lo[128 * KTOT];
__device__ __nv_bfloat16 g_W2T_hi[192 * 128];
__device__ __nv_bfloat16 g_W2T_lo[192 * 128];
__device__ int g_deg[N_NODES];
__device__ int g_offs[N_NODES];
__device__ int g_epos[N_EDGES];
__device__ int g_part[SCAN_CHUNKS];
__device__ int g_csr[N_EDGES];                          // src | (rel<<30), grouped by dst

// ---------------------------------------------------------------------------
__device__ __forceinline__ unsigned pack2(__nv_bfloat16 a, __nv_bfloat16 b) {
    union { __nv_bfloat162 v; unsigned u; } c;
    c.v = __halves2bfloat162(a, b);
    return c.u;
}

__device__ __forceinline__ void split4(const float4 v,
                                       unsigned& hi0, unsigned& hi1,
                                       unsigned& lo0, unsigned& lo1) {
    __nv_bfloat16 h0 = __float2bfloat16(v.x), h1 = __float2bfloat16(v.y);
    __nv_bfloat16 h2 = __float2bfloat16(v.z), h3 = __float2bfloat16(v.w);
    __nv_bfloat16 l0 = __float2bfloat16(v.x - __bfloat162float(h0));
    __nv_bfloat16 l1 = __float2bfloat16(v.y - __bfloat162float(h1));
    __nv_bfloat16 l2 = __float2bfloat16(v.z - __bfloat162float(h2));
    __nv_bfloat16 l3 = __float2bfloat16(v.w - __bfloat162float(h3));
    hi0 = pack2(h0, h1); hi1 = pack2(h2, h3);
    lo0 = pack2(l0, l1); lo1 = pack2(l2, l3);
}

// ---------------------------------------------------------------------------
__global__ void __launch_bounds__(256)
prep_w_kernel(const float* __restrict__ W1_rel,
              const float* __restrict__ W1_root,
              const float* __restrict__ W2_rel,
              const float* __restrict__ W2_root) {
    int i = blockIdx.x * blockDim.x + threadIdx.x;
    const int SZ1 = 128 * KTOT;
    const int SZ2 = 192 * 128;
    if (i >= SZ1 + SZ2) return;
    float v;
    __nv_bfloat16 *dh, *dl;
    if (i < SZ1) {
        int n = i / KTOT, k = i % KTOT;
        if (k < 128) v = W1_root[k * 128 + n];
        else {
            int r = (k - 128) >> 7, kk = (k - 128) & 127;
            v = W1_rel[(size_t)r * 128 * 128 + kk * 128 + n];
        }
        dh = g_W1T_hi + i; dl = g_W1T_lo + i;
    } else {
        int j = i - SZ1;
        int n = j / 128, k = j % 128;
        if (n < 64)       v = W2_root[k * 64 + n];
        else if (n < 128) v = W2_rel[(size_t)0 * 128 * 64 + k * 64 + (n - 64)];
        else              v = W2_rel[(size_t)1 * 128 * 64 + k * 64 + (n - 128)];
        dh = g_W2T_hi + j; dl = g_W2T_lo + j;
    }
    __nv_bfloat16 h = __float2bfloat16(v);
    *dh = h;
    *dl = __float2bfloat16(v - __bfloat162float(h));
}

// Pre-split x into bf16 hi/lo
__global__ void __launch_bounds__(256)
prep_x_kernel(const float* __restrict__ x,
              __nv_bfloat16* __restrict__ Xh, __nv_bfloat16* __restrict__ Xl) {
    int i = blockIdx.x * blockDim.x + threadIdx.x;      // over N*32 float4
    if (i >= N_NODES * 32) return;
    float4 v = ((const float4*)x)[i];
    unsigned h0, h1, l0, l1;
    split4(v, h0, h1, l0, l1);
    ((uint2*)Xh)[i] = make_uint2(h0, h1);
    ((uint2*)Xl)[i] = make_uint2(l0, l1);
}

// ---------------------------------------------------------------------------
// CSR construction
__global__ void __launch_bounds__(256)
deg_kernel(const int* __restrict__ ei, int* __restrict__ deg, int* __restrict__ epos) {
    int e = blockIdx.x * blockDim.x + threadIdx.x;
    if (e < N_EDGES) epos[e] = atomicAdd(&deg[ei[N_EDGES + e]], 1);
}

__global__ void __launch_bounds__(1024)
scan_partial_kernel(const int* __restrict__ deg, int* __restrict__ part) {
    __shared__ int red[32];
    int idx = blockIdx.x * 1024 + threadIdx.x;
    int v = (idx < N_NODES) ? deg[idx] : 0;
#pragma unroll
    for (int o = 16; o; o >>= 1) v += __shfl_xor_sync(0xFFFFFFFFu, v, o);
    if ((threadIdx.x & 31) == 0) red[threadIdx.x >> 5] = v;
    __syncthreads();
    if (threadIdx.x < 32) {
        int s = red[threadIdx.x];
#pragma unroll
        for (int o = 16; o; o >>= 1) s += __shfl_xor_sync(0xFFFFFFFFu, s, o);
        if (threadIdx.x == 0) part[blockIdx.x] = s;
    }
}

__global__ void __launch_bounds__(128)
scan_part_kernel(int* __restrict__ part) {
    __shared__ int buf[SCAN_CHUNKS];
    int t = threadIdx.x;
    if (t < SCAN_CHUNKS) buf[t] = part[t];
    __syncthreads();
    if (t == 0) {
        int run = 0;
        for (int i = 0; i < SCAN_CHUNKS; i++) {
            int v = buf[i];
            buf[i] = run;
            run += v;
        }
    }
    __syncthreads();
    if (t < SCAN_CHUNKS) part[t] = buf[t];
}

__global__ void __launch_bounds__(1024)
scan_final_kernel(const int* __restrict__ deg, const int* __restrict__ part,
                  int* __restrict__ offs) {
    __shared__ int warpsum[32];
    int t = threadIdx.x;
    int idx = blockIdx.x * 1024 + t;
    int v = (idx < N_NODES) ? deg[idx] : 0;
    int lane = t & 31, wid = t >> 5;
    int sc = v;
#pragma unroll
    for (int o = 1; o < 32; o <<= 1) {
        int u = __shfl_up_sync(0xFFFFFFFFu, sc, o);
        if (lane >= o) sc += u;
    }
    if (lane == 31) warpsum[wid] = sc;
    __syncthreads();
    if (wid == 0) {
        int s = warpsum[lane];
#pragma unroll
        for (int o = 1; o < 32; o <<= 1) {
            int u = __shfl_up_sync(0xFFFFFFFFu, s, o);
            if (lane >= o) s += u;
        }
        warpsum[lane] = s;
    }
    __syncthreads();
    int base = part[blockIdx.x] + ((wid > 0) ? warpsum[wid - 1] : 0);
    if (idx < N_NODES) offs[idx] = base + sc - v;
}

__global__ void __launch_bounds__(256)
fill_csr_kernel(const int* __restrict__ ei, const int* __restrict__ et,
                const int* __restrict__ offs, const int* __restrict__ epos,
                int* __restrict__ csr) {
    int e = blockIdx.x * blockDim.x + threadIdx.x;
    if (e >= N_EDGES) return;
    int s = ei[e];
    int d = ei[N_EDGES + e];
    int r = et[e];
    csr[offs[d] + epos[e]] = s | (r << 30);
}

// ---------------------------------------------------------------------------
// Layer-1 aggregation (L2 BW floor)
__global__ void __launch_bounds__(256)
agg1_kernel(const float* __restrict__ x,
            const int* __restrict__ offs, const int* __restrict__ deg,
            const int* __restrict__ csr,
            __nv_bfloat16* __restrict__ AGGh, __nv_bfloat16* __restrict__ AGGl) {
    int w = (blockIdx.x * blockDim.x + threadIdx.x) >> 5;
    int lane = threadIdx.x & 31;
    if (w >= N_NODES) return;
    int off = offs[w], dg = deg[w];
    float4 a0 = make_float4(0.f, 0.f, 0.f, 0.f);
    float4 a1 = make_float4(0.f, 0.f, 0.f, 0.f);
    int c0 = 0;
    int j = 0;
    const int col = lane * 4;
    for (; j + 4 <= dg; j += 4) {
        int e0 = csr[off + j], e1 = csr[off + j + 1];
        int e2 = csr[off + j + 2], e3 = csr[off + j + 3];
        float4 v0 = *(const float4*)(x + (size_t)(e0 & 0x3FFFFFFF) * 128 + col);
        float4 v1 = *(const float4*)(x + (size_t)(e1 & 0x3FFFFFFF) * 128 + col);
        float4 v2 = *(const float4*)(x + (size_t)(e2 & 0x3FFFFFFF) * 128 + col);
        float4 v3 = *(const float4*)(x + (size_t)(e3 & 0x3FFFFFFF) * 128 + col);
        if ((e0 >> 30) == 0) { a0.x += v0.x; a0.y += v0.y; a0.z += v0.z; a0.w += v0.w; c0++; }
        else                 { a1.x += v0.x; a1.y += v0.y; a1.z += v0.z; a1.w += v0.w; }
        if ((e1 >> 30) == 0) { a0.x += v1.x; a0.y += v1.y; a0.z += v1.z; a0.w += v1.w; c0++; }
        else                 { a1.x += v1.x; a1.y += v1.y; a1.z += v1.z; a1.w += v1.w; }
        if ((e2 >> 30) == 0) { a0.x += v2.x; a0.y += v2.y; a0.z += v2.z; a0.w += v2.w; c0++; }
        else                 { a1.x += v2.x; a1.y += v2.y; a1.z += v2.z; a1.w += v2.w; }
        if ((e3 >> 30) == 0) { a0.x += v3.x; a0.y += v3.y; a0.z += v3.z; a0.w += v3.w; c0++; }
        else                 { a1.x += v3.x; a1.y += v3.y; a1.z += v3.z; a1.w += v3.w; }
    }
    for (; j < dg; j++) {
        int e0 = csr[off + j];
        float4 v0 = *(const float4*)(x + (size_t)(e0 & 0x3FFFFFFF) * 128 + col);
        if ((e0 >> 30) == 0) { a0.x += v0.x; a0.y += v0.y; a0.z += v0.z; a0.w += v0.w; c0++; }
        else                 { a1.x += v0.x; a1.y += v0.y; a1.z += v0.z; a1.w += v0.w; }
    }
    int c1 = dg - c0;
    float s0 = 1.0f / (float)max(c0, 1);
    float s1 = 1.0f / (float)max(c1, 1);
    a0.x *= s0; a0.y *= s0; a0.z *= s0; a0.w *= s0;
    a1.x *= s1; a1.y *= s1; a1.z *= s1; a1.w *= s1;
    unsigned h0, h1, l0, l1;
    split4(a0, h0, h1, l0, l1);
    *(uint2*)(AGGh + (size_t)w * 256 + col) = make_uint2(h0, h1);
    *(uint2*)(AGGl + (size_t)w * 256 + col) = make_uint2(l0, l1);
    split4(a1, h0, h1, l0, l1);
    *(uint2*)(AGGh + (size_t)w * 256 + 128 + col) = make_uint2(h0, h1);
    *(uint2*)(AGGl + (size_t)w * 256 + 128 + col) = make_uint2(l0, l1);
}

// Layer-2 aggregation + final epilogue
__global__ void __launch_bounds__(256)
agg2_kernel(const float* __restrict__ P,
            const int* __restrict__ offs, const int* __restrict__ deg,
            const int* __restrict__ csr,
            const float* __restrict__ b2, float* __restrict__ out) {
    int w = (blockIdx.x * blockDim.x + threadIdx.x) >> 5;
    int lane = threadIdx.x & 31;
    if (w >= N_NODES) return;
    int off = offs[w], dg = deg[w];
    float2 a0 = make_float2(0.f, 0.f), a1 = make_float2(0.f, 0.f);
    int c0 = 0;
    int j = 0;
    const int col = lane * 2;
    for (; j + 4 <= dg; j += 4) {
        int e0 = csr[off + j], e1 = csr[off + j + 1];
        int e2 = csr[off + j + 2], e3 = csr[off + j + 3];
        float2 v0 = *(const float2*)(P + (size_t)(e0 & 0x3FFFFFFF) * 192 + 64 + (e0 >> 30) * 64 + col);
        float2 v1 = *(const float2*)(P + (size_t)(e1 & 0x3FFFFFFF) * 192 + 64 + (e1 >> 30) * 64 + col);
        float2 v2 = *(const float2*)(P + (size_t)(e2 & 0x3FFFFFFF) * 192 + 64 + (e2 >> 30) * 64 + col);
        float2 v3 = *(const float2*)(P + (size_t)(e3 & 0x3FFFFFFF) * 192 + 64 + (e3 >> 30) * 64 + col);
        if ((e0 >> 30) == 0) { a0.x += v0.x; a0.y += v0.y; c0++; } else { a1.x += v0.x; a1.y += v0.y; }
        if ((e1 >> 30) == 0) { a0.x += v1.x; a0.y += v1.y; c0++; } else { a1.x += v1.x; a1.y += v1.y; }
        if ((e2 >> 30) == 0) { a0.x += v2.x; a0.y += v2.y; c0++; } else { a1.x += v2.x; a1.y += v2.y; }
        if ((e3 >> 30) == 0) { a0.x += v3.x; a0.y += v3.y; c0++; } else { a1.x += v3.x; a1.y += v3.y; }
    }
    for (; j < dg; j++) {
        int e0 = csr[off + j];
        float2 v0 = *(const float2*)(P + (size_t)(e0 & 0x3FFFFFFF) * 192 + 64 + (e0 >> 30) * 64 + col);
        if ((e0 >> 30) == 0) { a0.x += v0.x; a0.y += v0.y; c0++; } else { a1.x += v0.x; a1.y += v0.y; }
    }
    int c1 = dg - c0;
    float s0 = 1.0f / (float)max(c0, 1);
    float s1 = 1.0f / (float)max(c1, 1);
    float2 p0 = *(const float2*)(P + (size_t)w * 192 + col);
    float2 bb = *(const float2*)(b2 + col);
    float2 v;
    v.x = p0.x + a0.x * s0 + a1.x * s1 + bb.x;
    v.y = p0.y + a0.y * s0 + a1.y * s1 + bb.y;
    float ss = v.x * v.x + v.y * v.y;
#pragma unroll
    for (int o = 16; o; o >>= 1) ss += __shfl_xor_sync(0xFFFFFFFFu, ss, o);
    float sc = 1.0f / fmaxf(sqrtf(ss), 1e-12f);
    v.x *= sc; v.y *= sc;
    *(float2*)(out + (size_t)w * 64 + col) = v;
}

// ---------------------------------------------------------------------------
__device__ __forceinline__ void mma_bf16(float* c, const unsigned* a, unsigned b0, unsigned b1) {
    asm volatile(
        "mma.sync.aligned.m16n8k16.row.col.f32.bf16.bf16.f32 "
        "{%0,%1,%2,%3}, {%4,%5,%6,%7}, {%8,%9}, {%0,%1,%2,%3};"
        : "+f"(c[0]), "+f"(c[1]), "+f"(c[2]), "+f"(c[3])
        : "r"(a[0]), "r"(a[1]), "r"(a[2]), "r"(a[3]), "r"(b0), "r"(b1));
}

__device__ __forceinline__ void ldsm4(uint32_t addr, unsigned& r0, unsigned& r1,
                                      unsigned& r2, unsigned& r3) {
    asm volatile("ldmatrix.sync.aligned.m8n8.x4.shared.b16 {%0,%1,%2,%3}, [%4];"
                 : "=r"(r0), "=r"(r1), "=r"(r2), "=r"(r3) : "r"(addr));
}

__device__ __forceinline__ void cp16(void* dst_smem, const void* src) {
    uint32_t d = (uint32_t)__cvta_generic_to_shared(dst_smem);
    asm volatile("cp.async.ca.shared.global [%0], [%1], 16;" :: "r"(d), "l"(src));
}

// ---------------------------------------------------------------------------
// Double-buffered tensor-core GEMM, bf16 3-term split, pure cp.async A path.
// ldw: weight row stride (decoupled from KDIM — supports K-slices of W).
// PARTIAL: epilogue adds Cin[row, 0:128]. HOUT: pre-split bf16 H (+relu).
template<int BN, int KDIM, int WM, int WN, int MT, int NT, bool RELU, bool HOUT, bool PARTIAL>
__global__ void __launch_bounds__(256, 2)
gemm_db_kernel(const __nv_bfloat16* __restrict__ Ah,
               const __nv_bfloat16* __restrict__ Al, int lda,
               const __nv_bfloat16* __restrict__ WT_hi,
               const __nv_bfloat16* __restrict__ WT_lo, int ldw,
               const float* __restrict__ bias,
               const float* __restrict__ Cin,
               float* __restrict__ C, int M, int ldc,
               __nv_bfloat16* __restrict__ Hh,
               __nv_bfloat16* __restrict__ Hl) {
    constexpr int BM = 128, BK = 32, BKP = 40;
    constexpr int ASZ = BM * BKP;
    constexpr int BSZ = BN * BKP;
    constexpr int T = KDIM / BK;

    extern __shared__ __align__(16) char smem_raw[];
    __nv_bfloat16* As_hi[2]; __nv_bfloat16* As_lo[2];
    __nv_bfloat16* Bs_hi[2]; __nv_bfloat16* Bs_lo[2];
    {
        __nv_bfloat16* p = (__nv_bfloat16*)smem_raw;
        As_hi[0] = p;            As_lo[0] = p + ASZ;
        As_hi[1] = p + 2 * ASZ;  As_lo[1] = p + 3 * ASZ;
        p += 4 * ASZ;
        Bs_hi[0] = p;            Bs_lo[0] = p + BSZ;
        Bs_hi[1] = p + 2 * BSZ;  Bs_lo[1] = p + 3 * BSZ;
    }

    const int tid = threadIdx.x;
    const int lane = tid & 31;
    const int warp = tid >> 5;
    const int warpM = warp / WN;
    const int warpN = warp % WN;
    const int m0 = blockIdx.x * BM;
    const int g = lane >> 2;
    const int kq = (lane & 3) * 2;

    const __nv_bfloat16* Wh = WT_hi + (size_t)blockIdx.y * BN * ldw;
    const __nv_bfloat16* Wl = WT_lo + (size_t)blockIdx.y * BN * ldw;

    float acc[MT][NT][4];
#pragma unroll
    for (int i = 0; i < MT; i++)
#pragma unroll
        for (int j = 0; j < NT; j++)
#pragma unroll
            for (int q = 0; q < 4; q++) acc[i][j][q] = 0.f;

    auto loadB = [&](int k0, int stg) {
#pragma unroll
        for (int i = tid; i < BN * 4; i += 256) {
            int n = i >> 2, q = i & 3;
            cp16(Bs_hi[stg] + n * BKP + q * 8, Wh + (size_t)n * ldw + k0 + q * 8);
            cp16(Bs_lo[stg] + n * BKP + q * 8, Wl + (size_t)n * ldw + k0 + q * 8);
        }
    };
    auto loadA = [&](int k0, int stg) {
#pragma unroll
        for (int i = tid; i < BM * 4; i += 256) {
            int row = i >> 2, q = i & 3;
            int m = (m0 + row < M) ? (m0 + row) : (M - 1);
            cp16(As_hi[stg] + row * BKP + q * 8, Ah + (size_t)m * lda + k0 + q * 8);
            cp16(As_lo[stg] + row * BKP + q * 8, Al + (size_t)m * lda + k0 + q * 8);
        }
    };

    const int rowA = (lane & 7) + (lane & 8);
    const int colA = (lane & 16) ? 8 : 0;
    const int gB = lane >> 3;
    const int rowB = (lane & 7) + ((gB & 1) ? 8 : 0);
    const int colB = (gB >> 1) * 8;

    uint32_t sAhi[2], sAlo[2], sBhi[2], sBlo[2];
#pragma unroll
    for (int s = 0; s < 2; s++) {
        sAhi[s] = (uint32_t)__cvta_generic_to_shared(As_hi[s]);
        sAlo[s] = (uint32_t)__cvta_generic_to_shared(As_lo[s]);
        sBhi[s] = (uint32_t)__cvta_generic_to_shared(Bs_hi[s]);
        sBlo[s] = (uint32_t)__cvta_generic_to_shared(Bs_lo[s]);
    }

    auto compute = [&](int stg) {
#pragma unroll
        for (int ks = 0; ks < BK; ks += 16) {
            unsigned ah[MT][4], al[MT][4];
#pragma unroll
            for (int mt = 0; mt < MT; mt++) {
                uint32_t off = (uint32_t)(2 * ((warpM * MT * 16 + mt * 16 + rowA) * BKP + ks + colA));
                ldsm4(sAhi[stg] + off, ah[mt][0], ah[mt][1], ah[mt][2], ah[mt][3]);
                ldsm4(sAlo[stg] + off, al[mt][0], al[mt][1], al[mt][2], al[mt][3]);
            }
            unsigned bh0[NT], bh1[NT], bl0[NT], bl1[NT];
#pragma unroll
            for (int np = 0; np < NT / 2; np++) {
                uint32_t off = (uint32_t)(2 * ((warpN * NT * 8 + np * 16 + rowB) * BKP + ks + colB));
                ldsm4(sBhi[stg] + off, bh0[np * 2], bh0[np * 2 + 1], bh1[np * 2], bh1[np * 2 + 1]);
                ldsm4(sBlo[stg] + off, bl0[np * 2], bl0[np * 2 + 1], bl1[np * 2], bl1[np * 2 + 1]);
            }
#pragma unroll
            for (int mt = 0; mt < MT; mt++)
#pragma unroll
                for (int nt = 0; nt < NT; nt++) {
                    mma_bf16(acc[mt][nt], ah[mt], bh0[nt], bh1[nt]);
                    mma_bf16(acc[mt][nt], ah[mt], bl0[nt], bl1[nt]);
                    mma_bf16(acc[mt][nt], al[mt], bh0[nt], bh1[nt]);
                }
        }
    };

    loadB(0, 0);
    loadA(0, 0);
    asm volatile("cp.async.commit_group;\ncp.async.wait_group 0;" ::: "memory");
    __syncthreads();

    for (int t = 0; t < T; t++) {
        int cur = t & 1, nxt = cur ^ 1;
        bool hasNext = (t + 1 < T);
        int k1 = (t + 1) * BK;
        if (hasNext) {
            loadB(k1, nxt);
            loadA(k1, nxt);
        }
        compute(cur);
        asm volatile("cp.async.commit_group;\ncp.async.wait_group 0;" ::: "memory");
        __syncthreads();
    }

#pragma unroll
    for (int nt = 0; nt < NT; nt++) {
        int n = warpN * NT * 8 + nt * 8 + kq;
        float b0 = bias ? bias[n] : 0.f;
        float b1 = bias ? bias[n + 1] : 0.f;
#pragma unroll
        for (int mt = 0; mt < MT; mt++) {
            float* c = acc[mt][nt];
            c[0] += b0; c[1] += b1; c[2] += b0; c[3] += b1;
        }
    }

    if (HOUT) {
#pragma unroll
        for (int mt = 0; mt < MT; mt++) {
            int r0 = m0 + warpM * MT * 16 + mt * 16 + g;
#pragma unroll
            for (int nt = 0; nt < NT; nt++) {
                int n = warpN * NT * 8 + nt * 8 + kq;
                float* c = acc[mt][nt];
                if (r0 < M) {
                    float v0 = c[0], v1 = c[1];
                    if (PARTIAL) {
                        float2 pc = *(const float2*)(Cin + (size_t)r0 * 128 + n);
                        v0 += pc.x; v1 += pc.y;
                    }
                    if (RELU) { v0 = fmaxf(v0, 0.f); v1 = fmaxf(v1, 0.f); }
                    __nv_bfloat16 h0 = __float2bfloat16(v0);
                    __nv_bfloat16 h1 = __float2bfloat16(v1);
                    *(unsigned*)(Hh + (size_t)r0 * 128 + n) = pack2(h0, h1);
                    *(unsigned*)(Hl + (size_t)r0 * 128 + n) =
                        pack2(__float2bfloat16(v0 - __bfloat162float(h0)),
                              __float2bfloat16(v1 - __bfloat162float(h1)));
                }
                if (r0 + 8 < M) {
                    float v2 = c[2], v3 = c[3];
                    if (PARTIAL) {
                        float2 pc = *(const float2*)(Cin + (size_t)(r0 + 8) * 128 + n);
                        v2 += pc.x; v3 += pc.y;
                    }
                    if (RELU) { v2 = fmaxf(v2, 0.f); v3 = fmaxf(v3, 0.f); }
                    __nv_bfloat16 h2 = __float2bfloat16(v2);
                    __nv_bfloat16 h3 = __float2bfloat16(v3);
                    *(unsigned*)(Hh + (size_t)(r0 + 8) * 128 + n) = pack2(h2, h3);
                    *(unsigned*)(Hl + (size_t)(r0 + 8) * 128 + n) =
                        pack2(__float2bfloat16(v2 - __bfloat162float(h2)),
                              __float2bfloat16(v3 - __bfloat162float(h3)));
                }
            }
        }
    } else {
        float* Cb = C + (size_t)blockIdx.y * BN;
#pragma unroll
        for (int mt = 0; mt < MT; mt++) {
            int r0 = m0 + warpM * MT * 16 + mt * 16 + g;
#pragma unroll
            for (int nt = 0; nt < NT; nt++) {
                int n = warpN * NT * 8 + nt * 8 + kq;
                float* c = acc[mt][nt];
                if (r0 < M)
                    *(float2*)(Cb + (size_t)r0 * ldc + n) = make_float2(c[0], c[1]);
                if (r0 + 8 < M)
                    *(float2*)(Cb + (size_t)(r0 + 8) * ldc + n) = make_float2(c[2], c[3]);
            }
        }
    }
}

// ---------------------------------------------------------------------------
extern "C" void kernel_launch(void* const* d_in, const int* in_sizes, int n_in,
                              void* d_out, int out_size) {
    const float* x       = (const float*)d_in[0];
    const int*   ei      = (const int*)d_in[1];
    const int*   et      = (const int*)d_in[2];
    const float* W1_rel  = (const float*)d_in[3];
    const float* W1_root = (const float*)d_in[4];
    const float* b1      = (const float*)d_in[5];
    const float* W2_rel  = (const float*)d_in[6];
    const float* W2_root = (const float*)d_in[7];
    const float* b2      = (const float*)d_in[8];
    float* out = (float*)d_out;

    float *P, *C1;
    __nv_bfloat16 *Xh, *Xl, *Ah, *Al, *Hh, *Hl, *W1Th, *W1Tl, *W2Th, *W2Tl;
    int *deg, *offs, *epos, *part, *csr;
    cudaGetSymbolAddress((void**)&P,    g_P);
    cudaGetSymbolAddress((void**)&C1,   g_C1);
    cudaGetSymbolAddress((void**)&Xh,   g_X_hi);
    cudaGetSymbolAddress((void**)&Xl,   g_X_lo);
    cudaGetSymbolAddress((void**)&Ah,   g_AGG_hi);
    cudaGetSymbolAddress((void**)&Al,   g_AGG_lo);
    cudaGetSymbolAddress((void**)&Hh,   g_H_hi);
    cudaGetSymbolAddress((void**)&Hl,   g_H_lo);
    cudaGetSymbolAddress((void**)&W1Th, g_W1T_hi);
    cudaGetSymbolAddress((void**)&W1Tl, g_W1T_lo);
    cudaGetSymbolAddress((void**)&W2Th, g_W2T_hi);
    cudaGetSymbolAddress((void**)&W2Tl, g_W2T_lo);
    cudaGetSymbolAddress((void**)&deg,  g_deg);
    cudaGetSymbolAddress((void**)&offs, g_offs);
    cudaGetSymbolAddress((void**)&epos, g_epos);
    cudaGetSymbolAddress((void**)&part, g_part);
    cudaGetSymbolAddress((void**)&csr,  g_csr);

    const int SMG = (4 * 128 * 40 + 4 * 128 * 40) * 2;   // 81920 (BN=128)
    const int SM2 = (4 * 128 * 40 + 4 * 64 * 40) * 2;    // 61440 (BN=64)
    auto* k1a = gemm_db_kernel<128, 128, 2, 4, 4, 4, false, false, false>;  // x part -> fp32 C1
    auto* k1b = gemm_db_kernel<128, 256, 2, 4, 4, 4, true,  true,  true>;   // AGG part + C1 -> H
    auto* k2  = gemm_db_kernel<64,  128, 4, 2, 2, 4, false, false, false>;
    cudaFuncSetAttribute(k1a, cudaFuncAttributeMaxDynamicSharedMemorySize, SMG);
    cudaFuncSetAttribute(k1b, cudaFuncAttributeMaxDynamicSharedMemorySize, SMG);
    cudaFuncSetAttribute(k2,  cudaFuncAttributeMaxDynamicSharedMemorySize, SM2);

    const int TB = 256;
    const int g_prep  = (128 * KTOT + 192 * 128 + TB - 1) / TB;
    const int g_prepx = (N_NODES * 32 + TB - 1) / TB;
    const int g_edge  = (N_EDGES + TB - 1) / TB;
    const int g_agg   = (N_NODES * 32 + TB - 1) / TB;
    const int g_gemm  = (N_NODES + 127) / 128;

    // ---- fork: side stream runs preps + gemm1a while main runs CSR + agg1 ----
    cudaStream_t s1;
    cudaEvent_t ev0, ev1;
    cudaStreamCreateWithFlags(&s1, cudaStreamNonBlocking);
    cudaEventCreateWithFlags(&ev0, cudaEventDisableTiming);
    cudaEventCreateWithFlags(&ev1, cudaEventDisableTiming);

    cudaEventRecord(ev0, 0);
    cudaStreamWaitEvent(s1, ev0, 0);

    // side stream: weight/x preps, then x-slice GEMM (independent of CSR/agg1)
    prep_w_kernel<<<g_prep, TB, 0, s1>>>(W1_rel, W1_root, W2_rel, W2_root);
    prep_x_kernel<<<g_prepx, TB, 0, s1>>>(x, Xh, Xl);
    // C1 = x @ W1[0:128]  (weight rows stride KTOT)
    k1a<<<g_gemm, TB, SMG, s1>>>(Xh, Xl, 128, W1Th, W1Tl, KTOT, nullptr, nullptr,
                                 C1, N_NODES, 128, nullptr, nullptr);
    cudaEventRecord(ev1, s1);

    // main stream: CSR build + layer-1 aggregation
    cudaMemsetAsync(deg, 0, N_NODES * 4);
    deg_kernel<<<g_edge, TB>>>(ei, deg, epos);
    scan_partial_kernel<<<SCAN_CHUNKS, 1024>>>(deg, part);
    scan_part_kernel<<<1, 128>>>(part);
    scan_final_kernel<<<SCAN_CHUNKS, 1024>>>(deg, part, offs);
    fill_csr_kernel<<<g_edge, TB>>>(ei, et, offs, epos, csr);
    agg1_kernel<<<g_agg, TB>>>(x, offs, deg, csr, Ah, Al);

    // join, then AGG-slice GEMM completes H = relu(C1 + AGG@W1[128:384] + b1)
    cudaStreamWaitEvent(0, ev1, 0);
    k1b<<<g_gemm, TB, SMG>>>(Ah, Al, 256, W1Th + 128, W1Tl + 128, KTOT, b1, C1,
                             nullptr, N_NODES, 0, Hh, Hl);

    // ---- Layer 2 ----
    k2<<<dim3(g_gemm, 3), TB, SM2>>>(Hh, Hl, 128, W2Th, W2Tl, 128, nullptr, nullptr,
                                     P, N_NODES, 192, nullptr, nullptr);
    agg2_kernel<<<g_agg, TB>>>(P, offs, deg, csr, b2, out);

    cudaEventDestroy(ev0);
    cudaEventDestroy(ev1);
    cudaStreamDestroy(s1);
}

// round 14
// speedup vs baseline: 2.8189x; 1.0043x over previous
#include <cuda_runtime.h>
#include <cuda_bf16.h>
#include <cstdint>

#define N_NODES 100000
#define N_EDGES 1600000
#define KTOT 384
#define SCAN_CHUNKS ((N_NODES + 1023) / 1024)   // 98
#define HALF0 50048                              // 391 * 128
#define HALF1 (N_NODES - HALF0)                  // 49952

// ---------------------------------------------------------------------------
// Device-global scratch
__device__ float g_P[(size_t)N_NODES * 192];            // layer-2 transformed
__device__ float g_C1[(size_t)N_NODES * 128];           // gemm1a partial (x @ W1[0:128])
__device__ __nv_bfloat16 g_X_hi[(size_t)N_NODES * 128]; // x pre-split
__device__ __nv_bfloat16 g_X_lo[(size_t)N_NODES * 128];
__device__ __nv_bfloat16 g_AGG_hi[(size_t)N_NODES * 256]; // A0|A1 mean-scaled, pre-split
__device__ __nv_bfloat16 g_AGG_lo[(size_t)N_NODES * 256];
__device__ __nv_bfloat16 g_H_hi[(size_t)N_NODES * 128];
__device__ __nv_bfloat16 g_H_lo[(size_t)N_NODES * 128];
__device__ __nv_bfloat16 g_W1T_hi[128 * KTOT];
__device__ __nv_bfloat16 g_W1T_lo[128 * KTOT];
__device__ __nv_bfloat16 g_W2T_hi[192 * 128];
__device__ __nv_bfloat16 g_W2T_lo[192 * 128];
__device__ int g_deg[N_NODES];
__device__ int g_offs[N_NODES];
__device__ int g_epos[N_EDGES];
__device__ int g_part[SCAN_CHUNKS];
__device__ int g_csr[N_EDGES];                          // src | (rel<<30), grouped by dst

// ---------------------------------------------------------------------------
__device__ __forceinline__ unsigned pack2(__nv_bfloat16 a, __nv_bfloat16 b) {
    union { __nv_bfloat162 v; unsigned u; } c;
    c.v = __halves2bfloat162(a, b);
    return c.u;
}

__device__ __forceinline__ void split4(const float4 v,
                                       unsigned& hi0, unsigned& hi1,
                                       unsigned& lo0, unsigned& lo1) {
    __nv_bfloat16 h0 = __float2bfloat16(v.x), h1 = __float2bfloat16(v.y);
    __nv_bfloat16 h2 = __float2bfloat16(v.z), h3 = __float2bfloat16(v.w);
    __nv_bfloat16 l0 = __float2bfloat16(v.x - __bfloat162float(h0));
    __nv_bfloat16 l1 = __float2bfloat16(v.y - __bfloat162float(h1));
    __nv_bfloat16 l2 = __float2bfloat16(v.z - __bfloat162float(h2));
    __nv_bfloat16 l3 = __float2bfloat16(v.w - __bfloat162float(h3));
    hi0 = pack2(h0, h1); hi1 = pack2(h2, h3);
    lo0 = pack2(l0, l1); lo1 = pack2(l2, l3);
}

// ---------------------------------------------------------------------------
__global__ void __launch_bounds__(256)
prep_w_kernel(const float* __restrict__ W1_rel,
              const float* __restrict__ W1_root,
              const float* __restrict__ W2_rel,
              const float* __restrict__ W2_root) {
    int i = blockIdx.x * blockDim.x + threadIdx.x;
    const int SZ1 = 128 * KTOT;
    const int SZ2 = 192 * 128;
    if (i >= SZ1 + SZ2) return;
    float v;
    __nv_bfloat16 *dh, *dl;
    if (i < SZ1) {
        int n = i / KTOT, k = i % KTOT;
        if (k < 128) v = W1_root[k * 128 + n];
        else {
            int r = (k - 128) >> 7, kk = (k - 128) & 127;
            v = W1_rel[(size_t)r * 128 * 128 + kk * 128 + n];
        }
        dh = g_W1T_hi + i; dl = g_W1T_lo + i;
    } else {
        int j = i - SZ1;
        int n = j / 128, k = j % 128;
        if (n < 64)       v = W2_root[k * 64 + n];
        else if (n < 128) v = W2_rel[(size_t)0 * 128 * 64 + k * 64 + (n - 64)];
        else              v = W2_rel[(size_t)1 * 128 * 64 + k * 64 + (n - 128)];
        dh = g_W2T_hi + j; dl = g_W2T_lo + j;
    }
    __nv_bfloat16 h = __float2bfloat16(v);
    *dh = h;
    *dl = __float2bfloat16(v - __bfloat162float(h));
}

// Pre-split x into bf16 hi/lo
__global__ void __launch_bounds__(256)
prep_x_kernel(const float* __restrict__ x,
              __nv_bfloat16* __restrict__ Xh, __nv_bfloat16* __restrict__ Xl) {
    int i = blockIdx.x * blockDim.x + threadIdx.x;      // over N*32 float4
    if (i >= N_NODES * 32) return;
    float4 v = ((const float4*)x)[i];
    unsigned h0, h1, l0, l1;
    split4(v, h0, h1, l0, l1);
    ((uint2*)Xh)[i] = make_uint2(h0, h1);
    ((uint2*)Xl)[i] = make_uint2(l0, l1);
}

// ---------------------------------------------------------------------------
// CSR construction
__global__ void __launch_bounds__(256)
deg_kernel(const int* __restrict__ ei, int* __restrict__ deg, int* __restrict__ epos) {
    int e = blockIdx.x * blockDim.x + threadIdx.x;
    if (e < N_EDGES) epos[e] = atomicAdd(&deg[ei[N_EDGES + e]], 1);
}

__global__ void __launch_bounds__(1024)
scan_partial_kernel(const int* __restrict__ deg, int* __restrict__ part) {
    __shared__ int red[32];
    int idx = blockIdx.x * 1024 + threadIdx.x;
    int v = (idx < N_NODES) ? deg[idx] : 0;
#pragma unroll
    for (int o = 16; o; o >>= 1) v += __shfl_xor_sync(0xFFFFFFFFu, v, o);
    if ((threadIdx.x & 31) == 0) red[threadIdx.x >> 5] = v;
    __syncthreads();
    if (threadIdx.x < 32) {
        int s = red[threadIdx.x];
#pragma unroll
        for (int o = 16; o; o >>= 1) s += __shfl_xor_sync(0xFFFFFFFFu, s, o);
        if (threadIdx.x == 0) part[blockIdx.x] = s;
    }
}

__global__ void __launch_bounds__(128)
scan_part_kernel(int* __restrict__ part) {
    __shared__ int buf[SCAN_CHUNKS];
    int t = threadIdx.x;
    if (t < SCAN_CHUNKS) buf[t] = part[t];
    __syncthreads();
    if (t == 0) {
        int run = 0;
        for (int i = 0; i < SCAN_CHUNKS; i++) {
            int v = buf[i];
            buf[i] = run;
            run += v;
        }
    }
    __syncthreads();
    if (t < SCAN_CHUNKS) part[t] = buf[t];
}

__global__ void __launch_bounds__(1024)
scan_final_kernel(const int* __restrict__ deg, const int* __restrict__ part,
                  int* __restrict__ offs) {
    __shared__ int warpsum[32];
    int t = threadIdx.x;
    int idx = blockIdx.x * 1024 + t;
    int v = (idx < N_NODES) ? deg[idx] : 0;
    int lane = t & 31, wid = t >> 5;
    int sc = v;
#pragma unroll
    for (int o = 1; o < 32; o <<= 1) {
        int u = __shfl_up_sync(0xFFFFFFFFu, sc, o);
        if (lane >= o) sc += u;
    }
    if (lane == 31) warpsum[wid] = sc;
    __syncthreads();
    if (wid == 0) {
        int s = warpsum[lane];
#pragma unroll
        for (int o = 1; o < 32; o <<= 1) {
            int u = __shfl_up_sync(0xFFFFFFFFu, s, o);
            if (lane >= o) s += u;
        }
        warpsum[lane] = s;
    }
    __syncthreads();
    int base = part[blockIdx.x] + ((wid > 0) ? warpsum[wid - 1] : 0);
    if (idx < N_NODES) offs[idx] = base + sc - v;
}

__global__ void __launch_bounds__(256)
fill_csr_kernel(const int* __restrict__ ei, const int* __restrict__ et,
                const int* __restrict__ offs, const int* __restrict__ epos,
                int* __restrict__ csr) {
    int e = blockIdx.x * blockDim.x + threadIdx.x;
    if (e >= N_EDGES) return;
    int s = ei[e];
    int d = ei[N_EDGES + e];
    int r = et[e];
    csr[offs[d] + epos[e]] = s | (r << 30);
}

// ---------------------------------------------------------------------------
// Layer-1 aggregation over node range [base, base+count)
__global__ void __launch_bounds__(256)
agg1_kernel(const float* __restrict__ x,
            const int* __restrict__ offs, const int* __restrict__ deg,
            const int* __restrict__ csr, int base, int count,
            __nv_bfloat16* __restrict__ AGGh, __nv_bfloat16* __restrict__ AGGl) {
    int wi = (blockIdx.x * blockDim.x + threadIdx.x) >> 5;
    int lane = threadIdx.x & 31;
    if (wi >= count) return;
    int w = base + wi;
    int off = offs[w], dg = deg[w];
    float4 a0 = make_float4(0.f, 0.f, 0.f, 0.f);
    float4 a1 = make_float4(0.f, 0.f, 0.f, 0.f);
    int c0 = 0;
    int j = 0;
    const int col = lane * 4;
    for (; j + 4 <= dg; j += 4) {
        int e0 = csr[off + j], e1 = csr[off + j + 1];
        int e2 = csr[off + j + 2], e3 = csr[off + j + 3];
        float4 v0 = *(const float4*)(x + (size_t)(e0 & 0x3FFFFFFF) * 128 + col);
        float4 v1 = *(const float4*)(x + (size_t)(e1 & 0x3FFFFFFF) * 128 + col);
        float4 v2 = *(const float4*)(x + (size_t)(e2 & 0x3FFFFFFF) * 128 + col);
        float4 v3 = *(const float4*)(x + (size_t)(e3 & 0x3FFFFFFF) * 128 + col);
        if ((e0 >> 30) == 0) { a0.x += v0.x; a0.y += v0.y; a0.z += v0.z; a0.w += v0.w; c0++; }
        else                 { a1.x += v0.x; a1.y += v0.y; a1.z += v0.z; a1.w += v0.w; }
        if ((e1 >> 30) == 0) { a0.x += v1.x; a0.y += v1.y; a0.z += v1.z; a0.w += v1.w; c0++; }
        else                 { a1.x += v1.x; a1.y += v1.y; a1.z += v1.z; a1.w += v1.w; }
        if ((e2 >> 30) == 0) { a0.x += v2.x; a0.y += v2.y; a0.z += v2.z; a0.w += v2.w; c0++; }
        else                 { a1.x += v2.x; a1.y += v2.y; a1.z += v2.z; a1.w += v2.w; }
        if ((e3 >> 30) == 0) { a0.x += v3.x; a0.y += v3.y; a0.z += v3.z; a0.w += v3.w; c0++; }
        else                 { a1.x += v3.x; a1.y += v3.y; a1.z += v3.z; a1.w += v3.w; }
    }
    for (; j < dg; j++) {
        int e0 = csr[off + j];
        float4 v0 = *(const float4*)(x + (size_t)(e0 & 0x3FFFFFFF) * 128 + col);
        if ((e0 >> 30) == 0) { a0.x += v0.x; a0.y += v0.y; a0.z += v0.z; a0.w += v0.w; c0++; }
        else                 { a1.x += v0.x; a1.y += v0.y; a1.z += v0.z; a1.w += v0.w; }
    }
    int c1 = dg - c0;
    float s0 = 1.0f / (float)max(c0, 1);
    float s1 = 1.0f / (float)max(c1, 1);
    a0.x *= s0; a0.y *= s0; a0.z *= s0; a0.w *= s0;
    a1.x *= s1; a1.y *= s1; a1.z *= s1; a1.w *= s1;
    unsigned h0, h1, l0, l1;
    split4(a0, h0, h1, l0, l1);
    *(uint2*)(AGGh + (size_t)w * 256 + col) = make_uint2(h0, h1);
    *(uint2*)(AGGl + (size_t)w * 256 + col) = make_uint2(l0, l1);
    split4(a1, h0, h1, l0, l1);
    *(uint2*)(AGGh + (size_t)w * 256 + 128 + col) = make_uint2(h0, h1);
    *(uint2*)(AGGl + (size_t)w * 256 + 128 + col) = make_uint2(l0, l1);
}

// Layer-2 aggregation + final epilogue
__global__ void __launch_bounds__(256)
agg2_kernel(const float* __restrict__ P,
            const int* __restrict__ offs, const int* __restrict__ deg,
            const int* __restrict__ csr,
            const float* __restrict__ b2, float* __restrict__ out) {
    int w = (blockIdx.x * blockDim.x + threadIdx.x) >> 5;
    int lane = threadIdx.x & 31;
    if (w >= N_NODES) return;
    int off = offs[w], dg = deg[w];
    float2 a0 = make_float2(0.f, 0.f), a1 = make_float2(0.f, 0.f);
    int c0 = 0;
    int j = 0;
    const int col = lane * 2;
    for (; j + 4 <= dg; j += 4) {
        int e0 = csr[off + j], e1 = csr[off + j + 1];
        int e2 = csr[off + j + 2], e3 = csr[off + j + 3];
        float2 v0 = *(const float2*)(P + (size_t)(e0 & 0x3FFFFFFF) * 192 + 64 + (e0 >> 30) * 64 + col);
        float2 v1 = *(const float2*)(P + (size_t)(e1 & 0x3FFFFFFF) * 192 + 64 + (e1 >> 30) * 64 + col);
        float2 v2 = *(const float2*)(P + (size_t)(e2 & 0x3FFFFFFF) * 192 + 64 + (e2 >> 30) * 64 + col);
        float2 v3 = *(const float2*)(P + (size_t)(e3 & 0x3FFFFFFF) * 192 + 64 + (e3 >> 30) * 64 + col);
        if ((e0 >> 30) == 0) { a0.x += v0.x; a0.y += v0.y; c0++; } else { a1.x += v0.x; a1.y += v0.y; }
        if ((e1 >> 30) == 0) { a0.x += v1.x; a0.y += v1.y; c0++; } else { a1.x += v1.x; a1.y += v1.y; }
        if ((e2 >> 30) == 0) { a0.x += v2.x; a0.y += v2.y; c0++; } else { a1.x += v2.x; a1.y += v2.y; }
        if ((e3 >> 30) == 0) { a0.x += v3.x; a0.y += v3.y; c0++; } else { a1.x += v3.x; a1.y += v3.y; }
    }
    for (; j < dg; j++) {
        int e0 = csr[off + j];
        float2 v0 = *(const float2*)(P + (size_t)(e0 & 0x3FFFFFFF) * 192 + 64 + (e0 >> 30) * 64 + col);
        if ((e0 >> 30) == 0) { a0.x += v0.x; a0.y += v0.y; c0++; } else { a1.x += v0.x; a1.y += v0.y; }
    }
    int c1 = dg - c0;
    float s0 = 1.0f / (float)max(c0, 1);
    float s1 = 1.0f / (float)max(c1, 1);
    float2 p0 = *(const float2*)(P + (size_t)w * 192 + col);
    float2 bb = *(const float2*)(b2 + col);
    float2 v;
    v.x = p0.x + a0.x * s0 + a1.x * s1 + bb.x;
    v.y = p0.y + a0.y * s0 + a1.y * s1 + bb.y;
    float ss = v.x * v.x + v.y * v.y;
#pragma unroll
    for (int o = 16; o; o >>= 1) ss += __shfl_xor_sync(0xFFFFFFFFu, ss, o);
    float sc = 1.0f / fmaxf(sqrtf(ss), 1e-12f);
    v.x *= sc; v.y *= sc;
    *(float2*)(out + (size_t)w * 64 + col) = v;
}

// ---------------------------------------------------------------------------
__device__ __forceinline__ void mma_bf16(float* c, const unsigned* a, unsigned b0, unsigned b1) {
    asm volatile(
        "mma.sync.aligned.m16n8k16.row.col.f32.bf16.bf16.f32 "
        "{%0,%1,%2,%3}, {%4,%5,%6,%7}, {%8,%9}, {%0,%1,%2,%3};"
        : "+f"(c[0]), "+f"(c[1]), "+f"(c[2]), "+f"(c[3])
        : "r"(a[0]), "r"(a[1]), "r"(a[2]), "r"(a[3]), "r"(b0), "r"(b1));
}

__device__ __forceinline__ void ldsm4(uint32_t addr, unsigned& r0, unsigned& r1,
                                      unsigned& r2, unsigned& r3) {
    asm volatile("ldmatrix.sync.aligned.m8n8.x4.shared.b16 {%0,%1,%2,%3}, [%4];"
                 : "=r"(r0), "=r"(r1), "=r"(r2), "=r"(r3) : "r"(addr));
}

__device__ __forceinline__ void cp16(void* dst_smem, const void* src) {
    uint32_t d = (uint32_t)__cvta_generic_to_shared(dst_smem);
    asm volatile("cp.async.ca.shared.global [%0], [%1], 16;" :: "r"(d), "l"(src));
}

// ---------------------------------------------------------------------------
// Double-buffered tensor-core GEMM, bf16 3-term split, pure cp.async A path.
// ldw: weight row stride. PARTIAL: adds Cin. HOUT: pre-split bf16 H (+relu).
template<int BN, int KDIM, int WM, int WN, int MT, int NT, bool RELU, bool HOUT, bool PARTIAL>
__global__ void __launch_bounds__(256, 2)
gemm_db_kernel(const __nv_bfloat16* __restrict__ Ah,
               const __nv_bfloat16* __restrict__ Al, int lda,
               const __nv_bfloat16* __restrict__ WT_hi,
               const __nv_bfloat16* __restrict__ WT_lo, int ldw,
               const float* __restrict__ bias,
               const float* __restrict__ Cin,
               float* __restrict__ C, int M, int ldc,
               __nv_bfloat16* __restrict__ Hh,
               __nv_bfloat16* __restrict__ Hl) {
    constexpr int BM = 128, BK = 32, BKP = 40;
    constexpr int ASZ = BM * BKP;
    constexpr int BSZ = BN * BKP;
    constexpr int T = KDIM / BK;

    extern __shared__ __align__(16) char smem_raw[];
    __nv_bfloat16* As_hi[2]; __nv_bfloat16* As_lo[2];
    __nv_bfloat16* Bs_hi[2]; __nv_bfloat16* Bs_lo[2];
    {
        __nv_bfloat16* p = (__nv_bfloat16*)smem_raw;
        As_hi[0] = p;            As_lo[0] = p + ASZ;
        As_hi[1] = p + 2 * ASZ;  As_lo[1] = p + 3 * ASZ;
        p += 4 * ASZ;
        Bs_hi[0] = p;            Bs_lo[0] = p + BSZ;
        Bs_hi[1] = p + 2 * BSZ;  Bs_lo[1] = p + 3 * BSZ;
    }

    const int tid = threadIdx.x;
    const int lane = tid & 31;
    const int warp = tid >> 5;
    const int warpM = warp / WN;
    const int warpN = warp % WN;
    const int m0 = blockIdx.x * BM;
    const int g = lane >> 2;
    const int kq = (lane & 3) * 2;

    const __nv_bfloat16* Wh = WT_hi + (size_t)blockIdx.y * BN * ldw;
    const __nv_bfloat16* Wl = WT_lo + (size_t)blockIdx.y * BN * ldw;

    float acc[MT][NT][4];
#pragma unroll
    for (int i = 0; i < MT; i++)
#pragma unroll
        for (int j = 0; j < NT; j++)
#pragma unroll
            for (int q = 0; q < 4; q++) acc[i][j][q] = 0.f;

    auto loadB = [&](int k0, int stg) {
#pragma unroll
        for (int i = tid; i < BN * 4; i += 256) {
            int n = i >> 2, q = i & 3;
            cp16(Bs_hi[stg] + n * BKP + q * 8, Wh + (size_t)n * ldw + k0 + q * 8);
            cp16(Bs_lo[stg] + n * BKP + q * 8, Wl + (size_t)n * ldw + k0 + q * 8);
        }
    };
    auto loadA = [&](int k0, int stg) {
#pragma unroll
        for (int i = tid; i < BM * 4; i += 256) {
            int row = i >> 2, q = i & 3;
            int m = (m0 + row < M) ? (m0 + row) : (M - 1);
            cp16(As_hi[stg] + row * BKP + q * 8, Ah + (size_t)m * lda + k0 + q * 8);
            cp16(As_lo[stg] + row * BKP + q * 8, Al + (size_t)m * lda + k0 + q * 8);
        }
    };

    const int rowA = (lane & 7) + (lane & 8);
    const int colA = (lane & 16) ? 8 : 0;
    const int gB = lane >> 3;
    const int rowB = (lane & 7) + ((gB & 1) ? 8 : 0);
    const int colB = (gB >> 1) * 8;

    uint32_t sAhi[2], sAlo[2], sBhi[2], sBlo[2];
#pragma unroll
    for (int s = 0; s < 2; s++) {
        sAhi[s] = (uint32_t)__cvta_generic_to_shared(As_hi[s]);
        sAlo[s] = (uint32_t)__cvta_generic_to_shared(As_lo[s]);
        sBhi[s] = (uint32_t)__cvta_generic_to_shared(Bs_hi[s]);
        sBlo[s] = (uint32_t)__cvta_generic_to_shared(Bs_lo[s]);
    }

    auto compute = [&](int stg) {
#pragma unroll
        for (int ks = 0; ks < BK; ks += 16) {
            unsigned ah[MT][4], al[MT][4];
#pragma unroll
            for (int mt = 0; mt < MT; mt++) {
                uint32_t off = (uint32_t)(2 * ((warpM * MT * 16 + mt * 16 + rowA) * BKP + ks + colA));
                ldsm4(sAhi[stg] + off, ah[mt][0], ah[mt][1], ah[mt][2], ah[mt][3]);
                ldsm4(sAlo[stg] + off, al[mt][0], al[mt][1], al[mt][2], al[mt][3]);
            }
            unsigned bh0[NT], bh1[NT], bl0[NT], bl1[NT];
#pragma unroll
            for (int np = 0; np < NT / 2; np++) {
                uint32_t off = (uint32_t)(2 * ((warpN * NT * 8 + np * 16 + rowB) * BKP + ks + colB));
                ldsm4(sBhi[stg] + off, bh0[np * 2], bh0[np * 2 + 1], bh1[np * 2], bh1[np * 2 + 1]);
                ldsm4(sBlo[stg] + off, bl0[np * 2], bl0[np * 2 + 1], bl1[np * 2], bl1[np * 2 + 1]);
            }
#pragma unroll
            for (int mt = 0; mt < MT; mt++)
#pragma unroll
                for (int nt = 0; nt < NT; nt++) {
                    mma_bf16(acc[mt][nt], ah[mt], bh0[nt], bh1[nt]);
                    mma_bf16(acc[mt][nt], ah[mt], bl0[nt], bl1[nt]);
                    mma_bf16(acc[mt][nt], al[mt], bh0[nt], bh1[nt]);
                }
        }
    };

    loadB(0, 0);
    loadA(0, 0);
    asm volatile("cp.async.commit_group;\ncp.async.wait_group 0;" ::: "memory");
    __syncthreads();

    for (int t = 0; t < T; t++) {
        int cur = t & 1, nxt = cur ^ 1;
        bool hasNext = (t + 1 < T);
        int k1 = (t + 1) * BK;
        if (hasNext) {
            loadB(k1, nxt);
            loadA(k1, nxt);
        }
        compute(cur);
        asm volatile("cp.async.commit_group;\ncp.async.wait_group 0;" ::: "memory");
        __syncthreads();
    }

#pragma unroll
    for (int nt = 0; nt < NT; nt++) {
        int n = warpN * NT * 8 + nt * 8 + kq;
        float b0 = bias ? bias[n] : 0.f;
        float b1 = bias ? bias[n + 1] : 0.f;
#pragma unroll
        for (int mt = 0; mt < MT; mt++) {
            float* c = acc[mt][nt];
            c[0] += b0; c[1] += b1; c[2] += b0; c[3] += b1;
        }
    }

    if (HOUT) {
#pragma unroll
        for (int mt = 0; mt < MT; mt++) {
            int r0 = m0 + warpM * MT * 16 + mt * 16 + g;
#pragma unroll
            for (int nt = 0; nt < NT; nt++) {
                int n = warpN * NT * 8 + nt * 8 + kq;
                float* c = acc[mt][nt];
                if (r0 < M) {
                    float v0 = c[0], v1 = c[1];
                    if (PARTIAL) {
                        float2 pc = *(const float2*)(Cin + (size_t)r0 * 128 + n);
                        v0 += pc.x; v1 += pc.y;
                    }
                    if (RELU) { v0 = fmaxf(v0, 0.f); v1 = fmaxf(v1, 0.f); }
                    __nv_bfloat16 h0 = __float2bfloat16(v0);
                    __nv_bfloat16 h1 = __float2bfloat16(v1);
                    *(unsigned*)(Hh + (size_t)r0 * 128 + n) = pack2(h0, h1);
                    *(unsigned*)(Hl + (size_t)r0 * 128 + n) =
                        pack2(__float2bfloat16(v0 - __bfloat162float(h0)),
                              __float2bfloat16(v1 - __bfloat162float(h1)));
                }
                if (r0 + 8 < M) {
                    float v2 = c[2], v3 = c[3];
                    if (PARTIAL) {
                        float2 pc = *(const float2*)(Cin + (size_t)(r0 + 8) * 128 + n);
                        v2 += pc.x; v3 += pc.y;
                    }
                    if (RELU) { v2 = fmaxf(v2, 0.f); v3 = fmaxf(v3, 0.f); }
                    __nv_bfloat16 h2 = __float2bfloat16(v2);
                    __nv_bfloat16 h3 = __float2bfloat16(v3);
                    *(unsigned*)(Hh + (size_t)(r0 + 8) * 128 + n) = pack2(h2, h3);
                    *(unsigned*)(Hl + (size_t)(r0 + 8) * 128 + n) =
                        pack2(__float2bfloat16(v2 - __bfloat162float(h2)),
                              __float2bfloat16(v3 - __bfloat162float(h3)));
                }
            }
        }
    } else {
        float* Cb = C + (size_t)blockIdx.y * BN;
#pragma unroll
        for (int mt = 0; mt < MT; mt++) {
            int r0 = m0 + warpM * MT * 16 + mt * 16 + g;
#pragma unroll
            for (int nt = 0; nt < NT; nt++) {
                int n = warpN * NT * 8 + nt * 8 + kq;
                float* c = acc[mt][nt];
                if (r0 < M)
                    *(float2*)(Cb + (size_t)r0 * ldc + n) = make_float2(c[0], c[1]);
                if (r0 + 8 < M)
                    *(float2*)(Cb + (size_t)(r0 + 8) * ldc + n) = make_float2(c[2], c[3]);
            }
        }
    }
}

// ---------------------------------------------------------------------------
extern "C" void kernel_launch(void* const* d_in, const int* in_sizes, int n_in,
                              void* d_out, int out_size) {
    const float* x       = (const float*)d_in[0];
    const int*   ei      = (const int*)d_in[1];
    const int*   et      = (const int*)d_in[2];
    const float* W1_rel  = (const float*)d_in[3];
    const float* W1_root = (const float*)d_in[4];
    const float* b1      = (const float*)d_in[5];
    const float* W2_rel  = (const float*)d_in[6];
    const float* W2_root = (const float*)d_in[7];
    const float* b2      = (const float*)d_in[8];
    float* out = (float*)d_out;

    float *P, *C1;
    __nv_bfloat16 *Xh, *Xl, *Ah, *Al, *Hh, *Hl, *W1Th, *W1Tl, *W2Th, *W2Tl;
    int *deg, *offs, *epos, *part, *csr;
    cudaGetSymbolAddress((void**)&P,    g_P);
    cudaGetSymbolAddress((void**)&C1,   g_C1);
    cudaGetSymbolAddress((void**)&Xh,   g_X_hi);
    cudaGetSymbolAddress((void**)&Xl,   g_X_lo);
    cudaGetSymbolAddress((void**)&Ah,   g_AGG_hi);
    cudaGetSymbolAddress((void**)&Al,   g_AGG_lo);
    cudaGetSymbolAddress((void**)&Hh,   g_H_hi);
    cudaGetSymbolAddress((void**)&Hl,   g_H_lo);
    cudaGetSymbolAddress((void**)&W1Th, g_W1T_hi);
    cudaGetSymbolAddress((void**)&W1Tl, g_W1T_lo);
    cudaGetSymbolAddress((void**)&W2Th, g_W2T_hi);
    cudaGetSymbolAddress((void**)&W2Tl, g_W2T_lo);
    cudaGetSymbolAddress((void**)&deg,  g_deg);
    cudaGetSymbolAddress((void**)&offs, g_offs);
    cudaGetSymbolAddress((void**)&epos, g_epos);
    cudaGetSymbolAddress((void**)&part, g_part);
    cudaGetSymbolAddress((void**)&csr,  g_csr);

    const int SMG = (4 * 128 * 40 + 4 * 128 * 40) * 2;   // 81920 (BN=128)
    const int SM2 = (4 * 128 * 40 + 4 * 64 * 40) * 2;    // 61440 (BN=64)
    auto* k1a = gemm_db_kernel<128, 128, 2, 4, 4, 4, false, false, false>;  // x part -> fp32 C1
    auto* k1b = gemm_db_kernel<128, 256, 2, 4, 4, 4, true,  true,  true>;   // AGG part + C1 -> H
    auto* k2  = gemm_db_kernel<64,  128, 4, 2, 2, 4, false, false, false>;
    cudaFuncSetAttribute(k1a, cudaFuncAttributeMaxDynamicSharedMemorySize, SMG);
    cudaFuncSetAttribute(k1b, cudaFuncAttributeMaxDynamicSharedMemorySize, SMG);
    cudaFuncSetAttribute(k2,  cudaFuncAttributeMaxDynamicSharedMemorySize, SM2);

    const int TB = 256;
    const int g_prep  = (128 * KTOT + 192 * 128 + TB - 1) / TB;
    const int g_prepx = (N_NODES * 32 + TB - 1) / TB;
    const int g_edge  = (N_EDGES + TB - 1) / TB;
    const int g_agg   = (N_NODES * 32 + TB - 1) / TB;
    const int g_agg0  = (HALF0 * 32 + TB - 1) / TB;
    const int g_agg1  = (HALF1 * 32 + TB - 1) / TB;
    const int NB0     = HALF0 / 128;                      // 391
    const int NB1     = (HALF1 + 127) / 128;              // 391

    // ---- streams / events for the two-half pipeline ----
    cudaStream_t s1, s2;
    cudaEvent_t ev0, evA0, evA1, evB0, evB1, evC0;
    cudaStreamCreateWithFlags(&s1, cudaStreamNonBlocking);
    cudaStreamCreateWithFlags(&s2, cudaStreamNonBlocking);
    cudaEventCreateWithFlags(&ev0,  cudaEventDisableTiming);
    cudaEventCreateWithFlags(&evA0, cudaEventDisableTiming);
    cudaEventCreateWithFlags(&evA1, cudaEventDisableTiming);
    cudaEventCreateWithFlags(&evB0, cudaEventDisableTiming);
    cudaEventCreateWithFlags(&evB1, cudaEventDisableTiming);
    cudaEventCreateWithFlags(&evC0, cudaEventDisableTiming);

    cudaEventRecord(ev0, 0);
    cudaStreamWaitEvent(s1, ev0, 0);

    // ---- s1: preps + x-slice GEMM (independent of CSR/agg1), then k1b halves ----
    prep_w_kernel<<<g_prep, TB, 0, s1>>>(W1_rel, W1_root, W2_rel, W2_root);
    prep_x_kernel<<<g_prepx, TB, 0, s1>>>(x, Xh, Xl);
    k1a<<<(N_NODES + 127) / 128, TB, SMG, s1>>>(Xh, Xl, 128, W1Th, W1Tl, KTOT,
                                                nullptr, nullptr, C1, N_NODES, 128,
                                                nullptr, nullptr);

    // ---- main: CSR build, then agg1 in two halves ----
    cudaMemsetAsync(deg, 0, N_NODES * 4);
    deg_kernel<<<g_edge, TB>>>(ei, deg, epos);
    scan_partial_kernel<<<SCAN_CHUNKS, 1024>>>(deg, part);
    scan_part_kernel<<<1, 128>>>(part);
    scan_final_kernel<<<SCAN_CHUNKS, 1024>>>(deg, part, offs);
    fill_csr_kernel<<<g_edge, TB>>>(ei, et, offs, epos, csr);
    agg1_kernel<<<g_agg0, TB>>>(x, offs, deg, csr, 0, HALF0, Ah, Al);
    cudaEventRecord(evA0, 0);
    agg1_kernel<<<g_agg1, TB>>>(x, offs, deg, csr, HALF0, HALF1, Ah, Al);
    cudaEventRecord(evA1, 0);

    // ---- s1: k1b half 0 (needs agg1_0), then half 1 (needs agg1_1) ----
    cudaStreamWaitEvent(s1, evA0, 0);
    k1b<<<NB0, TB, SMG, s1>>>(Ah, Al, 256, W1Th + 128, W1Tl + 128, KTOT, b1, C1,
                              nullptr, HALF0, 0, Hh, Hl);
    cudaEventRecord(evB0, s1);
    cudaStreamWaitEvent(s1, evA1, 0);
    k1b<<<NB1, TB, SMG, s1>>>(Ah + (size_t)HALF0 * 256, Al + (size_t)HALF0 * 256, 256,
                              W1Th + 128, W1Tl + 128, KTOT, b1, C1 + (size_t)HALF0 * 128,
                              nullptr, HALF1, 0,
                              Hh + (size_t)HALF0 * 128, Hl + (size_t)HALF0 * 128);
    cudaEventRecord(evB1, s1);

    // ---- s2: k2 half 0 overlaps k1b half 1 ----
    cudaStreamWaitEvent(s2, evB0, 0);
    k2<<<dim3(NB0, 3), TB, SM2, s2>>>(Hh, Hl, 128, W2Th, W2Tl, 128, nullptr, nullptr,
                                      P, HALF0, 192, nullptr, nullptr);
    cudaEventRecord(evC0, s2);

    // ---- main: k2 half 1, then final aggregation+epilogue ----
    cudaStreamWaitEvent(0, evB1, 0);
    k2<<<dim3(NB1, 3), TB, SM2>>>(Hh + (size_t)HALF0 * 128, Hl + (size_t)HALF0 * 128, 128,
                                  W2Th, W2Tl, 128, nullptr, nullptr,
                                  P + (size_t)HALF0 * 192, HALF1, 192, nullptr, nullptr);
    cudaStreamWaitEvent(0, evC0, 0);
    agg2_kernel<<<g_agg, TB>>>(P, offs, deg, csr, b2, out);

    cudaEventDestroy(ev0);
    cudaEventDestroy(evA0);
    cudaEventDestroy(evA1);
    cudaEventDestroy(evB0);
    cudaEventDestroy(evB1);
    cudaEventDestroy(evC0);
    cudaStreamDestroy(s1);
    cudaStreamDestroy(s2);
}